// round 1
// baseline (speedup 1.0000x reference)
#include <cuda_runtime.h>
#include <math.h>

// Problem constants
#define BB 4
#define SS 2048
#define DD 1024
#define HH 16
#define DKK 64
#define MTOT (BB * SS)   // 8192

// Scratch: device globals (no allocation allowed in kernel_launch)
__device__ float g_Q[BB * HH * SS * DKK];   // [B,H,S,DK]
__device__ float g_K[BB * HH * SS * DKK];
__device__ float g_V[BB * HH * SS * DKK];
__device__ float g_ATT[MTOT * DD];          // [B,S,D]

// ---------------------------------------------------------------------------
// 128x128x8 fp32 GEMM core: C[m][n] = sum_k A[m][k] * W[n][k]
// A: [M x 1024] row-major, W: [1024 x 1024] row-major (both k-contiguous: NT)
// 256 threads, 8x8 micro-tile per thread.
// ---------------------------------------------------------------------------
__device__ __forceinline__ void gemm_128x128(
    const float* __restrict__ A, const float* __restrict__ W,
    int m0, int n0, float acc[8][8], float* As, float* Ws)
{
    const int t    = threadIdx.x;
    const int tx   = t & 15;
    const int ty   = t >> 4;
    const int lrow = t >> 1;        // 0..127
    const int lk   = (t & 1) * 4;   // 0 or 4

    const float* aptr = A + (m0 + lrow) * 1024 + lk;
    const float* wptr = W + (n0 + lrow) * 1024 + lk;

    for (int k0 = 0; k0 < 1024; k0 += 8) {
        float4 av = *(const float4*)(aptr + k0);
        float4 wv = *(const float4*)(wptr + k0);
        __syncthreads();
        As[(lk + 0) * 128 + lrow] = av.x;
        As[(lk + 1) * 128 + lrow] = av.y;
        As[(lk + 2) * 128 + lrow] = av.z;
        As[(lk + 3) * 128 + lrow] = av.w;
        Ws[(lk + 0) * 128 + lrow] = wv.x;
        Ws[(lk + 1) * 128 + lrow] = wv.y;
        Ws[(lk + 2) * 128 + lrow] = wv.z;
        Ws[(lk + 3) * 128 + lrow] = wv.w;
        __syncthreads();
#pragma unroll
        for (int kk = 0; kk < 8; kk++) {
            float ar[8], br[8];
            *(float4*)(ar)     = *(const float4*)&As[kk * 128 + ty * 8];
            *(float4*)(ar + 4) = *(const float4*)&As[kk * 128 + ty * 8 + 4];
            *(float4*)(br)     = *(const float4*)&Ws[kk * 128 + tx * 8];
            *(float4*)(br + 4) = *(const float4*)&Ws[kk * 128 + tx * 8 + 4];
#pragma unroll
            for (int i = 0; i < 8; i++)
#pragma unroll
                for (int j = 0; j < 8; j++)
                    acc[i][j] = fmaf(ar[i], br[j], acc[i][j]);
        }
    }
}

// ---------------------------------------------------------------------------
// QKV projection: Y = X @ W^T + b, written into [B,H,S,DK] head-split layout.
// grid: (M/128=64, D/128=8, 3)  z picks q/k/v.
// ---------------------------------------------------------------------------
__global__ __launch_bounds__(256) void qkv_proj_kernel(
    const float* __restrict__ q, const float* __restrict__ k, const float* __restrict__ v,
    const float* __restrict__ wq, const float* __restrict__ bq,
    const float* __restrict__ wk, const float* __restrict__ bk,
    const float* __restrict__ wv, const float* __restrict__ bv)
{
    __shared__ float As[8 * 128];
    __shared__ float Ws[8 * 128];

    const float* A; const float* W; const float* bias; float* out;
    if (blockIdx.z == 0)      { A = q; W = wq; bias = bq; out = g_Q; }
    else if (blockIdx.z == 1) { A = k; W = wk; bias = bk; out = g_K; }
    else                      { A = v; W = wv; bias = bv; out = g_V; }

    const int m0 = blockIdx.x * 128;
    const int n0 = blockIdx.y * 128;

    float acc[8][8];
#pragma unroll
    for (int i = 0; i < 8; i++)
#pragma unroll
        for (int j = 0; j < 8; j++) acc[i][j] = 0.f;

    gemm_128x128(A, W, m0, n0, acc, As, Ws);

    const int tx = threadIdx.x & 15;
    const int ty = threadIdx.x >> 4;
#pragma unroll
    for (int i = 0; i < 8; i++) {
        int m = m0 + ty * 8 + i;
        int b = m >> 11;          // /2048
        int s = m & 2047;
#pragma unroll
        for (int j = 0; j < 8; j++) {
            int n  = n0 + tx * 8 + j;
            int h  = n >> 6;
            int dk = n & 63;
            out[((b * HH + h) * SS + s) * DKK + dk] = acc[i][j] + bias[n];
        }
    }
}

// ---------------------------------------------------------------------------
// Flash attention (causal), fp32. One block per (q-tile of 64 rows, h, b).
// 256 threads: thread t -> row r = t>>2, group g = t&3; columns interleaved
// c = g + 4*j so smem accesses with stride-65 padding are conflict-free.
// ---------------------------------------------------------------------------
#define ATTN_PAD 65
#define ATTN_SMEM (4 * 64 * ATTN_PAD * 4)

__global__ __launch_bounds__(256) void attn_kernel()
{
    extern __shared__ float sm[];
    float* Qs = sm;
    float* Ks = Qs + 64 * ATTN_PAD;
    float* Vs = Ks + 64 * ATTN_PAD;
    float* Ps = Vs + 64 * ATTN_PAD;

    const int t  = threadIdx.x;
    const int qt = blockIdx.x;
    const int h  = blockIdx.y;
    const int b  = blockIdx.z;

    const float* Qbase = g_Q + ((size_t)(b * HH + h) * SS) * DKK;
    const float* Kbase = g_K + ((size_t)(b * HH + h) * SS) * DKK;
    const float* Vbase = g_V + ((size_t)(b * HH + h) * SS) * DKK;

    // Load Q tile (64 x 64)
    for (int idx = t; idx < 64 * 16; idx += 256) {
        int r  = idx >> 4;
        int c4 = (idx & 15) * 4;
        float4 qv = *(const float4*)&Qbase[(qt * 64 + r) * DKK + c4];
        Qs[r * ATTN_PAD + c4 + 0] = qv.x;
        Qs[r * ATTN_PAD + c4 + 1] = qv.y;
        Qs[r * ATTN_PAD + c4 + 2] = qv.z;
        Qs[r * ATTN_PAD + c4 + 3] = qv.w;
    }

    const int r = t >> 2;     // row within tile, 0..63
    const int g = t & 3;      // lane group
    const int qrow = qt * 64 + r;

    float m_run = -1e30f;
    float l_run = 0.f;
    float Oacc[16];
#pragma unroll
    for (int i = 0; i < 16; i++) Oacc[i] = 0.f;

    for (int kt = 0; kt <= qt; kt++) {
        __syncthreads();   // previous iteration fully consumed Ks/Vs/Ps

        // Load K and V tiles (64 x 64 each)
        const float* Kt = Kbase + (size_t)(kt * 64) * DKK;
        const float* Vt = Vbase + (size_t)(kt * 64) * DKK;
        for (int idx = t; idx < 64 * 16; idx += 256) {
            int rr = idx >> 4;
            int c4 = (idx & 15) * 4;
            float4 kv = *(const float4*)&Kt[rr * DKK + c4];
            Ks[rr * ATTN_PAD + c4 + 0] = kv.x;
            Ks[rr * ATTN_PAD + c4 + 1] = kv.y;
            Ks[rr * ATTN_PAD + c4 + 2] = kv.z;
            Ks[rr * ATTN_PAD + c4 + 3] = kv.w;
            float4 vv = *(const float4*)&Vt[rr * DKK + c4];
            Vs[rr * ATTN_PAD + c4 + 0] = vv.x;
            Vs[rr * ATTN_PAD + c4 + 1] = vv.y;
            Vs[rr * ATTN_PAD + c4 + 2] = vv.z;
            Vs[rr * ATTN_PAD + c4 + 3] = vv.w;
        }
        __syncthreads();

        // S = Q @ K^T * (1/8), 16 columns per thread (interleaved c = g + 4j)
        float s[16];
#pragma unroll
        for (int j = 0; j < 16; j++) s[j] = 0.f;

#pragma unroll 4
        for (int dk0 = 0; dk0 < 64; dk0 += 4) {
            float q0 = Qs[r * ATTN_PAD + dk0 + 0];
            float q1 = Qs[r * ATTN_PAD + dk0 + 1];
            float q2 = Qs[r * ATTN_PAD + dk0 + 2];
            float q3 = Qs[r * ATTN_PAD + dk0 + 3];
#pragma unroll
            for (int j = 0; j < 16; j++) {
                int c = g + 4 * j;
                const float* kr = &Ks[c * ATTN_PAD + dk0];
                s[j] = fmaf(q0, kr[0], s[j]);
                s[j] = fmaf(q1, kr[1], s[j]);
                s[j] = fmaf(q2, kr[2], s[j]);
                s[j] = fmaf(q3, kr[3], s[j]);
            }
        }
#pragma unroll
        for (int j = 0; j < 16; j++) s[j] *= 0.125f;

        // Causal mask (only diagonal tile can be partial)
        if (kt == qt) {
#pragma unroll
            for (int j = 0; j < 16; j++) {
                int c = kt * 64 + g + 4 * j;
                if (c > qrow) s[j] = -1e30f;
            }
        }

        // Online softmax update
        float mt = s[0];
#pragma unroll
        for (int j = 1; j < 16; j++) mt = fmaxf(mt, s[j]);
        mt = fmaxf(mt, __shfl_xor_sync(0xffffffffu, mt, 1));
        mt = fmaxf(mt, __shfl_xor_sync(0xffffffffu, mt, 2));

        float m_new = fmaxf(m_run, mt);
        float alpha = __expf(m_run - m_new);

        float lsum = 0.f;
#pragma unroll
        for (int j = 0; j < 16; j++) {
            s[j] = __expf(s[j] - m_new);
            lsum += s[j];
        }
        lsum += __shfl_xor_sync(0xffffffffu, lsum, 1);
        lsum += __shfl_xor_sync(0xffffffffu, lsum, 2);

        l_run = l_run * alpha + lsum;
        m_run = m_new;

        // Stage P
#pragma unroll
        for (int j = 0; j < 16; j++)
            Ps[r * ATTN_PAD + g + 4 * j] = s[j];

#pragma unroll
        for (int i = 0; i < 16; i++) Oacc[i] *= alpha;

        __syncthreads();

        // O += P @ V   (16 dk per thread, interleaved dk = g + 4i)
#pragma unroll 4
        for (int j0 = 0; j0 < 64; j0 += 4) {
            float p0 = Ps[r * ATTN_PAD + j0 + 0];
            float p1 = Ps[r * ATTN_PAD + j0 + 1];
            float p2 = Ps[r * ATTN_PAD + j0 + 2];
            float p3 = Ps[r * ATTN_PAD + j0 + 3];
#pragma unroll
            for (int i = 0; i < 16; i++) {
                int c = g + 4 * i;
                float o = Oacc[i];
                o = fmaf(p0, Vs[(j0 + 0) * ATTN_PAD + c], o);
                o = fmaf(p1, Vs[(j0 + 1) * ATTN_PAD + c], o);
                o = fmaf(p2, Vs[(j0 + 2) * ATTN_PAD + c], o);
                o = fmaf(p3, Vs[(j0 + 3) * ATTN_PAD + c], o);
                Oacc[i] = o;
            }
        }
    }

    // Finalize + write in [B,S,D] layout for the output projection
    float inv_l = 1.f / l_run;
    float* outp = g_ATT + ((size_t)(b * SS + qrow)) * DD + h * DKK;
#pragma unroll
    for (int i = 0; i < 16; i++)
        outp[g + 4 * i] = Oacc[i] * inv_l;
}

// ---------------------------------------------------------------------------
// Output projection: out = ATT @ Wo^T + bo, written [B,S,D] (= flat [M,D])
// ---------------------------------------------------------------------------
__global__ __launch_bounds__(256) void out_proj_kernel(
    const float* __restrict__ wo, const float* __restrict__ bo,
    float* __restrict__ out)
{
    __shared__ float As[8 * 128];
    __shared__ float Ws[8 * 128];

    const int m0 = blockIdx.x * 128;
    const int n0 = blockIdx.y * 128;

    float acc[8][8];
#pragma unroll
    for (int i = 0; i < 8; i++)
#pragma unroll
        for (int j = 0; j < 8; j++) acc[i][j] = 0.f;

    gemm_128x128(g_ATT, wo, m0, n0, acc, As, Ws);

    const int tx = threadIdx.x & 15;
    const int ty = threadIdx.x >> 4;
#pragma unroll
    for (int i = 0; i < 8; i++) {
        int m = m0 + ty * 8 + i;
#pragma unroll
        for (int j4 = 0; j4 < 8; j4 += 4) {
            int n = n0 + tx * 8 + j4;
            float4 rv;
            rv.x = acc[i][j4 + 0] + bo[n + 0];
            rv.y = acc[i][j4 + 1] + bo[n + 1];
            rv.z = acc[i][j4 + 2] + bo[n + 2];
            rv.w = acc[i][j4 + 3] + bo[n + 3];
            *(float4*)&out[(size_t)m * DD + n] = rv;
        }
    }
}

// ---------------------------------------------------------------------------
// Entry point
// Inputs (metadata order): q, k, v, mask, w_q, b_q, w_k, b_k, w_v, b_v, w_o, b_o
// mask is the static causal tril -> ignored (causality handled analytically).
// ---------------------------------------------------------------------------
extern "C" void kernel_launch(void* const* d_in, const int* in_sizes, int n_in,
                              void* d_out, int out_size)
{
    const float* q  = (const float*)d_in[0];
    const float* k  = (const float*)d_in[1];
    const float* v  = (const float*)d_in[2];
    const float* wq = (const float*)d_in[4];
    const float* bq = (const float*)d_in[5];
    const float* wk = (const float*)d_in[6];
    const float* bk = (const float*)d_in[7];
    const float* wv = (const float*)d_in[8];
    const float* bv = (const float*)d_in[9];
    const float* wo = (const float*)d_in[10];
    const float* bo = (const float*)d_in[11];
    float* out = (float*)d_out;

    // QKV projections (z = 0/1/2 -> q/k/v)
    dim3 gproj(MTOT / 128, DD / 128, 3);
    qkv_proj_kernel<<<gproj, 256>>>(q, k, v, wq, bq, wk, bk, wv, bv);

    // Flash attention (needs >48KB dynamic smem)
    cudaFuncSetAttribute(attn_kernel, cudaFuncAttributeMaxDynamicSharedMemorySize, ATTN_SMEM);
    dim3 gattn(SS / 64, HH, BB);
    attn_kernel<<<gattn, 256, ATTN_SMEM>>>();

    // Output projection
    dim3 gout(MTOT / 128, DD / 128, 1);
    out_proj_kernel<<<gout, 256>>>(wo, bo, out);
}

// round 3
// speedup vs baseline: 3.7690x; 3.7690x over previous
#include <cuda_runtime.h>
#include <math.h>
#include <stdint.h>

// Problem constants
#define BB 4
#define SS 2048
#define DD 1024
#define HH 16
#define DKK 64
#define MTOT (BB * SS)   // 8192

// Scratch device globals (no allocation allowed)
__device__ float g_Q[BB * HH * SS * DKK];   // [B,H,S,DK]
__device__ float g_K[BB * HH * SS * DKK];
__device__ float g_V[BB * HH * SS * DKK];
__device__ float g_ATT[MTOT * DD];          // [B,S,D]

// ---------------------------------------------------------------------------
// Helpers: tf32 conversion + m16n8k8 tf32 mma
// ---------------------------------------------------------------------------
__device__ __forceinline__ uint32_t f2tf32(float x) {
    uint32_t y;
    asm("cvt.rna.tf32.f32 %0, %1;" : "=r"(y) : "f"(x));
    return y;
}

__device__ __forceinline__ void mma_tf32(float d[4], const uint32_t a[4], const uint32_t b[2]) {
    asm volatile(
        "mma.sync.aligned.m16n8k8.row.col.f32.tf32.tf32.f32 "
        "{%0,%1,%2,%3}, {%4,%5,%6,%7}, {%8,%9}, {%0,%1,%2,%3};"
        : "+f"(d[0]), "+f"(d[1]), "+f"(d[2]), "+f"(d[3])
        : "r"(a[0]), "r"(a[1]), "r"(a[2]), "r"(a[3]), "r"(b[0]), "r"(b[1]));
}

// ---------------------------------------------------------------------------
// TF32 GEMM core: C[m][n] = sum_k A[m][k] * W[n][k], 128x128 tile, K=1024.
// 256 threads = 8 warps in 2(m) x 4(n); warp tile 64x32 = 4x4 m16n8 frags.
// Smem stride 20 words -> fragment loads are 32-bank conflict-free.
// ---------------------------------------------------------------------------
#define LDP 20

__device__ __forceinline__ void gemm_core_tf32(
    const float* __restrict__ A, const float* __restrict__ W,
    int m0, int n0, float acc[4][4][4],
    uint32_t* As, uint32_t* Ws)
{
    const int t    = threadIdx.x;
    const int lane = t & 31;
    const int warp = t >> 5;
    const int wm   = warp >> 2;   // 0..1
    const int wn   = warp & 3;    // 0..3
    const int qq   = lane & 3;
    const int l4   = lane >> 2;

    // per-thread gmem load coords (2 float4 per matrix per chunk)
    const int idx0 = t, idx1 = t + 256;
    const int ra0 = idx0 >> 2, ca0 = (idx0 & 3) * 4;
    const int ra1 = idx1 >> 2, ca1 = (idx1 & 3) * 4;

    const float* a0p = A + (size_t)(m0 + ra0) * DD + ca0;
    const float* a1p = A + (size_t)(m0 + ra1) * DD + ca1;
    const float* w0p = W + (size_t)(n0 + ra0) * DD + ca0;
    const float* w1p = W + (size_t)(n0 + ra1) * DD + ca1;

    float4 pa0 = *(const float4*)(a0p);
    float4 pa1 = *(const float4*)(a1p);
    float4 pw0 = *(const float4*)(w0p);
    float4 pw1 = *(const float4*)(w1p);

    for (int k0 = 0; k0 < DD; k0 += 16) {
        __syncthreads();
        As[ra0 * LDP + ca0 + 0] = f2tf32(pa0.x);
        As[ra0 * LDP + ca0 + 1] = f2tf32(pa0.y);
        As[ra0 * LDP + ca0 + 2] = f2tf32(pa0.z);
        As[ra0 * LDP + ca0 + 3] = f2tf32(pa0.w);
        As[ra1 * LDP + ca1 + 0] = f2tf32(pa1.x);
        As[ra1 * LDP + ca1 + 1] = f2tf32(pa1.y);
        As[ra1 * LDP + ca1 + 2] = f2tf32(pa1.z);
        As[ra1 * LDP + ca1 + 3] = f2tf32(pa1.w);
        Ws[ra0 * LDP + ca0 + 0] = f2tf32(pw0.x);
        Ws[ra0 * LDP + ca0 + 1] = f2tf32(pw0.y);
        Ws[ra0 * LDP + ca0 + 2] = f2tf32(pw0.z);
        Ws[ra0 * LDP + ca0 + 3] = f2tf32(pw0.w);
        Ws[ra1 * LDP + ca1 + 0] = f2tf32(pw1.x);
        Ws[ra1 * LDP + ca1 + 1] = f2tf32(pw1.y);
        Ws[ra1 * LDP + ca1 + 2] = f2tf32(pw1.z);
        Ws[ra1 * LDP + ca1 + 3] = f2tf32(pw1.w);
        __syncthreads();

        if (k0 + 16 < DD) {
            pa0 = *(const float4*)(a0p + k0 + 16);
            pa1 = *(const float4*)(a1p + k0 + 16);
            pw0 = *(const float4*)(w0p + k0 + 16);
            pw1 = *(const float4*)(w1p + k0 + 16);
        }

#pragma unroll
        for (int kf = 0; kf < 2; kf++) {
            const int k = kf * 8;
            uint32_t af[4][4], bf[4][2];
#pragma unroll
            for (int mi = 0; mi < 4; mi++) {
                int m = wm * 64 + mi * 16 + l4;
                af[mi][0] = As[m * LDP + k + qq];
                af[mi][1] = As[(m + 8) * LDP + k + qq];
                af[mi][2] = As[m * LDP + k + qq + 4];
                af[mi][3] = As[(m + 8) * LDP + k + qq + 4];
            }
#pragma unroll
            for (int ni = 0; ni < 4; ni++) {
                int n = wn * 32 + ni * 8 + l4;
                bf[ni][0] = Ws[n * LDP + k + qq];
                bf[ni][1] = Ws[n * LDP + k + qq + 4];
            }
#pragma unroll
            for (int mi = 0; mi < 4; mi++)
#pragma unroll
                for (int ni = 0; ni < 4; ni++)
                    mma_tf32(acc[mi][ni], af[mi], bf[ni]);
        }
    }
}

// ---------------------------------------------------------------------------
// QKV projections -> head-split [B,H,S,DK]
// ---------------------------------------------------------------------------
__global__ __launch_bounds__(256) void qkv_proj_kernel(
    const float* __restrict__ q, const float* __restrict__ k, const float* __restrict__ v,
    const float* __restrict__ wq, const float* __restrict__ bq,
    const float* __restrict__ wk, const float* __restrict__ bk,
    const float* __restrict__ wv, const float* __restrict__ bv)
{
    __shared__ uint32_t As[128 * LDP];
    __shared__ uint32_t Ws[128 * LDP];

    const float* A; const float* W; const float* bias; float* out;
    if (blockIdx.z == 0)      { A = q; W = wq; bias = bq; out = g_Q; }
    else if (blockIdx.z == 1) { A = k; W = wk; bias = bk; out = g_K; }
    else                      { A = v; W = wv; bias = bv; out = g_V; }

    const int m0 = blockIdx.x * 128;
    const int n0 = blockIdx.y * 128;

    float acc[4][4][4];
#pragma unroll
    for (int a = 0; a < 4; a++)
#pragma unroll
        for (int b = 0; b < 4; b++)
#pragma unroll
            for (int c = 0; c < 4; c++) acc[a][b][c] = 0.f;

    gemm_core_tf32(A, W, m0, n0, acc, As, Ws);

    const int lane = threadIdx.x & 31;
    const int warp = threadIdx.x >> 5;
    const int wm = warp >> 2, wn = warp & 3;
    const int qq = lane & 3, l4 = lane >> 2;

#pragma unroll
    for (int mi = 0; mi < 4; mi++) {
#pragma unroll
        for (int rr = 0; rr < 2; rr++) {
            int m = m0 + wm * 64 + mi * 16 + l4 + rr * 8;
            int b = m >> 11;
            int s = m & 2047;
#pragma unroll
            for (int ni = 0; ni < 4; ni++) {
                int n = n0 + wn * 32 + ni * 8 + 2 * qq;
                int h = n >> 6;
                int dk = n & 63;
                float2 rv;
                rv.x = acc[mi][ni][rr * 2 + 0] + bias[n];
                rv.y = acc[mi][ni][rr * 2 + 1] + bias[n + 1];
                *(float2*)&out[((size_t)(b * HH + h) * SS + s) * DKK + dk] = rv;
            }
        }
    }
}

// ---------------------------------------------------------------------------
// Output projection: out = ATT @ Wo^T + bo
// ---------------------------------------------------------------------------
__global__ __launch_bounds__(256) void out_proj_kernel(
    const float* __restrict__ wo, const float* __restrict__ bo,
    float* __restrict__ out)
{
    __shared__ uint32_t As[128 * LDP];
    __shared__ uint32_t Ws[128 * LDP];

    const int m0 = blockIdx.x * 128;
    const int n0 = blockIdx.y * 128;

    float acc[4][4][4];
#pragma unroll
    for (int a = 0; a < 4; a++)
#pragma unroll
        for (int b = 0; b < 4; b++)
#pragma unroll
            for (int c = 0; c < 4; c++) acc[a][b][c] = 0.f;

    gemm_core_tf32(g_ATT, wo, m0, n0, acc, As, Ws);

    const int lane = threadIdx.x & 31;
    const int warp = threadIdx.x >> 5;
    const int wm = warp >> 2, wn = warp & 3;
    const int qq = lane & 3, l4 = lane >> 2;

#pragma unroll
    for (int mi = 0; mi < 4; mi++) {
#pragma unroll
        for (int rr = 0; rr < 2; rr++) {
            int m = m0 + wm * 64 + mi * 16 + l4 + rr * 8;
#pragma unroll
            for (int ni = 0; ni < 4; ni++) {
                int n = n0 + wn * 32 + ni * 8 + 2 * qq;
                float2 rv;
                rv.x = acc[mi][ni][rr * 2 + 0] + bo[n];
                rv.y = acc[mi][ni][rr * 2 + 1] + bo[n + 1];
                *(float2*)&out[(size_t)m * DD + n] = rv;
            }
        }
    }
}

// ---------------------------------------------------------------------------
// Flash attention (causal), TF32 tensor cores.
// Block: 256 thr (8 warps), q-tile 128 rows; warp w owns rows 16w..16w+15.
// kt loop over 64-row K/V tiles. Q frags in registers; P via smem (reuses Qs).
// Smem pads: Qs/Ps ld=68, Ks ld=68, Vs ld=72 (conflict-free frag patterns).
// ---------------------------------------------------------------------------
#define LQ 68
#define LK 68
#define LV 72
#define ATTN_SMEM ((128 * LQ + 64 * LK + 64 * LV) * 4)

__global__ __launch_bounds__(256) void attn_kernel()
{
    extern __shared__ uint32_t sm[];
    uint32_t* Qs = sm;                 // 128 x LQ (reused as Ps)
    uint32_t* Ks = sm + 128 * LQ;      // 64 x LK
    uint32_t* Vs = Ks + 64 * LK;       // 64 x LV
    uint32_t* Ps = Qs;

    const int t    = threadIdx.x;
    const int lane = t & 31;
    const int w    = t >> 5;
    const int qq   = lane & 3;
    const int l4   = lane >> 2;

    const int bx = blockIdx.x;   // q-tile (128 rows)
    const int h  = blockIdx.y;
    const int b  = blockIdx.z;

    const float* Qbase = g_Q + ((size_t)(b * HH + h) * SS) * DKK;
    const float* Kbase = g_K + ((size_t)(b * HH + h) * SS) * DKK;
    const float* Vbase = g_V + ((size_t)(b * HH + h) * SS) * DKK;

    // Load Q tile 128x64 (tf32)
    for (int idx = t; idx < 128 * 16; idx += 256) {
        int r  = idx >> 4;
        int c4 = (idx & 15) * 4;
        float4 qv = *(const float4*)&Qbase[(size_t)(bx * 128 + r) * DKK + c4];
        Qs[r * LQ + c4 + 0] = f2tf32(qv.x);
        Qs[r * LQ + c4 + 1] = f2tf32(qv.y);
        Qs[r * LQ + c4 + 2] = f2tf32(qv.z);
        Qs[r * LQ + c4 + 3] = f2tf32(qv.w);
    }
    __syncthreads();

    // Q fragments in registers (8 k-frags x 4 regs)
    const int rl = 16 * w + l4;        // local row (lo)
    uint32_t aq[8][4];
#pragma unroll
    for (int kf = 0; kf < 8; kf++) {
        aq[kf][0] = Qs[rl * LQ + 8 * kf + qq];
        aq[kf][1] = Qs[(rl + 8) * LQ + 8 * kf + qq];
        aq[kf][2] = Qs[rl * LQ + 8 * kf + qq + 4];
        aq[kf][3] = Qs[(rl + 8) * LQ + 8 * kf + qq + 4];
    }

    const int row_lo = bx * 128 + rl;
    const int row_hi = row_lo + 8;

    float m_lo = -1e30f, m_hi = -1e30f, l_lo = 0.f, l_hi = 0.f;
    float Oacc[8][4];
#pragma unroll
    for (int j = 0; j < 8; j++)
#pragma unroll
        for (int c = 0; c < 4; c++) Oacc[j][c] = 0.f;

    const int kt_max = 2 * bx + 1;
    for (int kt = 0; kt <= kt_max; kt++) {
        __syncthreads();   // prior iter fully consumed Ks/Vs/Ps (also covers Q frag loads)

        // Load K,V tiles 64x64 (tf32)
        const float* Kt = Kbase + (size_t)(kt * 64) * DKK;
        const float* Vt = Vbase + (size_t)(kt * 64) * DKK;
        for (int idx = t; idx < 64 * 16; idx += 256) {
            int r  = idx >> 4;
            int c4 = (idx & 15) * 4;
            float4 kv = *(const float4*)&Kt[(size_t)r * DKK + c4];
            Ks[r * LK + c4 + 0] = f2tf32(kv.x);
            Ks[r * LK + c4 + 1] = f2tf32(kv.y);
            Ks[r * LK + c4 + 2] = f2tf32(kv.z);
            Ks[r * LK + c4 + 3] = f2tf32(kv.w);
            float4 vv = *(const float4*)&Vt[(size_t)r * DKK + c4];
            Vs[r * LV + c4 + 0] = f2tf32(vv.x);
            Vs[r * LV + c4 + 1] = f2tf32(vv.y);
            Vs[r * LV + c4 + 2] = f2tf32(vv.z);
            Vs[r * LV + c4 + 3] = f2tf32(vv.w);
        }
        __syncthreads();

        // S = Q @ K^T (warp: 16 rows x 64 cols = 8 n-frags)
        float Sacc[8][4];
#pragma unroll
        for (int j = 0; j < 8; j++)
#pragma unroll
            for (int c = 0; c < 4; c++) Sacc[j][c] = 0.f;

#pragma unroll
        for (int kf = 0; kf < 8; kf++) {
#pragma unroll
            for (int j = 0; j < 8; j++) {
                uint32_t bf[2];
                bf[0] = Ks[(8 * j + l4) * LK + 8 * kf + qq];
                bf[1] = Ks[(8 * j + l4) * LK + 8 * kf + qq + 4];
                mma_tf32(Sacc[j], aq[kf], bf);
            }
        }

#pragma unroll
        for (int j = 0; j < 8; j++)
#pragma unroll
            for (int c = 0; c < 4; c++) Sacc[j][c] *= 0.125f;

        // Causal mask (only the two diagonal-adjacent tiles)
        if (kt >= 2 * bx) {
#pragma unroll
            for (int j = 0; j < 8; j++) {
                int col = kt * 64 + 8 * j + 2 * qq;
                if (col     > row_lo) Sacc[j][0] = -1e30f;
                if (col + 1 > row_lo) Sacc[j][1] = -1e30f;
                if (col     > row_hi) Sacc[j][2] = -1e30f;
                if (col + 1 > row_hi) Sacc[j][3] = -1e30f;
            }
        }

        // Online softmax (row groups: 4 threads sharing lane>>2)
        float mt_lo = -1e30f, mt_hi = -1e30f;
#pragma unroll
        for (int j = 0; j < 8; j++) {
            mt_lo = fmaxf(mt_lo, fmaxf(Sacc[j][0], Sacc[j][1]));
            mt_hi = fmaxf(mt_hi, fmaxf(Sacc[j][2], Sacc[j][3]));
        }
        mt_lo = fmaxf(mt_lo, __shfl_xor_sync(0xffffffffu, mt_lo, 1));
        mt_lo = fmaxf(mt_lo, __shfl_xor_sync(0xffffffffu, mt_lo, 2));
        mt_hi = fmaxf(mt_hi, __shfl_xor_sync(0xffffffffu, mt_hi, 1));
        mt_hi = fmaxf(mt_hi, __shfl_xor_sync(0xffffffffu, mt_hi, 2));

        float mn_lo = fmaxf(m_lo, mt_lo);
        float mn_hi = fmaxf(m_hi, mt_hi);
        float al_lo = __expf(m_lo - mn_lo);
        float al_hi = __expf(m_hi - mn_hi);

        float ls_lo = 0.f, ls_hi = 0.f;
#pragma unroll
        for (int j = 0; j < 8; j++) {
            Sacc[j][0] = __expf(Sacc[j][0] - mn_lo);
            Sacc[j][1] = __expf(Sacc[j][1] - mn_lo);
            Sacc[j][2] = __expf(Sacc[j][2] - mn_hi);
            Sacc[j][3] = __expf(Sacc[j][3] - mn_hi);
            ls_lo += Sacc[j][0] + Sacc[j][1];
            ls_hi += Sacc[j][2] + Sacc[j][3];
        }
        ls_lo += __shfl_xor_sync(0xffffffffu, ls_lo, 1);
        ls_lo += __shfl_xor_sync(0xffffffffu, ls_lo, 2);
        ls_hi += __shfl_xor_sync(0xffffffffu, ls_hi, 1);
        ls_hi += __shfl_xor_sync(0xffffffffu, ls_hi, 2);

        l_lo = l_lo * al_lo + ls_lo;
        l_hi = l_hi * al_hi + ls_hi;
        m_lo = mn_lo;
        m_hi = mn_hi;

        // Stage P (tf32) into Ps (reuses Q buffer; warp-private rows)
#pragma unroll
        for (int j = 0; j < 8; j++) {
            uint2 p0 = make_uint2(f2tf32(Sacc[j][0]), f2tf32(Sacc[j][1]));
            uint2 p1 = make_uint2(f2tf32(Sacc[j][2]), f2tf32(Sacc[j][3]));
            *(uint2*)&Ps[rl * LQ + 8 * j + 2 * qq]       = p0;
            *(uint2*)&Ps[(rl + 8) * LQ + 8 * j + 2 * qq] = p1;
        }

#pragma unroll
        for (int j = 0; j < 8; j++) {
            Oacc[j][0] *= al_lo;
            Oacc[j][1] *= al_lo;
            Oacc[j][2] *= al_hi;
            Oacc[j][3] *= al_hi;
        }
        __syncwarp();

        // O += P @ V
#pragma unroll
        for (int kf = 0; kf < 8; kf++) {
            uint32_t ap[4];
            ap[0] = Ps[rl * LQ + 8 * kf + qq];
            ap[1] = Ps[(rl + 8) * LQ + 8 * kf + qq];
            ap[2] = Ps[rl * LQ + 8 * kf + qq + 4];
            ap[3] = Ps[(rl + 8) * LQ + 8 * kf + qq + 4];
#pragma unroll
            for (int j = 0; j < 8; j++) {
                uint32_t bf[2];
                bf[0] = Vs[(8 * kf + qq) * LV + 8 * j + l4];
                bf[1] = Vs[(8 * kf + qq + 4) * LV + 8 * j + l4];
                mma_tf32(Oacc[j], ap, bf);
            }
        }
    }

    // Finalize -> g_ATT [B,S,D]
    float il_lo = 1.f / l_lo;
    float il_hi = 1.f / l_hi;
    float* out_lo = g_ATT + ((size_t)(b * SS + row_lo)) * DD + h * DKK;
    float* out_hi = g_ATT + ((size_t)(b * SS + row_hi)) * DD + h * DKK;
#pragma unroll
    for (int j = 0; j < 8; j++) {
        int dk = 8 * j + 2 * qq;
        *(float2*)&out_lo[dk] = make_float2(Oacc[j][0] * il_lo, Oacc[j][1] * il_lo);
        *(float2*)&out_hi[dk] = make_float2(Oacc[j][2] * il_hi, Oacc[j][3] * il_hi);
    }
}

// ---------------------------------------------------------------------------
// Entry point. Inputs: q,k,v,mask,w_q,b_q,w_k,b_k,w_v,b_v,w_o,b_o
// ---------------------------------------------------------------------------
extern "C" void kernel_launch(void* const* d_in, const int* in_sizes, int n_in,
                              void* d_out, int out_size)
{
    const float* q  = (const float*)d_in[0];
    const float* k  = (const float*)d_in[1];
    const float* v  = (const float*)d_in[2];
    const float* wq = (const float*)d_in[4];
    const float* bq = (const float*)d_in[5];
    const float* wk = (const float*)d_in[6];
    const float* bk = (const float*)d_in[7];
    const float* wv = (const float*)d_in[8];
    const float* bv = (const float*)d_in[9];
    const float* wo = (const float*)d_in[10];
    const float* bo = (const float*)d_in[11];
    float* out = (float*)d_out;

    dim3 gproj(MTOT / 128, DD / 128, 3);
    qkv_proj_kernel<<<gproj, 256>>>(q, k, v, wq, bq, wk, bk, wv, bv);

    cudaFuncSetAttribute(attn_kernel, cudaFuncAttributeMaxDynamicSharedMemorySize, ATTN_SMEM);
    dim3 gattn(SS / 128, HH, BB);
    attn_kernel<<<gattn, 256, ATTN_SMEM>>>();

    dim3 gout(MTOT / 128, DD / 128, 1);
    out_proj_kernel<<<gout, 256>>>(wo, bo, out);
}

// round 4
// speedup vs baseline: 7.3401x; 1.9475x over previous
#include <cuda_runtime.h>
#include <cuda_fp16.h>
#include <math.h>
#include <stdint.h>

// Problem constants
#define BB 4
#define SS 2048
#define DD 1024
#define HH 16
#define DKK 64
#define MTOT (BB * SS)   // 8192

// Scratch device globals (half precision intermediates)
__device__ __half g_Q[BB * HH * SS * DKK];   // [B,H,S,DK]
__device__ __half g_K[BB * HH * SS * DKK];
__device__ __half g_V[BB * HH * SS * DKK];
__device__ __half g_ATT[(size_t)MTOT * DD];  // [B,S,D]

// ---------------------------------------------------------------------------
// Helpers
// ---------------------------------------------------------------------------
__device__ __forceinline__ uint32_t su(const void* p) {
    return (uint32_t)__cvta_generic_to_shared(p);
}
__device__ __forceinline__ void ldm4(uint32_t* r, uint32_t a) {
    asm volatile("ldmatrix.sync.aligned.m8n8.x4.shared.b16 {%0,%1,%2,%3},[%4];"
        : "=r"(r[0]), "=r"(r[1]), "=r"(r[2]), "=r"(r[3]) : "r"(a));
}
__device__ __forceinline__ void ldm4t(uint32_t* r, uint32_t a) {
    asm volatile("ldmatrix.sync.aligned.m8n8.x4.trans.shared.b16 {%0,%1,%2,%3},[%4];"
        : "=r"(r[0]), "=r"(r[1]), "=r"(r[2]), "=r"(r[3]) : "r"(a));
}
__device__ __forceinline__ void mma16(float* d, const uint32_t* a, const uint32_t* b) {
    asm volatile(
        "mma.sync.aligned.m16n8k16.row.col.f32.f16.f16.f32 "
        "{%0,%1,%2,%3},{%4,%5,%6,%7},{%8,%9},{%0,%1,%2,%3};"
        : "+f"(d[0]), "+f"(d[1]), "+f"(d[2]), "+f"(d[3])
        : "r"(a[0]), "r"(a[1]), "r"(a[2]), "r"(a[3]), "r"(b[0]), "r"(b[1]));
}
__device__ __forceinline__ uint32_t packh2(float x, float y) {
    __half2 h = __floats2half2_rn(x, y);
    return *(uint32_t*)&h;
}
__device__ __forceinline__ void cpa16(uint32_t d, const void* s) {
    asm volatile("cp.async.cg.shared.global [%0],[%1],16;" :: "r"(d), "l"(s));
}
#define CP_COMMIT() asm volatile("cp.async.commit_group;")

// ---------------------------------------------------------------------------
// FP16 GEMM tile compute (shared by proj kernels)
// 128x128 tile, k-chunk 16. 8 warps 2(m)x4(n), warp tile 64x32.
// smem rows padded to 24 halves (48B) -> ldmatrix conflict-free.
// ---------------------------------------------------------------------------
#define GROW 24

// ---------------------------------------------------------------------------
// QKV projections: Y = X @ W^T + b -> half, head-split [B,H,S,DK]
// ---------------------------------------------------------------------------
__global__ __launch_bounds__(256) void qkv_proj_kernel(
    const float* __restrict__ q, const float* __restrict__ k, const float* __restrict__ v,
    const float* __restrict__ wq, const float* __restrict__ bq,
    const float* __restrict__ wk, const float* __restrict__ bk,
    const float* __restrict__ wv, const float* __restrict__ bv)
{
    __shared__ __half As[128 * GROW];
    __shared__ __half Ws[128 * GROW];

    const float* A; const float* W; const float* bias; __half* out;
    if (blockIdx.z == 0)      { A = q; W = wq; bias = bq; out = g_Q; }
    else if (blockIdx.z == 1) { A = k; W = wk; bias = bk; out = g_K; }
    else                      { A = v; W = wv; bias = bv; out = g_V; }

    const int t    = threadIdx.x;
    const int lane = t & 31;
    const int warp = t >> 5;
    const int wm   = warp >> 2;
    const int wn   = warp & 3;
    const int qq   = lane & 3;
    const int l4   = lane >> 2;

    const int m0 = blockIdx.x * 128;
    const int n0 = blockIdx.y * 128;

    // gmem load coords: 128 rows x 4 quads = 512 float4, 2 per thread
    const int r0 = t >> 2;
    const int c0 = (t & 3) * 4;
    const float* ap0 = A + (size_t)(m0 + r0) * DD + c0;
    const float* ap1 = ap0 + (size_t)64 * DD;
    const float* wp0 = W + (size_t)(n0 + r0) * DD + c0;
    const float* wp1 = wp0 + (size_t)64 * DD;

    float4 pa0 = *(const float4*)ap0;
    float4 pa1 = *(const float4*)ap1;
    float4 pw0 = *(const float4*)wp0;
    float4 pw1 = *(const float4*)wp1;

    // ldmatrix addresses (fixed: single-buffer smem, within-chunk k only)
    const int rowoff = (lane & 7) + ((lane >> 3) & 1) * 8;   // A rows
    const int akoff  = ((lane >> 4) & 1) * 8;                // A k halves
    const int noff   = (lane & 7) + ((lane >> 4) & 1) * 8;   // B n rows
    const int bkoff  = ((lane >> 3) & 1) * 8;                // B k halves
    uint32_t aAddr[4], bAddr[2];
#pragma unroll
    for (int mi = 0; mi < 4; mi++)
        aAddr[mi] = su(&As[(wm * 64 + mi * 16 + rowoff) * GROW + akoff]);
#pragma unroll
    for (int p = 0; p < 2; p++)
        bAddr[p] = su(&Ws[(wn * 32 + p * 16 + noff) * GROW + bkoff]);

    float acc[4][4][4];
#pragma unroll
    for (int a = 0; a < 4; a++)
#pragma unroll
        for (int b = 0; b < 4; b++)
#pragma unroll
            for (int c = 0; c < 4; c++) acc[a][b][c] = 0.f;

    for (int k0 = 0; k0 < DD; k0 += 16) {
        __syncthreads();
        *(__half2*)&As[r0 * GROW + c0]            = __floats2half2_rn(pa0.x, pa0.y);
        *(__half2*)&As[r0 * GROW + c0 + 2]        = __floats2half2_rn(pa0.z, pa0.w);
        *(__half2*)&As[(r0 + 64) * GROW + c0]     = __floats2half2_rn(pa1.x, pa1.y);
        *(__half2*)&As[(r0 + 64) * GROW + c0 + 2] = __floats2half2_rn(pa1.z, pa1.w);
        *(__half2*)&Ws[r0 * GROW + c0]            = __floats2half2_rn(pw0.x, pw0.y);
        *(__half2*)&Ws[r0 * GROW + c0 + 2]        = __floats2half2_rn(pw0.z, pw0.w);
        *(__half2*)&Ws[(r0 + 64) * GROW + c0]     = __floats2half2_rn(pw1.x, pw1.y);
        *(__half2*)&Ws[(r0 + 64) * GROW + c0 + 2] = __floats2half2_rn(pw1.z, pw1.w);
        __syncthreads();

        if (k0 + 16 < DD) {
            pa0 = *(const float4*)(ap0 + k0 + 16);
            pa1 = *(const float4*)(ap1 + k0 + 16);
            pw0 = *(const float4*)(wp0 + k0 + 16);
            pw1 = *(const float4*)(wp1 + k0 + 16);
        }

        uint32_t af[4][4], bf[4][2];
#pragma unroll
        for (int mi = 0; mi < 4; mi++) ldm4(af[mi], aAddr[mi]);
#pragma unroll
        for (int p = 0; p < 2; p++) {
            uint32_t tmp[4];
            ldm4(tmp, bAddr[p]);
            bf[2 * p][0] = tmp[0]; bf[2 * p][1] = tmp[1];
            bf[2 * p + 1][0] = tmp[2]; bf[2 * p + 1][1] = tmp[3];
        }
#pragma unroll
        for (int mi = 0; mi < 4; mi++)
#pragma unroll
            for (int ni = 0; ni < 4; ni++)
                mma16(acc[mi][ni], af[mi], bf[ni]);
    }

    // Epilogue -> half, head-split
#pragma unroll
    for (int mi = 0; mi < 4; mi++) {
#pragma unroll
        for (int rr = 0; rr < 2; rr++) {
            int m = m0 + wm * 64 + mi * 16 + l4 + rr * 8;
            int b = m >> 11;
            int s = m & 2047;
#pragma unroll
            for (int ni = 0; ni < 4; ni++) {
                int n  = n0 + wn * 32 + ni * 8 + 2 * qq;
                int h  = n >> 6;
                int dk = n & 63;
                __half2 hv = __floats2half2_rn(acc[mi][ni][rr * 2 + 0] + bias[n],
                                               acc[mi][ni][rr * 2 + 1] + bias[n + 1]);
                *(__half2*)&out[((size_t)(b * HH + h) * SS + s) * DKK + dk] = hv;
            }
        }
    }
}

// ---------------------------------------------------------------------------
// Output projection: out(f32) = g_ATT(half) @ Wo^T + bo
// ---------------------------------------------------------------------------
__global__ __launch_bounds__(256) void out_proj_kernel(
    const float* __restrict__ wo, const float* __restrict__ bo,
    float* __restrict__ out)
{
    __shared__ __half As[128 * GROW];
    __shared__ __half Ws[128 * GROW];

    const int t    = threadIdx.x;
    const int lane = t & 31;
    const int warp = t >> 5;
    const int wm   = warp >> 2;
    const int wn   = warp & 3;
    const int qq   = lane & 3;
    const int l4   = lane >> 2;

    const int m0 = blockIdx.x * 128;
    const int n0 = blockIdx.y * 128;

    // A (half): 128 rows x 16 halves = 256 chunks of 8 halves, 1 per thread
    const int ra = t >> 1;
    const int ca = (t & 1) * 8;
    const __half* aptr = g_ATT + (size_t)(m0 + ra) * DD + ca;

    // W (f32): as qkv
    const int r0 = t >> 2;
    const int c0 = (t & 3) * 4;
    const float* wp0 = wo + (size_t)(n0 + r0) * DD + c0;
    const float* wp1 = wp0 + (size_t)64 * DD;

    uint4  pa  = *(const uint4*)aptr;
    float4 pw0 = *(const float4*)wp0;
    float4 pw1 = *(const float4*)wp1;

    const int rowoff = (lane & 7) + ((lane >> 3) & 1) * 8;
    const int akoff  = ((lane >> 4) & 1) * 8;
    const int noff   = (lane & 7) + ((lane >> 4) & 1) * 8;
    const int bkoff  = ((lane >> 3) & 1) * 8;
    uint32_t aAddr[4], bAddr[2];
#pragma unroll
    for (int mi = 0; mi < 4; mi++)
        aAddr[mi] = su(&As[(wm * 64 + mi * 16 + rowoff) * GROW + akoff]);
#pragma unroll
    for (int p = 0; p < 2; p++)
        bAddr[p] = su(&Ws[(wn * 32 + p * 16 + noff) * GROW + bkoff]);

    float acc[4][4][4];
#pragma unroll
    for (int a = 0; a < 4; a++)
#pragma unroll
        for (int b = 0; b < 4; b++)
#pragma unroll
            for (int c = 0; c < 4; c++) acc[a][b][c] = 0.f;

    for (int k0 = 0; k0 < DD; k0 += 16) {
        __syncthreads();
        *(uint4*)&As[ra * GROW + ca] = pa;
        *(__half2*)&Ws[r0 * GROW + c0]            = __floats2half2_rn(pw0.x, pw0.y);
        *(__half2*)&Ws[r0 * GROW + c0 + 2]        = __floats2half2_rn(pw0.z, pw0.w);
        *(__half2*)&Ws[(r0 + 64) * GROW + c0]     = __floats2half2_rn(pw1.x, pw1.y);
        *(__half2*)&Ws[(r0 + 64) * GROW + c0 + 2] = __floats2half2_rn(pw1.z, pw1.w);
        __syncthreads();

        if (k0 + 16 < DD) {
            pa  = *(const uint4*)(aptr + k0 + 16);
            pw0 = *(const float4*)(wp0 + k0 + 16);
            pw1 = *(const float4*)(wp1 + k0 + 16);
        }

        uint32_t af[4][4], bf[4][2];
#pragma unroll
        for (int mi = 0; mi < 4; mi++) ldm4(af[mi], aAddr[mi]);
#pragma unroll
        for (int p = 0; p < 2; p++) {
            uint32_t tmp[4];
            ldm4(tmp, bAddr[p]);
            bf[2 * p][0] = tmp[0]; bf[2 * p][1] = tmp[1];
            bf[2 * p + 1][0] = tmp[2]; bf[2 * p + 1][1] = tmp[3];
        }
#pragma unroll
        for (int mi = 0; mi < 4; mi++)
#pragma unroll
            for (int ni = 0; ni < 4; ni++)
                mma16(acc[mi][ni], af[mi], bf[ni]);
    }

#pragma unroll
    for (int mi = 0; mi < 4; mi++) {
#pragma unroll
        for (int rr = 0; rr < 2; rr++) {
            int m = m0 + wm * 64 + mi * 16 + l4 + rr * 8;
#pragma unroll
            for (int ni = 0; ni < 4; ni++) {
                int n = n0 + wn * 32 + ni * 8 + 2 * qq;
                float2 rv;
                rv.x = acc[mi][ni][rr * 2 + 0] + bo[n];
                rv.y = acc[mi][ni][rr * 2 + 1] + bo[n + 1];
                *(float2*)&out[(size_t)m * DD + n] = rv;
            }
        }
    }
}

// ---------------------------------------------------------------------------
// Flash attention (causal), FP16 mma + ldmatrix + cp.async double-buffered K/V.
// 256 thr (8 warps) x 128 q-rows; warp w owns rows 16w..16w+15.
// smem rows padded to 72 halves (144B).
// ---------------------------------------------------------------------------
#define AR 72
#define Q_HALVES (128 * AR)
#define KV_HALVES (64 * AR)
#define ATTN_SMEM ((Q_HALVES + 4 * KV_HALVES) * 2)

__global__ __launch_bounds__(256) void attn_kernel()
{
    extern __shared__ __half sm[];
    __half* Qs = sm;                       // 128 x AR
    __half* Ks0 = Qs + Q_HALVES;           // stage buffers
    __half* Vs0 = Ks0 + KV_HALVES;
    __half* Ks1 = Vs0 + KV_HALVES;
    __half* Vs1 = Ks1 + KV_HALVES;

    const int t    = threadIdx.x;
    const int lane = t & 31;
    const int w    = t >> 5;
    const int qq   = lane & 3;
    const int l4   = lane >> 2;

    const int bx = blockIdx.x;
    const int h  = blockIdx.y;
    const int b  = blockIdx.z;

    const __half* Qbase = g_Q + ((size_t)(b * HH + h) * SS) * DKK;
    const __half* Kbase = g_K + ((size_t)(b * HH + h) * SS) * DKK;
    const __half* Vbase = g_V + ((size_t)(b * HH + h) * SS) * DKK;

    const uint32_t ksB[2] = { su(Ks0), su(Ks1) };
    const uint32_t vsB[2] = { su(Vs0), su(Vs1) };

    // cp.async coords
    const int qr = t >> 3;          // Q: 1024 chunks, 4/thread (rows qr, qr+32, ...)
    const int qc = (t & 7) * 16;    // byte offset within 128B row
    const int kr = t >> 3;          // KV: 512 chunks, 2/thread
    const int kc = (t & 7) * 16;

    // Issue Q
    {
        uint32_t qdst = su(Qs);
#pragma unroll
        for (int i = 0; i < 4; i++) {
            int r = qr + 32 * i;
            cpa16(qdst + r * (AR * 2) + qc, (const char*)(Qbase + (size_t)(bx * 128 + r) * DKK) + qc);
        }
    }
    CP_COMMIT();

    // Issue K/V stage 0
    {
        const __half* Kt = Kbase;
        const __half* Vt = Vbase;
#pragma unroll
        for (int i = 0; i < 2; i++) {
            int r = kr + 32 * i;
            cpa16(ksB[0] + r * (AR * 2) + kc, (const char*)(Kt + (size_t)r * DKK) + kc);
            cpa16(vsB[0] + r * (AR * 2) + kc, (const char*)(Vt + (size_t)r * DKK) + kc);
        }
    }
    CP_COMMIT();

    // Wait for Q (leave KV0 in flight), extract Q fragments
    asm volatile("cp.async.wait_group 1;");
    __syncthreads();

    const int rowoff = (lane & 7) + ((lane >> 3) & 1) * 8;
    const int akoff  = ((lane >> 4) & 1) * 8;
    const int noff   = (lane & 7) + ((lane >> 4) & 1) * 8;
    const int bkoff  = ((lane >> 3) & 1) * 8;
    const int vkoff  = ((lane >> 4) & 1) * 8;

    uint32_t aq[4][4];
#pragma unroll
    for (int g = 0; g < 4; g++)
        ldm4(aq[g], su(&Qs[(16 * w + rowoff) * AR + g * 16 + akoff]));

    const int rl = 16 * w + l4;
    const int row_lo = bx * 128 + rl;
    const int row_hi = row_lo + 8;

    float m_lo = -1e30f, m_hi = -1e30f, l_lo = 0.f, l_hi = 0.f;
    float Oacc[8][4];
#pragma unroll
    for (int j = 0; j < 8; j++)
#pragma unroll
        for (int c = 0; c < 4; c++) Oacc[j][c] = 0.f;

    const int kt_max = 2 * bx + 1;
    for (int kt = 0; kt <= kt_max; kt++) {
        const int st = kt & 1;

        // Issue next stage, then wait for current
        if (kt + 1 <= kt_max) {
            const __half* Kt = Kbase + (size_t)(kt + 1) * 64 * DKK;
            const __half* Vt = Vbase + (size_t)(kt + 1) * 64 * DKK;
            const int ns = st ^ 1;
#pragma unroll
            for (int i = 0; i < 2; i++) {
                int r = kr + 32 * i;
                cpa16(ksB[ns] + r * (AR * 2) + kc, (const char*)(Kt + (size_t)r * DKK) + kc);
                cpa16(vsB[ns] + r * (AR * 2) + kc, (const char*)(Vt + (size_t)r * DKK) + kc);
            }
            CP_COMMIT();
            asm volatile("cp.async.wait_group 1;");
        } else {
            asm volatile("cp.async.wait_group 0;");
        }
        __syncthreads();

        // S = Q @ K^T
        float Sacc[8][4];
#pragma unroll
        for (int j = 0; j < 8; j++)
#pragma unroll
            for (int c = 0; c < 4; c++) Sacc[j][c] = 0.f;

#pragma unroll
        for (int g = 0; g < 4; g++) {
#pragma unroll
            for (int p = 0; p < 4; p++) {
                uint32_t tmp[4];
                ldm4(tmp, ksB[st] + ((p * 16 + noff) * AR + g * 16 + bkoff) * 2);
                mma16(Sacc[2 * p],     aq[g], tmp);
                mma16(Sacc[2 * p + 1], aq[g], tmp + 2);
            }
        }

#pragma unroll
        for (int j = 0; j < 8; j++)
#pragma unroll
            for (int c = 0; c < 4; c++) Sacc[j][c] *= 0.125f;

        // Causal mask (only diagonal-adjacent tiles)
        if (kt >= 2 * bx) {
#pragma unroll
            for (int j = 0; j < 8; j++) {
                int col = kt * 64 + 8 * j + 2 * qq;
                if (col     > row_lo) Sacc[j][0] = -1e30f;
                if (col + 1 > row_lo) Sacc[j][1] = -1e30f;
                if (col     > row_hi) Sacc[j][2] = -1e30f;
                if (col + 1 > row_hi) Sacc[j][3] = -1e30f;
            }
        }

        // Online softmax
        float mt_lo = -1e30f, mt_hi = -1e30f;
#pragma unroll
        for (int j = 0; j < 8; j++) {
            mt_lo = fmaxf(mt_lo, fmaxf(Sacc[j][0], Sacc[j][1]));
            mt_hi = fmaxf(mt_hi, fmaxf(Sacc[j][2], Sacc[j][3]));
        }
        mt_lo = fmaxf(mt_lo, __shfl_xor_sync(0xffffffffu, mt_lo, 1));
        mt_lo = fmaxf(mt_lo, __shfl_xor_sync(0xffffffffu, mt_lo, 2));
        mt_hi = fmaxf(mt_hi, __shfl_xor_sync(0xffffffffu, mt_hi, 1));
        mt_hi = fmaxf(mt_hi, __shfl_xor_sync(0xffffffffu, mt_hi, 2));

        float mn_lo = fmaxf(m_lo, mt_lo);
        float mn_hi = fmaxf(m_hi, mt_hi);
        float al_lo = __expf(m_lo - mn_lo);
        float al_hi = __expf(m_hi - mn_hi);

        float ls_lo = 0.f, ls_hi = 0.f;
#pragma unroll
        for (int j = 0; j < 8; j++) {
            Sacc[j][0] = __expf(Sacc[j][0] - mn_lo);
            Sacc[j][1] = __expf(Sacc[j][1] - mn_lo);
            Sacc[j][2] = __expf(Sacc[j][2] - mn_hi);
            Sacc[j][3] = __expf(Sacc[j][3] - mn_hi);
            ls_lo += Sacc[j][0] + Sacc[j][1];
            ls_hi += Sacc[j][2] + Sacc[j][3];
        }
        ls_lo += __shfl_xor_sync(0xffffffffu, ls_lo, 1);
        ls_lo += __shfl_xor_sync(0xffffffffu, ls_lo, 2);
        ls_hi += __shfl_xor_sync(0xffffffffu, ls_hi, 1);
        ls_hi += __shfl_xor_sync(0xffffffffu, ls_hi, 2);

        l_lo = l_lo * al_lo + ls_lo;
        l_hi = l_hi * al_hi + ls_hi;
        m_lo = mn_lo;
        m_hi = mn_hi;

        // P fragments directly in registers (C-frag layout == A-frag layout)
        uint32_t ap[4][4];
#pragma unroll
        for (int g = 0; g < 4; g++) {
            ap[g][0] = packh2(Sacc[2 * g][0],     Sacc[2 * g][1]);
            ap[g][1] = packh2(Sacc[2 * g][2],     Sacc[2 * g][3]);
            ap[g][2] = packh2(Sacc[2 * g + 1][0], Sacc[2 * g + 1][1]);
            ap[g][3] = packh2(Sacc[2 * g + 1][2], Sacc[2 * g + 1][3]);
        }

#pragma unroll
        for (int j = 0; j < 8; j++) {
            Oacc[j][0] *= al_lo;
            Oacc[j][1] *= al_lo;
            Oacc[j][2] *= al_hi;
            Oacc[j][3] *= al_hi;
        }

        // O += P @ V  (V via ldmatrix.trans from [seq][dk] tile)
#pragma unroll
        for (int g = 0; g < 4; g++) {
#pragma unroll
            for (int p = 0; p < 4; p++) {
                uint32_t tmp[4];
                ldm4t(tmp, vsB[st] + ((g * 16 + rowoff) * AR + p * 16 + vkoff) * 2);
                mma16(Oacc[2 * p],     ap[g], tmp);
                mma16(Oacc[2 * p + 1], ap[g], tmp + 2);
            }
        }

        __syncthreads();   // all warps done with stage st before it is refilled
    }

    // Finalize -> g_ATT (half) [B,S,D]
    float il_lo = 1.f / l_lo;
    float il_hi = 1.f / l_hi;
    __half* out_lo = g_ATT + ((size_t)(b * SS + row_lo)) * DD + h * DKK;
    __half* out_hi = g_ATT + ((size_t)(b * SS + row_hi)) * DD + h * DKK;
#pragma unroll
    for (int j = 0; j < 8; j++) {
        int dk = 8 * j + 2 * qq;
        *(__half2*)&out_lo[dk] = __floats2half2_rn(Oacc[j][0] * il_lo, Oacc[j][1] * il_lo);
        *(__half2*)&out_hi[dk] = __floats2half2_rn(Oacc[j][2] * il_hi, Oacc[j][3] * il_hi);
    }
}

// ---------------------------------------------------------------------------
// Entry point. Inputs: q,k,v,mask,w_q,b_q,w_k,b_k,w_v,b_v,w_o,b_o
// ---------------------------------------------------------------------------
extern "C" void kernel_launch(void* const* d_in, const int* in_sizes, int n_in,
                              void* d_out, int out_size)
{
    const float* q  = (const float*)d_in[0];
    const float* k  = (const float*)d_in[1];
    const float* v  = (const float*)d_in[2];
    const float* wq = (const float*)d_in[4];
    const float* bq = (const float*)d_in[5];
    const float* wk = (const float*)d_in[6];
    const float* bk = (const float*)d_in[7];
    const float* wv = (const float*)d_in[8];
    const float* bv = (const float*)d_in[9];
    const float* wo = (const float*)d_in[10];
    const float* bo = (const float*)d_in[11];
    float* out = (float*)d_out;

    dim3 gproj(MTOT / 128, DD / 128, 3);
    qkv_proj_kernel<<<gproj, 256>>>(q, k, v, wq, bq, wk, bk, wv, bv);

    cudaFuncSetAttribute(attn_kernel, cudaFuncAttributeMaxDynamicSharedMemorySize, ATTN_SMEM);
    dim3 gattn(SS / 128, HH, BB);
    attn_kernel<<<gattn, 256, ATTN_SMEM>>>();

    dim3 gout(MTOT / 128, DD / 128, 1);
    out_proj_kernel<<<gout, 256>>>(wo, bo, out);
}

// round 5
// speedup vs baseline: 10.1200x; 1.3787x over previous
#include <cuda_runtime.h>
#include <cuda_fp16.h>
#include <math.h>
#include <stdint.h>

// Problem constants
#define BB 4
#define SS 2048
#define DD 1024
#define HH 16
#define DKK 64
#define MTOT (BB * SS)   // 8192

// Scratch device globals
__device__ __half g_Q[BB * HH * SS * DKK];    // [B,H,S,DK]
__device__ __half g_K[BB * HH * SS * DKK];
__device__ __half g_V[BB * HH * SS * DKK];
__device__ __half g_ATT[(size_t)MTOT * DD];   // [B,S,D]
// half copies of inputs/weights (enable cp.async GEMM operands)
__device__ __half g_qh[(size_t)MTOT * DD];
__device__ __half g_kh[(size_t)MTOT * DD];
__device__ __half g_vh[(size_t)MTOT * DD];
__device__ __half g_wqh[DD * DD];
__device__ __half g_wkh[DD * DD];
__device__ __half g_wvh[DD * DD];
__device__ __half g_woh[DD * DD];

// ---------------------------------------------------------------------------
// Helpers
// ---------------------------------------------------------------------------
__device__ __forceinline__ uint32_t su(const void* p) {
    return (uint32_t)__cvta_generic_to_shared(p);
}
__device__ __forceinline__ void ldm4(uint32_t* r, uint32_t a) {
    asm volatile("ldmatrix.sync.aligned.m8n8.x4.shared.b16 {%0,%1,%2,%3},[%4];"
        : "=r"(r[0]), "=r"(r[1]), "=r"(r[2]), "=r"(r[3]) : "r"(a));
}
__device__ __forceinline__ void ldm4t(uint32_t* r, uint32_t a) {
    asm volatile("ldmatrix.sync.aligned.m8n8.x4.trans.shared.b16 {%0,%1,%2,%3},[%4];"
        : "=r"(r[0]), "=r"(r[1]), "=r"(r[2]), "=r"(r[3]) : "r"(a));
}
__device__ __forceinline__ void mma16(float* d, const uint32_t* a, const uint32_t* b) {
    asm volatile(
        "mma.sync.aligned.m16n8k16.row.col.f32.f16.f16.f32 "
        "{%0,%1,%2,%3},{%4,%5,%6,%7},{%8,%9},{%0,%1,%2,%3};"
        : "+f"(d[0]), "+f"(d[1]), "+f"(d[2]), "+f"(d[3])
        : "r"(a[0]), "r"(a[1]), "r"(a[2]), "r"(a[3]), "r"(b[0]), "r"(b[1]));
}
__device__ __forceinline__ uint32_t packh2(float x, float y) {
    __half2 h = __floats2half2_rn(x, y);
    return *(uint32_t*)&h;
}
__device__ __forceinline__ void cpa16(uint32_t d, const void* s) {
    asm volatile("cp.async.cg.shared.global [%0],[%1],16;" :: "r"(d), "l"(s));
}
#define CP_COMMIT() asm volatile("cp.async.commit_group;")

// ---------------------------------------------------------------------------
// f32 -> f16 streaming convert
// ---------------------------------------------------------------------------
__global__ __launch_bounds__(256) void f2h_kernel(
    const float4* __restrict__ src, uint2* __restrict__ dst, int n4)
{
    int i = blockIdx.x * 256 + threadIdx.x;
    if (i < n4) {
        float4 v = src[i];
        dst[i] = make_uint2(packh2(v.x, v.y), packh2(v.z, v.w));
    }
}

// ---------------------------------------------------------------------------
// 3-stage cp.async pipelined FP16 GEMM core: C = A @ W^T (both [*,1024] half,
// k-contiguous). Tile 128x128, k-chunk 32, rows padded to 40 halves.
// 8 warps 2(m)x4(n), warp tile 64x32.
// ---------------------------------------------------------------------------
#define PR 40
#define STG_H (128 * PR)        // halves per matrix per stage
#define STG_B (STG_H * 2)       // bytes per matrix per stage
#define NSTG 3
#define GEMM_SMEM (2 * NSTG * STG_B)   // 61440 B

__device__ __forceinline__ void gemm_pipe_core(
    const __half* __restrict__ A, const __half* __restrict__ W,
    __half* smem, float acc[4][4][4])
{
    const int t    = threadIdx.x;
    const int lane = t & 31;
    const int warp = t >> 5;
    const int wm   = warp >> 2;
    const int wn   = warp & 3;

    const int m0 = blockIdx.x * 128;
    const int n0 = blockIdx.y * 128;

    const uint32_t asB = su(smem);
    const uint32_t wsB = asB + NSTG * STG_B;

    // cp.async mapping: 512 chunks of 16B per matrix per stage, 2 per thread
    const int row0 = t >> 2;
    const int c    = t & 3;
    const __half* a0 = A + (size_t)(m0 + row0) * DD + c * 8;
    const __half* a1 = a0 + (size_t)64 * DD;
    const __half* w0 = W + (size_t)(n0 + row0) * DD + c * 8;
    const __half* w1 = w0 + (size_t)64 * DD;
    const uint32_t d0 = row0 * (PR * 2) + c * 16;
    const uint32_t d1 = (row0 + 64) * (PR * 2) + c * 16;

    // ldmatrix addresses (stage 0 base)
    const int rowoff = (lane & 7) + ((lane >> 3) & 1) * 8;
    const int akoff  = ((lane >> 4) & 1) * 8;
    const int noff   = (lane & 7) + ((lane >> 4) & 1) * 8;
    const int bkoff  = ((lane >> 3) & 1) * 8;
    uint32_t aAddr[4], bAddr[2];
#pragma unroll
    for (int mi = 0; mi < 4; mi++)
        aAddr[mi] = asB + ((wm * 64 + mi * 16 + rowoff) * PR + akoff) * 2;
#pragma unroll
    for (int p = 0; p < 2; p++)
        bAddr[p] = wsB + ((wn * 32 + p * 16 + noff) * PR + bkoff) * 2;

    auto issue = [&](int s) {
        const int ko = s * 32;
        const uint32_t sb = (uint32_t)(s % NSTG) * STG_B;
        cpa16(asB + sb + d0, a0 + ko);
        cpa16(asB + sb + d1, a1 + ko);
        cpa16(wsB + sb + d0, w0 + ko);
        cpa16(wsB + sb + d1, w1 + ko);
        CP_COMMIT();
    };

    issue(0);
    issue(1);

    for (int it = 0; it < DD / 32; it++) {
        if (it < DD / 32 - 2) { asm volatile("cp.async.wait_group 1;"); }
        else                  { asm volatile("cp.async.wait_group 0;"); }
        __syncthreads();
        if (it + 2 < DD / 32) issue(it + 2);

        const uint32_t off = (uint32_t)(it % NSTG) * STG_B;
#pragma unroll
        for (int ks = 0; ks < 2; ks++) {
            uint32_t af[4][4];
#pragma unroll
            for (int mi = 0; mi < 4; mi++)
                ldm4(af[mi], aAddr[mi] + off + ks * 32);
            uint32_t bf[4][2];
#pragma unroll
            for (int p = 0; p < 2; p++) {
                uint32_t tmp[4];
                ldm4(tmp, bAddr[p] + off + ks * 32);
                bf[2 * p][0] = tmp[0]; bf[2 * p][1] = tmp[1];
                bf[2 * p + 1][0] = tmp[2]; bf[2 * p + 1][1] = tmp[3];
            }
#pragma unroll
            for (int mi = 0; mi < 4; mi++)
#pragma unroll
                for (int ni = 0; ni < 4; ni++)
                    mma16(acc[mi][ni], af[mi], bf[ni]);
        }
    }
}

// ---------------------------------------------------------------------------
// QKV projections (half in/out): Y = X @ W^T + b -> head-split [B,H,S,DK]
// ---------------------------------------------------------------------------
__global__ __launch_bounds__(256, 2) void qkv_proj_kernel(
    const float* __restrict__ bq, const float* __restrict__ bk,
    const float* __restrict__ bv)
{
    extern __shared__ __half smem[];

    const __half* A; const __half* W; const float* bias; __half* out;
    if (blockIdx.z == 0)      { A = g_qh; W = g_wqh; bias = bq; out = g_Q; }
    else if (blockIdx.z == 1) { A = g_kh; W = g_wkh; bias = bk; out = g_K; }
    else                      { A = g_vh; W = g_wvh; bias = bv; out = g_V; }

    float acc[4][4][4];
#pragma unroll
    for (int a = 0; a < 4; a++)
#pragma unroll
        for (int b = 0; b < 4; b++)
#pragma unroll
            for (int c = 0; c < 4; c++) acc[a][b][c] = 0.f;

    gemm_pipe_core(A, W, smem, acc);

    const int lane = threadIdx.x & 31;
    const int warp = threadIdx.x >> 5;
    const int wm = warp >> 2, wn = warp & 3;
    const int qq = lane & 3, l4 = lane >> 2;
    const int m0 = blockIdx.x * 128;
    const int n0 = blockIdx.y * 128;

#pragma unroll
    for (int mi = 0; mi < 4; mi++) {
#pragma unroll
        for (int rr = 0; rr < 2; rr++) {
            int m = m0 + wm * 64 + mi * 16 + l4 + rr * 8;
            int b = m >> 11;
            int s = m & 2047;
#pragma unroll
            for (int ni = 0; ni < 4; ni++) {
                int n  = n0 + wn * 32 + ni * 8 + 2 * qq;
                int h  = n >> 6;
                int dk = n & 63;
                __half2 hv = __floats2half2_rn(acc[mi][ni][rr * 2 + 0] + bias[n],
                                               acc[mi][ni][rr * 2 + 1] + bias[n + 1]);
                *(__half2*)&out[((size_t)(b * HH + h) * SS + s) * DKK + dk] = hv;
            }
        }
    }
}

// ---------------------------------------------------------------------------
// Output projection: out(f32) = g_ATT(half) @ Wo^T + bo
// ---------------------------------------------------------------------------
__global__ __launch_bounds__(256, 2) void out_proj_kernel(
    const float* __restrict__ bo, float* __restrict__ out)
{
    extern __shared__ __half smem[];

    float acc[4][4][4];
#pragma unroll
    for (int a = 0; a < 4; a++)
#pragma unroll
        for (int b = 0; b < 4; b++)
#pragma unroll
            for (int c = 0; c < 4; c++) acc[a][b][c] = 0.f;

    gemm_pipe_core(g_ATT, g_woh, smem, acc);

    const int lane = threadIdx.x & 31;
    const int warp = threadIdx.x >> 5;
    const int wm = warp >> 2, wn = warp & 3;
    const int qq = lane & 3, l4 = lane >> 2;
    const int m0 = blockIdx.x * 128;
    const int n0 = blockIdx.y * 128;

#pragma unroll
    for (int mi = 0; mi < 4; mi++) {
#pragma unroll
        for (int rr = 0; rr < 2; rr++) {
            int m = m0 + wm * 64 + mi * 16 + l4 + rr * 8;
#pragma unroll
            for (int ni = 0; ni < 4; ni++) {
                int n = n0 + wn * 32 + ni * 8 + 2 * qq;
                float2 rv;
                rv.x = acc[mi][ni][rr * 2 + 0] + bo[n];
                rv.y = acc[mi][ni][rr * 2 + 1] + bo[n + 1];
                *(float2*)&out[(size_t)m * DD + n] = rv;
            }
        }
    }
}

// ---------------------------------------------------------------------------
// Flash attention (causal), FP16 mma + ldmatrix + cp.async double-buffered K/V.
// (unchanged from round 4 — measured fast)
// ---------------------------------------------------------------------------
#define AR 72
#define Q_HALVES (128 * AR)
#define KV_HALVES (64 * AR)
#define ATTN_SMEM ((Q_HALVES + 4 * KV_HALVES) * 2)

__global__ __launch_bounds__(256) void attn_kernel()
{
    extern __shared__ __half sm[];
    __half* Qs = sm;
    __half* Ks0 = Qs + Q_HALVES;
    __half* Vs0 = Ks0 + KV_HALVES;
    __half* Ks1 = Vs0 + KV_HALVES;
    __half* Vs1 = Ks1 + KV_HALVES;

    const int t    = threadIdx.x;
    const int lane = t & 31;
    const int w    = t >> 5;
    const int qq   = lane & 3;
    const int l4   = lane >> 2;

    const int bx = blockIdx.x;
    const int h  = blockIdx.y;
    const int b  = blockIdx.z;

    const __half* Qbase = g_Q + ((size_t)(b * HH + h) * SS) * DKK;
    const __half* Kbase = g_K + ((size_t)(b * HH + h) * SS) * DKK;
    const __half* Vbase = g_V + ((size_t)(b * HH + h) * SS) * DKK;

    const uint32_t ksB[2] = { su(Ks0), su(Ks1) };
    const uint32_t vsB[2] = { su(Vs0), su(Vs1) };

    const int qr = t >> 3;
    const int qc = (t & 7) * 16;
    const int kr = t >> 3;
    const int kc = (t & 7) * 16;

    {
        uint32_t qdst = su(Qs);
#pragma unroll
        for (int i = 0; i < 4; i++) {
            int r = qr + 32 * i;
            cpa16(qdst + r * (AR * 2) + qc, (const char*)(Qbase + (size_t)(bx * 128 + r) * DKK) + qc);
        }
    }
    CP_COMMIT();

    {
#pragma unroll
        for (int i = 0; i < 2; i++) {
            int r = kr + 32 * i;
            cpa16(ksB[0] + r * (AR * 2) + kc, (const char*)(Kbase + (size_t)r * DKK) + kc);
            cpa16(vsB[0] + r * (AR * 2) + kc, (const char*)(Vbase + (size_t)r * DKK) + kc);
        }
    }
    CP_COMMIT();

    asm volatile("cp.async.wait_group 1;");
    __syncthreads();

    const int rowoff = (lane & 7) + ((lane >> 3) & 1) * 8;
    const int akoff  = ((lane >> 4) & 1) * 8;
    const int noff   = (lane & 7) + ((lane >> 4) & 1) * 8;
    const int bkoff  = ((lane >> 3) & 1) * 8;
    const int vkoff  = ((lane >> 4) & 1) * 8;

    uint32_t aq[4][4];
#pragma unroll
    for (int g = 0; g < 4; g++)
        ldm4(aq[g], su(&Qs[(16 * w + rowoff) * AR + g * 16 + akoff]));

    const int rl = 16 * w + l4;
    const int row_lo = bx * 128 + rl;
    const int row_hi = row_lo + 8;

    float m_lo = -1e30f, m_hi = -1e30f, l_lo = 0.f, l_hi = 0.f;
    float Oacc[8][4];
#pragma unroll
    for (int j = 0; j < 8; j++)
#pragma unroll
        for (int c = 0; c < 4; c++) Oacc[j][c] = 0.f;

    const int kt_max = 2 * bx + 1;
    for (int kt = 0; kt <= kt_max; kt++) {
        const int st = kt & 1;

        if (kt + 1 <= kt_max) {
            const __half* Kt = Kbase + (size_t)(kt + 1) * 64 * DKK;
            const __half* Vt = Vbase + (size_t)(kt + 1) * 64 * DKK;
            const int ns = st ^ 1;
#pragma unroll
            for (int i = 0; i < 2; i++) {
                int r = kr + 32 * i;
                cpa16(ksB[ns] + r * (AR * 2) + kc, (const char*)(Kt + (size_t)r * DKK) + kc);
                cpa16(vsB[ns] + r * (AR * 2) + kc, (const char*)(Vt + (size_t)r * DKK) + kc);
            }
            CP_COMMIT();
            asm volatile("cp.async.wait_group 1;");
        } else {
            asm volatile("cp.async.wait_group 0;");
        }
        __syncthreads();

        float Sacc[8][4];
#pragma unroll
        for (int j = 0; j < 8; j++)
#pragma unroll
            for (int c = 0; c < 4; c++) Sacc[j][c] = 0.f;

#pragma unroll
        for (int g = 0; g < 4; g++) {
#pragma unroll
            for (int p = 0; p < 4; p++) {
                uint32_t tmp[4];
                ldm4(tmp, ksB[st] + ((p * 16 + noff) * AR + g * 16 + bkoff) * 2);
                mma16(Sacc[2 * p],     aq[g], tmp);
                mma16(Sacc[2 * p + 1], aq[g], tmp + 2);
            }
        }

#pragma unroll
        for (int j = 0; j < 8; j++)
#pragma unroll
            for (int c = 0; c < 4; c++) Sacc[j][c] *= 0.125f;

        if (kt >= 2 * bx) {
#pragma unroll
            for (int j = 0; j < 8; j++) {
                int col = kt * 64 + 8 * j + 2 * qq;
                if (col     > row_lo) Sacc[j][0] = -1e30f;
                if (col + 1 > row_lo) Sacc[j][1] = -1e30f;
                if (col     > row_hi) Sacc[j][2] = -1e30f;
                if (col + 1 > row_hi) Sacc[j][3] = -1e30f;
            }
        }

        float mt_lo = -1e30f, mt_hi = -1e30f;
#pragma unroll
        for (int j = 0; j < 8; j++) {
            mt_lo = fmaxf(mt_lo, fmaxf(Sacc[j][0], Sacc[j][1]));
            mt_hi = fmaxf(mt_hi, fmaxf(Sacc[j][2], Sacc[j][3]));
        }
        mt_lo = fmaxf(mt_lo, __shfl_xor_sync(0xffffffffu, mt_lo, 1));
        mt_lo = fmaxf(mt_lo, __shfl_xor_sync(0xffffffffu, mt_lo, 2));
        mt_hi = fmaxf(mt_hi, __shfl_xor_sync(0xffffffffu, mt_hi, 1));
        mt_hi = fmaxf(mt_hi, __shfl_xor_sync(0xffffffffu, mt_hi, 2));

        float mn_lo = fmaxf(m_lo, mt_lo);
        float mn_hi = fmaxf(m_hi, mt_hi);
        float al_lo = __expf(m_lo - mn_lo);
        float al_hi = __expf(m_hi - mn_hi);

        float ls_lo = 0.f, ls_hi = 0.f;
#pragma unroll
        for (int j = 0; j < 8; j++) {
            Sacc[j][0] = __expf(Sacc[j][0] - mn_lo);
            Sacc[j][1] = __expf(Sacc[j][1] - mn_lo);
            Sacc[j][2] = __expf(Sacc[j][2] - mn_hi);
            Sacc[j][3] = __expf(Sacc[j][3] - mn_hi);
            ls_lo += Sacc[j][0] + Sacc[j][1];
            ls_hi += Sacc[j][2] + Sacc[j][3];
        }
        ls_lo += __shfl_xor_sync(0xffffffffu, ls_lo, 1);
        ls_lo += __shfl_xor_sync(0xffffffffu, ls_lo, 2);
        ls_hi += __shfl_xor_sync(0xffffffffu, ls_hi, 1);
        ls_hi += __shfl_xor_sync(0xffffffffu, ls_hi, 2);

        l_lo = l_lo * al_lo + ls_lo;
        l_hi = l_hi * al_hi + ls_hi;
        m_lo = mn_lo;
        m_hi = mn_hi;

        uint32_t ap[4][4];
#pragma unroll
        for (int g = 0; g < 4; g++) {
            ap[g][0] = packh2(Sacc[2 * g][0],     Sacc[2 * g][1]);
            ap[g][1] = packh2(Sacc[2 * g][2],     Sacc[2 * g][3]);
            ap[g][2] = packh2(Sacc[2 * g + 1][0], Sacc[2 * g + 1][1]);
            ap[g][3] = packh2(Sacc[2 * g + 1][2], Sacc[2 * g + 1][3]);
        }

#pragma unroll
        for (int j = 0; j < 8; j++) {
            Oacc[j][0] *= al_lo;
            Oacc[j][1] *= al_lo;
            Oacc[j][2] *= al_hi;
            Oacc[j][3] *= al_hi;
        }

#pragma unroll
        for (int g = 0; g < 4; g++) {
#pragma unroll
            for (int p = 0; p < 4; p++) {
                uint32_t tmp[4];
                ldm4t(tmp, vsB[st] + ((g * 16 + rowoff) * AR + p * 16 + vkoff) * 2);
                mma16(Oacc[2 * p],     ap[g], tmp);
                mma16(Oacc[2 * p + 1], ap[g], tmp + 2);
            }
        }

        __syncthreads();
    }

    float il_lo = 1.f / l_lo;
    float il_hi = 1.f / l_hi;
    __half* out_lo = g_ATT + ((size_t)(b * SS + row_lo)) * DD + h * DKK;
    __half* out_hi = g_ATT + ((size_t)(b * SS + row_hi)) * DD + h * DKK;
#pragma unroll
    for (int j = 0; j < 8; j++) {
        int dk = 8 * j + 2 * qq;
        *(__half2*)&out_lo[dk] = __floats2half2_rn(Oacc[j][0] * il_lo, Oacc[j][1] * il_lo);
        *(__half2*)&out_hi[dk] = __floats2half2_rn(Oacc[j][2] * il_hi, Oacc[j][3] * il_hi);
    }
}

// ---------------------------------------------------------------------------
// Entry point. Inputs: q,k,v,mask,w_q,b_q,w_k,b_k,w_v,b_v,w_o,b_o
// ---------------------------------------------------------------------------
extern "C" void kernel_launch(void* const* d_in, const int* in_sizes, int n_in,
                              void* d_out, int out_size)
{
    const float* q  = (const float*)d_in[0];
    const float* k  = (const float*)d_in[1];
    const float* v  = (const float*)d_in[2];
    const float* wq = (const float*)d_in[4];
    const float* bq = (const float*)d_in[5];
    const float* wk = (const float*)d_in[6];
    const float* bk = (const float*)d_in[7];
    const float* wv = (const float*)d_in[8];
    const float* bv = (const float*)d_in[9];
    const float* wo = (const float*)d_in[10];
    const float* bo = (const float*)d_in[11];
    float* out = (float*)d_out;

    // Resolve device-global addresses (host side)
    __half *p_qh, *p_kh, *p_vh, *p_wqh, *p_wkh, *p_wvh, *p_woh;
    cudaGetSymbolAddress((void**)&p_qh,  g_qh);
    cudaGetSymbolAddress((void**)&p_kh,  g_kh);
    cudaGetSymbolAddress((void**)&p_vh,  g_vh);
    cudaGetSymbolAddress((void**)&p_wqh, g_wqh);
    cudaGetSymbolAddress((void**)&p_wkh, g_wkh);
    cudaGetSymbolAddress((void**)&p_wvh, g_wvh);
    cudaGetSymbolAddress((void**)&p_woh, g_woh);

    // f32 -> f16 conversions
    const int nAct4 = MTOT * DD / 4;   // 2,097,152
    const int nW4   = DD * DD / 4;     // 262,144
    f2h_kernel<<<(nAct4 + 255) / 256, 256>>>((const float4*)q, (uint2*)p_qh, nAct4);
    f2h_kernel<<<(nAct4 + 255) / 256, 256>>>((const float4*)k, (uint2*)p_kh, nAct4);
    f2h_kernel<<<(nAct4 + 255) / 256, 256>>>((const float4*)v, (uint2*)p_vh, nAct4);
    f2h_kernel<<<(nW4 + 255) / 256, 256>>>((const float4*)wq, (uint2*)p_wqh, nW4);
    f2h_kernel<<<(nW4 + 255) / 256, 256>>>((const float4*)wk, (uint2*)p_wkh, nW4);
    f2h_kernel<<<(nW4 + 255) / 256, 256>>>((const float4*)wv, (uint2*)p_wvh, nW4);
    f2h_kernel<<<(nW4 + 255) / 256, 256>>>((const float4*)wo, (uint2*)p_woh, nW4);

    // QKV projections
    cudaFuncSetAttribute(qkv_proj_kernel, cudaFuncAttributeMaxDynamicSharedMemorySize, GEMM_SMEM);
    dim3 gproj(MTOT / 128, DD / 128, 3);
    qkv_proj_kernel<<<gproj, 256, GEMM_SMEM>>>(bq, bk, bv);

    // Flash attention
    cudaFuncSetAttribute(attn_kernel, cudaFuncAttributeMaxDynamicSharedMemorySize, ATTN_SMEM);
    dim3 gattn(SS / 128, HH, BB);
    attn_kernel<<<gattn, 256, ATTN_SMEM>>>();

    // Output projection
    cudaFuncSetAttribute(out_proj_kernel, cudaFuncAttributeMaxDynamicSharedMemorySize, GEMM_SMEM);
    dim3 gout(MTOT / 128, DD / 128, 1);
    out_proj_kernel<<<gout, 256, GEMM_SMEM>>>(bo, out);
}

// round 7
// speedup vs baseline: 10.1365x; 1.0016x over previous
#include <cuda_runtime.h>
#include <cuda_fp16.h>
#include <math.h>
#include <stdint.h>

// Problem constants
#define BB 4
#define SS 2048
#define DD 1024
#define HH 16
#define DKK 64
#define MTOT (BB * SS)   // 8192

// Scratch device globals
__device__ __half g_Q[BB * HH * SS * DKK];    // [B,H,S,DK]
__device__ __half g_K[BB * HH * SS * DKK];
__device__ __half g_V[BB * HH * SS * DKK];
__device__ __half g_ATT[(size_t)MTOT * DD];   // [B,S,D]
__device__ __half g_qh[(size_t)MTOT * DD];
__device__ __half g_kh[(size_t)MTOT * DD];
__device__ __half g_vh[(size_t)MTOT * DD];
__device__ __half g_wqh[DD * DD];
__device__ __half g_wkh[DD * DD];
__device__ __half g_wvh[DD * DD];
__device__ __half g_woh[DD * DD];

// ---------------------------------------------------------------------------
// Helpers
// ---------------------------------------------------------------------------
__device__ __forceinline__ uint32_t su(const void* p) {
    return (uint32_t)__cvta_generic_to_shared(p);
}
__device__ __forceinline__ void ldm4(uint32_t* r, uint32_t a) {
    asm volatile("ldmatrix.sync.aligned.m8n8.x4.shared.b16 {%0,%1,%2,%3},[%4];"
        : "=r"(r[0]), "=r"(r[1]), "=r"(r[2]), "=r"(r[3]) : "r"(a));
}
__device__ __forceinline__ void ldm4t(uint32_t* r, uint32_t a) {
    asm volatile("ldmatrix.sync.aligned.m8n8.x4.trans.shared.b16 {%0,%1,%2,%3},[%4];"
        : "=r"(r[0]), "=r"(r[1]), "=r"(r[2]), "=r"(r[3]) : "r"(a));
}
__device__ __forceinline__ void mma16(float* d, const uint32_t* a, const uint32_t* b) {
    asm volatile(
        "mma.sync.aligned.m16n8k16.row.col.f32.f16.f16.f32 "
        "{%0,%1,%2,%3},{%4,%5,%6,%7},{%8,%9},{%0,%1,%2,%3};"
        : "+f"(d[0]), "+f"(d[1]), "+f"(d[2]), "+f"(d[3])
        : "r"(a[0]), "r"(a[1]), "r"(a[2]), "r"(a[3]), "r"(b[0]), "r"(b[1]));
}
__device__ __forceinline__ uint32_t packh2(float x, float y) {
    __half2 h = __floats2half2_rn(x, y);
    return *(uint32_t*)&h;
}
__device__ __forceinline__ void cpa16(uint32_t d, const void* s) {
    asm volatile("cp.async.cg.shared.global [%0],[%1],16;" :: "r"(d), "l"(s));
}
#define CP_COMMIT() asm volatile("cp.async.commit_group;")

// ---------------------------------------------------------------------------
// Merged f32 -> f16 convert for all 7 arrays (one launch)
// ---------------------------------------------------------------------------
#define NACT4 (MTOT * DD / 4)   // 2,097,152 float4 per activation
#define NW4   (DD * DD / 4)     //   262,144 float4 per weight
#define NCONV_TOT (3 * NACT4 + 4 * NW4)

__global__ __launch_bounds__(256) void f2h_all_kernel(
    const float4* __restrict__ q, const float4* __restrict__ k,
    const float4* __restrict__ v,
    const float4* __restrict__ wq, const float4* __restrict__ wk,
    const float4* __restrict__ wv, const float4* __restrict__ wo)
{
    int i = blockIdx.x * 256 + threadIdx.x;
    if (i >= NCONV_TOT) return;
    const float4* src;
    uint2* dst;
    int off;
    if (i < 3 * NACT4) {
        int w = i / NACT4;
        off = i - w * NACT4;
        src = (w == 0) ? q : (w == 1) ? k : v;
        dst = (uint2*)((w == 0) ? g_qh : (w == 1) ? g_kh : g_vh);
    } else {
        int j = i - 3 * NACT4;
        int w = j / NW4;
        off = j - w * NW4;
        src = (w == 0) ? wq : (w == 1) ? wk : (w == 2) ? wv : wo;
        dst = (uint2*)((w == 0) ? g_wqh : (w == 1) ? g_wkh : (w == 2) ? g_wvh : g_woh);
    }
    float4 val = src[off];
    dst[off] = make_uint2(packh2(val.x, val.y), packh2(val.z, val.w));
}

// ---------------------------------------------------------------------------
// 4-stage cp.async pipelined FP16 GEMM core: C = A @ W^T (both [*,1024] half,
// k-contiguous). Tile 128x128, k-chunk 32, rows padded to 40 halves.
// 8 warps 2(m)x4(n), warp tile 64x32. 3 chunks in flight.
// ---------------------------------------------------------------------------
#define PR 40
#define STG_H (128 * PR)        // halves per matrix per stage
#define STG_B (STG_H * 2)       // bytes per matrix per stage
#define NSTG 4
#define GEMM_SMEM (2 * NSTG * STG_B)   // 81920 B

__device__ __forceinline__ void gemm_pipe_core(
    const __half* __restrict__ A, const __half* __restrict__ W,
    __half* smem, float acc[4][4][4])
{
    const int t    = threadIdx.x;
    const int lane = t & 31;
    const int warp = t >> 5;
    const int wm   = warp >> 2;
    const int wn   = warp & 3;

    const int m0 = blockIdx.x * 128;
    const int n0 = blockIdx.y * 128;

    const uint32_t asB = su(smem);
    const uint32_t wsB = asB + NSTG * STG_B;

    // cp.async mapping: 512 chunks of 16B per matrix per stage, 2 per thread
    const int row0 = t >> 2;
    const int c    = t & 3;
    const __half* a0 = A + (size_t)(m0 + row0) * DD + c * 8;
    const __half* a1 = a0 + (size_t)64 * DD;
    const __half* w0 = W + (size_t)(n0 + row0) * DD + c * 8;
    const __half* w1 = w0 + (size_t)64 * DD;
    const uint32_t d0 = row0 * (PR * 2) + c * 16;
    const uint32_t d1 = (row0 + 64) * (PR * 2) + c * 16;

    // ldmatrix addresses (stage 0 base)
    const int rowoff = (lane & 7) + ((lane >> 3) & 1) * 8;
    const int akoff  = ((lane >> 4) & 1) * 8;
    const int noff   = (lane & 7) + ((lane >> 4) & 1) * 8;
    const int bkoff  = ((lane >> 3) & 1) * 8;
    uint32_t aAddr[4], bAddr[2];
#pragma unroll
    for (int mi = 0; mi < 4; mi++)
        aAddr[mi] = asB + ((wm * 64 + mi * 16 + rowoff) * PR + akoff) * 2;
#pragma unroll
    for (int p = 0; p < 2; p++)
        bAddr[p] = wsB + ((wn * 32 + p * 16 + noff) * PR + bkoff) * 2;

    auto issue = [&](int s) {
        const int ko = s * 32;
        const uint32_t sb = (uint32_t)(s % NSTG) * STG_B;
        cpa16(asB + sb + d0, a0 + ko);
        cpa16(asB + sb + d1, a1 + ko);
        cpa16(wsB + sb + d0, w0 + ko);
        cpa16(wsB + sb + d1, w1 + ko);
        CP_COMMIT();
    };

    issue(0);
    issue(1);
    issue(2);

    const int NIT = DD / 32;   // 32
    for (int it = 0; it < NIT; it++) {
        // allowed pending groups = min(NIT, it+3) - it - 1
        if (it <= NIT - 4)      { asm volatile("cp.async.wait_group 2;"); }
        else if (it == NIT - 3) { asm volatile("cp.async.wait_group 2;"); }
        else if (it == NIT - 2) { asm volatile("cp.async.wait_group 1;"); }
        else                    { asm volatile("cp.async.wait_group 0;"); }
        __syncthreads();
        if (it + 3 < NIT) issue(it + 3);

        const uint32_t off = (uint32_t)(it % NSTG) * STG_B;
#pragma unroll
        for (int ks = 0; ks < 2; ks++) {
            uint32_t af[4][4];
#pragma unroll
            for (int mi = 0; mi < 4; mi++)
                ldm4(af[mi], aAddr[mi] + off + ks * 32);
            uint32_t bf[4][2];
#pragma unroll
            for (int p = 0; p < 2; p++) {
                uint32_t tmp[4];
                ldm4(tmp, bAddr[p] + off + ks * 32);
                bf[2 * p][0] = tmp[0]; bf[2 * p][1] = tmp[1];
                bf[2 * p + 1][0] = tmp[2]; bf[2 * p + 1][1] = tmp[3];
            }
#pragma unroll
            for (int mi = 0; mi < 4; mi++)
#pragma unroll
                for (int ni = 0; ni < 4; ni++)
                    mma16(acc[mi][ni], af[mi], bf[ni]);
        }
    }
}

// ---------------------------------------------------------------------------
// QKV projections (half in/out): Y = X @ W^T + b -> head-split [B,H,S,DK]
// ---------------------------------------------------------------------------
__global__ __launch_bounds__(256, 2) void qkv_proj_kernel(
    const float* __restrict__ bq, const float* __restrict__ bk,
    const float* __restrict__ bv)
{
    extern __shared__ __half smem[];

    const __half* A; const __half* W; const float* bias; __half* out;
    if (blockIdx.z == 0)      { A = g_qh; W = g_wqh; bias = bq; out = g_Q; }
    else if (blockIdx.z == 1) { A = g_kh; W = g_wkh; bias = bk; out = g_K; }
    else                      { A = g_vh; W = g_wvh; bias = bv; out = g_V; }

    float acc[4][4][4];
#pragma unroll
    for (int a = 0; a < 4; a++)
#pragma unroll
        for (int b = 0; b < 4; b++)
#pragma unroll
            for (int c = 0; c < 4; c++) acc[a][b][c] = 0.f;

    gemm_pipe_core(A, W, smem, acc);

    const int lane = threadIdx.x & 31;
    const int warp = threadIdx.x >> 5;
    const int wm = warp >> 2, wn = warp & 3;
    const int qq = lane & 3, l4 = lane >> 2;
    const int m0 = blockIdx.x * 128;
    const int n0 = blockIdx.y * 128;

#pragma unroll
    for (int mi = 0; mi < 4; mi++) {
#pragma unroll
        for (int rr = 0; rr < 2; rr++) {
            int m = m0 + wm * 64 + mi * 16 + l4 + rr * 8;
            int b = m >> 11;
            int s = m & 2047;
#pragma unroll
            for (int ni = 0; ni < 4; ni++) {
                int n  = n0 + wn * 32 + ni * 8 + 2 * qq;
                int h  = n >> 6;
                int dk = n & 63;
                __half2 hv = __floats2half2_rn(acc[mi][ni][rr * 2 + 0] + bias[n],
                                               acc[mi][ni][rr * 2 + 1] + bias[n + 1]);
                *(__half2*)&out[((size_t)(b * HH + h) * SS + s) * DKK + dk] = hv;
            }
        }
    }
}

// ---------------------------------------------------------------------------
// Output projection: out(f32) = g_ATT(half) @ Wo^T + bo
// ---------------------------------------------------------------------------
__global__ __launch_bounds__(256, 2) void out_proj_kernel(
    const float* __restrict__ bo, float* __restrict__ out)
{
    extern __shared__ __half smem[];

    float acc[4][4][4];
#pragma unroll
    for (int a = 0; a < 4; a++)
#pragma unroll
        for (int b = 0; b < 4; b++)
#pragma unroll
            for (int c = 0; c < 4; c++) acc[a][b][c] = 0.f;

    gemm_pipe_core(g_ATT, g_woh, smem, acc);

    const int lane = threadIdx.x & 31;
    const int warp = threadIdx.x >> 5;
    const int wm = warp >> 2, wn = warp & 3;
    const int qq = lane & 3, l4 = lane >> 2;
    const int m0 = blockIdx.x * 128;
    const int n0 = blockIdx.y * 128;

#pragma unroll
    for (int mi = 0; mi < 4; mi++) {
#pragma unroll
        for (int rr = 0; rr < 2; rr++) {
            int m = m0 + wm * 64 + mi * 16 + l4 + rr * 8;
#pragma unroll
            for (int ni = 0; ni < 4; ni++) {
                int n = n0 + wn * 32 + ni * 8 + 2 * qq;
                float2 rv;
                rv.x = acc[mi][ni][rr * 2 + 0] + bo[n];
                rv.y = acc[mi][ni][rr * 2 + 1] + bo[n + 1];
                *(float2*)&out[(size_t)m * DD + n] = rv;
            }
        }
    }
}

// ---------------------------------------------------------------------------
// Flash attention (causal), FP16 mma + ldmatrix + cp.async double-buffered K/V.
// New: warps whose 16 rows are entirely masked in the last diagonal tile skip
// all compute for that tile (exactly equivalent: exp of full mask = 0, alpha=1).
// ---------------------------------------------------------------------------
#define AR 72
#define Q_HALVES (128 * AR)
#define KV_HALVES (64 * AR)
#define ATTN_SMEM ((Q_HALVES + 4 * KV_HALVES) * 2)

__global__ __launch_bounds__(256) void attn_kernel()
{
    extern __shared__ __half sm[];
    __half* Qs = sm;
    __half* Ks0 = Qs + Q_HALVES;
    __half* Vs0 = Ks0 + KV_HALVES;
    __half* Ks1 = Vs0 + KV_HALVES;
    __half* Vs1 = Ks1 + KV_HALVES;

    const int t    = threadIdx.x;
    const int lane = t & 31;
    const int w    = t >> 5;
    const int qq   = lane & 3;
    const int l4   = lane >> 2;

    const int bx = blockIdx.x;
    const int h  = blockIdx.y;
    const int b  = blockIdx.z;

    const __half* Qbase = g_Q + ((size_t)(b * HH + h) * SS) * DKK;
    const __half* Kbase = g_K + ((size_t)(b * HH + h) * SS) * DKK;
    const __half* Vbase = g_V + ((size_t)(b * HH + h) * SS) * DKK;

    const uint32_t ksB[2] = { su(Ks0), su(Ks1) };
    const uint32_t vsB[2] = { su(Vs0), su(Vs1) };

    const int qr = t >> 3;
    const int qc = (t & 7) * 16;
    const int kr = t >> 3;
    const int kc = (t & 7) * 16;

    {
        uint32_t qdst = su(Qs);
#pragma unroll
        for (int i = 0; i < 4; i++) {
            int r = qr + 32 * i;
            cpa16(qdst + r * (AR * 2) + qc, (const char*)(Qbase + (size_t)(bx * 128 + r) * DKK) + qc);
        }
    }
    CP_COMMIT();

    {
#pragma unroll
        for (int i = 0; i < 2; i++) {
            int r = kr + 32 * i;
            cpa16(ksB[0] + r * (AR * 2) + kc, (const char*)(Kbase + (size_t)r * DKK) + kc);
            cpa16(vsB[0] + r * (AR * 2) + kc, (const char*)(Vbase + (size_t)r * DKK) + kc);
        }
    }
    CP_COMMIT();

    asm volatile("cp.async.wait_group 1;");
    __syncthreads();

    const int rowoff = (lane & 7) + ((lane >> 3) & 1) * 8;
    const int akoff  = ((lane >> 4) & 1) * 8;
    const int noff   = (lane & 7) + ((lane >> 4) & 1) * 8;
    const int bkoff  = ((lane >> 3) & 1) * 8;
    const int vkoff  = ((lane >> 4) & 1) * 8;

    uint32_t aq[4][4];
#pragma unroll
    for (int g = 0; g < 4; g++)
        ldm4(aq[g], su(&Qs[(16 * w + rowoff) * AR + g * 16 + akoff]));

    const int rl = 16 * w + l4;
    const int row_lo = bx * 128 + rl;
    const int row_hi = row_lo + 8;

    float m_lo = -1e30f, m_hi = -1e30f, l_lo = 0.f, l_hi = 0.f;
    float Oacc[8][4];
#pragma unroll
    for (int j = 0; j < 8; j++)
#pragma unroll
        for (int c = 0; c < 4; c++) Oacc[j][c] = 0.f;

    const int kt_max = 2 * bx + 1;
    for (int kt = 0; kt <= kt_max; kt++) {
        const int st = kt & 1;

        if (kt + 1 <= kt_max) {
            const __half* Kt = Kbase + (size_t)(kt + 1) * 64 * DKK;
            const __half* Vt = Vbase + (size_t)(kt + 1) * 64 * DKK;
            const int ns = st ^ 1;
#pragma unroll
            for (int i = 0; i < 2; i++) {
                int r = kr + 32 * i;
                cpa16(ksB[ns] + r * (AR * 2) + kc, (const char*)(Kt + (size_t)r * DKK) + kc);
                cpa16(vsB[ns] + r * (AR * 2) + kc, (const char*)(Vt + (size_t)r * DKK) + kc);
            }
            CP_COMMIT();
            asm volatile("cp.async.wait_group 1;");
        } else {
            asm volatile("cp.async.wait_group 0;");
        }
        __syncthreads();

        // Causal full-skip: last diagonal tile columns start at (2bx+1)*64 =
        // bx*128+64 > all rows of warps 0..3 (max bx*128+63). Contribution is
        // exactly zero (all-masked -> exp=0, alpha=1), so skip compute.
        const bool full_skip = (kt == kt_max) && (w < 4);
        if (!full_skip) {

        float Sacc[8][4];
#pragma unroll
        for (int j = 0; j < 8; j++)
#pragma unroll
            for (int c = 0; c < 4; c++) Sacc[j][c] = 0.f;

#pragma unroll
        for (int g = 0; g < 4; g++) {
#pragma unroll
            for (int p = 0; p < 4; p++) {
                uint32_t tmp[4];
                ldm4(tmp, ksB[st] + ((p * 16 + noff) * AR + g * 16 + bkoff) * 2);
                mma16(Sacc[2 * p],     aq[g], tmp);
                mma16(Sacc[2 * p + 1], aq[g], tmp + 2);
            }
        }

#pragma unroll
        for (int j = 0; j < 8; j++)
#pragma unroll
            for (int c = 0; c < 4; c++) Sacc[j][c] *= 0.125f;

        if (kt >= 2 * bx) {
#pragma unroll
            for (int j = 0; j < 8; j++) {
                int col = kt * 64 + 8 * j + 2 * qq;
                if (col     > row_lo) Sacc[j][0] = -1e30f;
                if (col + 1 > row_lo) Sacc[j][1] = -1e30f;
                if (col     > row_hi) Sacc[j][2] = -1e30f;
                if (col + 1 > row_hi) Sacc[j][3] = -1e30f;
            }
        }

        float mt_lo = -1e30f, mt_hi = -1e30f;
#pragma unroll
        for (int j = 0; j < 8; j++) {
            mt_lo = fmaxf(mt_lo, fmaxf(Sacc[j][0], Sacc[j][1]));
            mt_hi = fmaxf(mt_hi, fmaxf(Sacc[j][2], Sacc[j][3]));
        }
        mt_lo = fmaxf(mt_lo, __shfl_xor_sync(0xffffffffu, mt_lo, 1));
        mt_lo = fmaxf(mt_lo, __shfl_xor_sync(0xffffffffu, mt_lo, 2));
        mt_hi = fmaxf(mt_hi, __shfl_xor_sync(0xffffffffu, mt_hi, 1));
        mt_hi = fmaxf(mt_hi, __shfl_xor_sync(0xffffffffu, mt_hi, 2));

        float mn_lo = fmaxf(m_lo, mt_lo);
        float mn_hi = fmaxf(m_hi, mt_hi);
        float al_lo = __expf(m_lo - mn_lo);
        float al_hi = __expf(m_hi - mn_hi);

        float ls_lo = 0.f, ls_hi = 0.f;
#pragma unroll
        for (int j = 0; j < 8; j++) {
            Sacc[j][0] = __expf(Sacc[j][0] - mn_lo);
            Sacc[j][1] = __expf(Sacc[j][1] - mn_lo);
            Sacc[j][2] = __expf(Sacc[j][2] - mn_hi);
            Sacc[j][3] = __expf(Sacc[j][3] - mn_hi);
            ls_lo += Sacc[j][0] + Sacc[j][1];
            ls_hi += Sacc[j][2] + Sacc[j][3];
        }
        ls_lo += __shfl_xor_sync(0xffffffffu, ls_lo, 1);
        ls_lo += __shfl_xor_sync(0xffffffffu, ls_lo, 2);
        ls_hi += __shfl_xor_sync(0xffffffffu, ls_hi, 1);
        ls_hi += __shfl_xor_sync(0xffffffffu, ls_hi, 2);

        l_lo = l_lo * al_lo + ls_lo;
        l_hi = l_hi * al_hi + ls_hi;
        m_lo = mn_lo;
        m_hi = mn_hi;

        uint32_t ap[4][4];
#pragma unroll
        for (int g = 0; g < 4; g++) {
            ap[g][0] = packh2(Sacc[2 * g][0],     Sacc[2 * g][1]);
            ap[g][1] = packh2(Sacc[2 * g][2],     Sacc[2 * g][3]);
            ap[g][2] = packh2(Sacc[2 * g + 1][0], Sacc[2 * g + 1][1]);
            ap[g][3] = packh2(Sacc[2 * g + 1][2], Sacc[2 * g + 1][3]);
        }

#pragma unroll
        for (int j = 0; j < 8; j++) {
            Oacc[j][0] *= al_lo;
            Oacc[j][1] *= al_lo;
            Oacc[j][2] *= al_hi;
            Oacc[j][3] *= al_hi;
        }

#pragma unroll
        for (int g = 0; g < 4; g++) {
#pragma unroll
            for (int p = 0; p < 4; p++) {
                uint32_t tmp[4];
                ldm4t(tmp, vsB[st] + ((g * 16 + rowoff) * AR + p * 16 + vkoff) * 2);
                mma16(Oacc[2 * p],     ap[g], tmp);
                mma16(Oacc[2 * p + 1], ap[g], tmp + 2);
            }
        }

        }  // !full_skip

        __syncthreads();
    }

    float il_lo = 1.f / l_lo;
    float il_hi = 1.f / l_hi;
    __half* out_lo = g_ATT + ((size_t)(b * SS + row_lo)) * DD + h * DKK;
    __half* out_hi = g_ATT + ((size_t)(b * SS + row_hi)) * DD + h * DKK;
#pragma unroll
    for (int j = 0; j < 8; j++) {
        int dk = 8 * j + 2 * qq;
        *(__half2*)&out_lo[dk] = __floats2half2_rn(Oacc[j][0] * il_lo, Oacc[j][1] * il_lo);
        *(__half2*)&out_hi[dk] = __floats2half2_rn(Oacc[j][2] * il_hi, Oacc[j][3] * il_hi);
    }
}

// ---------------------------------------------------------------------------
// Entry point. Inputs: q,k,v,mask,w_q,b_q,w_k,b_k,w_v,b_v,w_o,b_o
// ---------------------------------------------------------------------------
extern "C" void kernel_launch(void* const* d_in, const int* in_sizes, int n_in,
                              void* d_out, int out_size)
{
    const float* q  = (const float*)d_in[0];
    const float* k  = (const float*)d_in[1];
    const float* v  = (const float*)d_in[2];
    const float* wq = (const float*)d_in[4];
    const float* bq = (const float*)d_in[5];
    const float* wk = (const float*)d_in[6];
    const float* bk = (const float*)d_in[7];
    const float* wv = (const float*)d_in[8];
    const float* bv = (const float*)d_in[9];
    const float* wo = (const float*)d_in[10];
    const float* bo = (const float*)d_in[11];
    float* out = (float*)d_out;

    // One merged conversion launch
    f2h_all_kernel<<<(NCONV_TOT + 255) / 256, 256>>>(
        (const float4*)q, (const float4*)k, (const float4*)v,
        (const float4*)wq, (const float4*)wk, (const float4*)wv, (const float4*)wo);

    // QKV projections
    cudaFuncSetAttribute(qkv_proj_kernel, cudaFuncAttributeMaxDynamicSharedMemorySize, GEMM_SMEM);
    dim3 gproj(MTOT / 128, DD / 128, 3);
    qkv_proj_kernel<<<gproj, 256, GEMM_SMEM>>>(bq, bk, bv);

    // Flash attention
    cudaFuncSetAttribute(attn_kernel, cudaFuncAttributeMaxDynamicSharedMemorySize, ATTN_SMEM);
    dim3 gattn(SS / 128, HH, BB);
    attn_kernel<<<gattn, 256, ATTN_SMEM>>>();

    // Output projection
    cudaFuncSetAttribute(out_proj_kernel, cudaFuncAttributeMaxDynamicSharedMemorySize, GEMM_SMEM);
    dim3 gout(MTOT / 128, DD / 128, 1);
    out_proj_kernel<<<gout, 256, GEMM_SMEM>>>(bo, out);
}

// round 8
// speedup vs baseline: 10.6373x; 1.0494x over previous
#include <cuda_runtime.h>
#include <cuda_fp16.h>
#include <math.h>
#include <stdint.h>

// Problem constants
#define BB 4
#define SS 2048
#define DD 1024
#define HH 16
#define DKK 64
#define MTOT (BB * SS)   // 8192

// Scratch device globals
__device__ __half g_Q[BB * HH * SS * DKK];    // [B,H,S,DK]
__device__ __half g_K[BB * HH * SS * DKK];
__device__ __half g_V[BB * HH * SS * DKK];
__device__ __half g_ATT[(size_t)MTOT * DD];   // [B,S,D]
__device__ __half g_qh[(size_t)MTOT * DD];
__device__ __half g_kh[(size_t)MTOT * DD];
__device__ __half g_vh[(size_t)MTOT * DD];
__device__ __half g_wqh[DD * DD];
__device__ __half g_wkh[DD * DD];
__device__ __half g_wvh[DD * DD];
__device__ __half g_woh[DD * DD];

// ---------------------------------------------------------------------------
// Helpers
// ---------------------------------------------------------------------------
__device__ __forceinline__ uint32_t su(const void* p) {
    return (uint32_t)__cvta_generic_to_shared(p);
}
__device__ __forceinline__ void ldm4(uint32_t* r, uint32_t a) {
    asm volatile("ldmatrix.sync.aligned.m8n8.x4.shared.b16 {%0,%1,%2,%3},[%4];"
        : "=r"(r[0]), "=r"(r[1]), "=r"(r[2]), "=r"(r[3]) : "r"(a));
}
__device__ __forceinline__ void ldm4t(uint32_t* r, uint32_t a) {
    asm volatile("ldmatrix.sync.aligned.m8n8.x4.trans.shared.b16 {%0,%1,%2,%3},[%4];"
        : "=r"(r[0]), "=r"(r[1]), "=r"(r[2]), "=r"(r[3]) : "r"(a));
}
__device__ __forceinline__ void mma16(float* d, const uint32_t* a, const uint32_t* b) {
    asm volatile(
        "mma.sync.aligned.m16n8k16.row.col.f32.f16.f16.f32 "
        "{%0,%1,%2,%3},{%4,%5,%6,%7},{%8,%9},{%0,%1,%2,%3};"
        : "+f"(d[0]), "+f"(d[1]), "+f"(d[2]), "+f"(d[3])
        : "r"(a[0]), "r"(a[1]), "r"(a[2]), "r"(a[3]), "r"(b[0]), "r"(b[1]));
}
__device__ __forceinline__ uint32_t packh2(float x, float y) {
    __half2 h = __floats2half2_rn(x, y);
    return *(uint32_t*)&h;
}
__device__ __forceinline__ void cpa16(uint32_t d, const void* s) {
    asm volatile("cp.async.cg.shared.global [%0],[%1],16;" :: "r"(d), "l"(s));
}
#define CP_COMMIT() asm volatile("cp.async.commit_group;")

// ---------------------------------------------------------------------------
// Merged f32 -> f16 convert for all 7 arrays (one launch)
// ---------------------------------------------------------------------------
#define NACT4 (MTOT * DD / 4)
#define NW4   (DD * DD / 4)
#define NCONV_TOT (3 * NACT4 + 4 * NW4)

__global__ __launch_bounds__(256) void f2h_all_kernel(
    const float4* __restrict__ q, const float4* __restrict__ k,
    const float4* __restrict__ v,
    const float4* __restrict__ wq, const float4* __restrict__ wk,
    const float4* __restrict__ wv, const float4* __restrict__ wo)
{
    int i = blockIdx.x * 256 + threadIdx.x;
    if (i >= NCONV_TOT) return;
    const float4* src;
    uint2* dst;
    int off;
    if (i < 3 * NACT4) {
        int w = i / NACT4;
        off = i - w * NACT4;
        src = (w == 0) ? q : (w == 1) ? k : v;
        dst = (uint2*)((w == 0) ? g_qh : (w == 1) ? g_kh : g_vh);
    } else {
        int j = i - 3 * NACT4;
        int w = j / NW4;
        off = j - w * NW4;
        src = (w == 0) ? wq : (w == 1) ? wk : (w == 2) ? wv : wo;
        dst = (uint2*)((w == 0) ? g_wqh : (w == 1) ? g_wkh : (w == 2) ? g_wvh : g_woh);
    }
    float4 val = src[off];
    dst[off] = make_uint2(packh2(val.x, val.y), packh2(val.z, val.w));
}

// ---------------------------------------------------------------------------
// Pipelined FP16 GEMM core: C = A @ W^T, tile 128x128, K=1024.
// k-chunk 64 (16 iterations), 3-stage ring, 2 chunks in flight.
// Rows padded to 72 halves (144B): ldmatrix phases conflict-free.
// 8 warps 2(m)x4(n), warp tile 64x32. One sync pair per 64 MMAs/warp.
// ---------------------------------------------------------------------------
#define PR 72
#define STG_B (128 * PR * 2)            // 18432 B per matrix per stage
#define NSTG 3
#define GEMM_SMEM (2 * NSTG * STG_B)    // 110592 B

__device__ __forceinline__ void gemm_pipe_core(
    const __half* __restrict__ A, const __half* __restrict__ W,
    __half* smem, float acc[4][4][4])
{
    const int t    = threadIdx.x;
    const int lane = t & 31;
    const int warp = t >> 5;
    const int wm   = warp >> 2;
    const int wn   = warp & 3;

    const int m0 = blockIdx.x * 128;
    const int n0 = blockIdx.y * 128;

    const uint32_t asB = su(smem);
    const uint32_t wsB = asB + NSTG * STG_B;

    // cp.async mapping: per stage per matrix, 128 rows x 8 x 16B = 1024 chunks,
    // 4 per thread (rows r0+32i, chunk c within the 128B of 64 halves)
    const int r0 = t >> 3;
    const int c  = t & 7;
    const __half* aS = A + (size_t)(m0 + r0) * DD + c * 8;
    const __half* wS = W + (size_t)(n0 + r0) * DD + c * 8;
    uint32_t dOff[4];
#pragma unroll
    for (int i = 0; i < 4; i++) dOff[i] = (uint32_t)((r0 + 32 * i) * (PR * 2) + c * 16);

    // ldmatrix addresses (stage 0 base)
    const int rowoff = (lane & 7) + ((lane >> 3) & 1) * 8;
    const int akoff  = ((lane >> 4) & 1) * 8;
    const int noff   = (lane & 7) + ((lane >> 4) & 1) * 8;
    const int bkoff  = ((lane >> 3) & 1) * 8;
    uint32_t aAddr[4], bAddr[2];
#pragma unroll
    for (int mi = 0; mi < 4; mi++)
        aAddr[mi] = asB + ((wm * 64 + mi * 16 + rowoff) * PR + akoff) * 2;
#pragma unroll
    for (int p = 0; p < 2; p++)
        bAddr[p] = wsB + ((wn * 32 + p * 16 + noff) * PR + bkoff) * 2;

    auto issue = [&](int s) {
        const int ko = s * 64;
        const uint32_t sb = (uint32_t)(s % NSTG) * STG_B;
#pragma unroll
        for (int i = 0; i < 4; i++) {
            cpa16(asB + sb + dOff[i], aS + (size_t)(32 * i) * DD + ko);
            cpa16(wsB + sb + dOff[i], wS + (size_t)(32 * i) * DD + ko);
        }
        CP_COMMIT();
    };

    issue(0);
    issue(1);

    const int NIT = DD / 64;   // 16
    for (int it = 0; it < NIT; it++) {
        if (it <= NIT - 2) { asm volatile("cp.async.wait_group 1;"); }
        else               { asm volatile("cp.async.wait_group 0;"); }
        __syncthreads();
        if (it + 2 < NIT) issue(it + 2);

        const uint32_t off = (uint32_t)(it % NSTG) * STG_B;
#pragma unroll
        for (int ks = 0; ks < 4; ks++) {
            uint32_t af[4][4];
#pragma unroll
            for (int mi = 0; mi < 4; mi++)
                ldm4(af[mi], aAddr[mi] + off + ks * 32);
            uint32_t bf[4][2];
#pragma unroll
            for (int p = 0; p < 2; p++) {
                uint32_t tmp[4];
                ldm4(tmp, bAddr[p] + off + ks * 32);
                bf[2 * p][0] = tmp[0]; bf[2 * p][1] = tmp[1];
                bf[2 * p + 1][0] = tmp[2]; bf[2 * p + 1][1] = tmp[3];
            }
#pragma unroll
            for (int mi = 0; mi < 4; mi++)
#pragma unroll
                for (int ni = 0; ni < 4; ni++)
                    mma16(acc[mi][ni], af[mi], bf[ni]);
        }
    }
}

// ---------------------------------------------------------------------------
// QKV projections (half in/out): Y = X @ W^T + b -> head-split [B,H,S,DK]
// ---------------------------------------------------------------------------
__global__ __launch_bounds__(256, 2) void qkv_proj_kernel(
    const float* __restrict__ bq, const float* __restrict__ bk,
    const float* __restrict__ bv)
{
    extern __shared__ __half smem[];

    const __half* A; const __half* W; const float* bias; __half* out;
    if (blockIdx.z == 0)      { A = g_qh; W = g_wqh; bias = bq; out = g_Q; }
    else if (blockIdx.z == 1) { A = g_kh; W = g_wkh; bias = bk; out = g_K; }
    else                      { A = g_vh; W = g_wvh; bias = bv; out = g_V; }

    float acc[4][4][4];
#pragma unroll
    for (int a = 0; a < 4; a++)
#pragma unroll
        for (int b = 0; b < 4; b++)
#pragma unroll
            for (int c = 0; c < 4; c++) acc[a][b][c] = 0.f;

    gemm_pipe_core(A, W, smem, acc);

    const int lane = threadIdx.x & 31;
    const int warp = threadIdx.x >> 5;
    const int wm = warp >> 2, wn = warp & 3;
    const int qq = lane & 3, l4 = lane >> 2;
    const int m0 = blockIdx.x * 128;
    const int n0 = blockIdx.y * 128;

#pragma unroll
    for (int mi = 0; mi < 4; mi++) {
#pragma unroll
        for (int rr = 0; rr < 2; rr++) {
            int m = m0 + wm * 64 + mi * 16 + l4 + rr * 8;
            int b = m >> 11;
            int s = m & 2047;
#pragma unroll
            for (int ni = 0; ni < 4; ni++) {
                int n  = n0 + wn * 32 + ni * 8 + 2 * qq;
                int h  = n >> 6;
                int dk = n & 63;
                __half2 hv = __floats2half2_rn(acc[mi][ni][rr * 2 + 0] + bias[n],
                                               acc[mi][ni][rr * 2 + 1] + bias[n + 1]);
                *(__half2*)&out[((size_t)(b * HH + h) * SS + s) * DKK + dk] = hv;
            }
        }
    }
}

// ---------------------------------------------------------------------------
// Output projection: out(f32) = g_ATT(half) @ Wo^T + bo
// ---------------------------------------------------------------------------
__global__ __launch_bounds__(256, 2) void out_proj_kernel(
    const float* __restrict__ bo, float* __restrict__ out)
{
    extern __shared__ __half smem[];

    float acc[4][4][4];
#pragma unroll
    for (int a = 0; a < 4; a++)
#pragma unroll
        for (int b = 0; b < 4; b++)
#pragma unroll
            for (int c = 0; c < 4; c++) acc[a][b][c] = 0.f;

    gemm_pipe_core(g_ATT, g_woh, smem, acc);

    const int lane = threadIdx.x & 31;
    const int warp = threadIdx.x >> 5;
    const int wm = warp >> 2, wn = warp & 3;
    const int qq = lane & 3, l4 = lane >> 2;
    const int m0 = blockIdx.x * 128;
    const int n0 = blockIdx.y * 128;

#pragma unroll
    for (int mi = 0; mi < 4; mi++) {
#pragma unroll
        for (int rr = 0; rr < 2; rr++) {
            int m = m0 + wm * 64 + mi * 16 + l4 + rr * 8;
#pragma unroll
            for (int ni = 0; ni < 4; ni++) {
                int n = n0 + wn * 32 + ni * 8 + 2 * qq;
                float2 rv;
                rv.x = acc[mi][ni][rr * 2 + 0] + bo[n];
                rv.y = acc[mi][ni][rr * 2 + 1] + bo[n + 1];
                *(float2*)&out[(size_t)m * DD + n] = rv;
            }
        }
    }
}

// ---------------------------------------------------------------------------
// Flash attention (causal), FP16 mma + ldmatrix + cp.async double-buffered K/V.
// ---------------------------------------------------------------------------
#define AR 72
#define Q_HALVES (128 * AR)
#define KV_HALVES (64 * AR)
#define ATTN_SMEM ((Q_HALVES + 4 * KV_HALVES) * 2)

__global__ __launch_bounds__(256) void attn_kernel()
{
    extern __shared__ __half sm[];
    __half* Qs = sm;
    __half* Ks0 = Qs + Q_HALVES;
    __half* Vs0 = Ks0 + KV_HALVES;
    __half* Ks1 = Vs0 + KV_HALVES;
    __half* Vs1 = Ks1 + KV_HALVES;

    const int t    = threadIdx.x;
    const int lane = t & 31;
    const int w    = t >> 5;
    const int qq   = lane & 3;
    const int l4   = lane >> 2;

    const int bx = blockIdx.x;
    const int h  = blockIdx.y;
    const int b  = blockIdx.z;

    const __half* Qbase = g_Q + ((size_t)(b * HH + h) * SS) * DKK;
    const __half* Kbase = g_K + ((size_t)(b * HH + h) * SS) * DKK;
    const __half* Vbase = g_V + ((size_t)(b * HH + h) * SS) * DKK;

    const uint32_t ksB[2] = { su(Ks0), su(Ks1) };
    const uint32_t vsB[2] = { su(Vs0), su(Vs1) };

    const int qr = t >> 3;
    const int qc = (t & 7) * 16;
    const int kr = t >> 3;
    const int kc = (t & 7) * 16;

    {
        uint32_t qdst = su(Qs);
#pragma unroll
        for (int i = 0; i < 4; i++) {
            int r = qr + 32 * i;
            cpa16(qdst + r * (AR * 2) + qc, (const char*)(Qbase + (size_t)(bx * 128 + r) * DKK) + qc);
        }
    }
    CP_COMMIT();

    {
#pragma unroll
        for (int i = 0; i < 2; i++) {
            int r = kr + 32 * i;
            cpa16(ksB[0] + r * (AR * 2) + kc, (const char*)(Kbase + (size_t)r * DKK) + kc);
            cpa16(vsB[0] + r * (AR * 2) + kc, (const char*)(Vbase + (size_t)r * DKK) + kc);
        }
    }
    CP_COMMIT();

    asm volatile("cp.async.wait_group 1;");
    __syncthreads();

    const int rowoff = (lane & 7) + ((lane >> 3) & 1) * 8;
    const int akoff  = ((lane >> 4) & 1) * 8;
    const int noff   = (lane & 7) + ((lane >> 4) & 1) * 8;
    const int bkoff  = ((lane >> 3) & 1) * 8;
    const int vkoff  = ((lane >> 4) & 1) * 8;

    uint32_t aq[4][4];
#pragma unroll
    for (int g = 0; g < 4; g++)
        ldm4(aq[g], su(&Qs[(16 * w + rowoff) * AR + g * 16 + akoff]));

    const int rl = 16 * w + l4;
    const int row_lo = bx * 128 + rl;
    const int row_hi = row_lo + 8;

    float m_lo = -1e30f, m_hi = -1e30f, l_lo = 0.f, l_hi = 0.f;
    float Oacc[8][4];
#pragma unroll
    for (int j = 0; j < 8; j++)
#pragma unroll
        for (int c = 0; c < 4; c++) Oacc[j][c] = 0.f;

    const int kt_max = 2 * bx + 1;
    for (int kt = 0; kt <= kt_max; kt++) {
        const int st = kt & 1;

        if (kt + 1 <= kt_max) {
            const __half* Kt = Kbase + (size_t)(kt + 1) * 64 * DKK;
            const __half* Vt = Vbase + (size_t)(kt + 1) * 64 * DKK;
            const int ns = st ^ 1;
#pragma unroll
            for (int i = 0; i < 2; i++) {
                int r = kr + 32 * i;
                cpa16(ksB[ns] + r * (AR * 2) + kc, (const char*)(Kt + (size_t)r * DKK) + kc);
                cpa16(vsB[ns] + r * (AR * 2) + kc, (const char*)(Vt + (size_t)r * DKK) + kc);
            }
            CP_COMMIT();
            asm volatile("cp.async.wait_group 1;");
        } else {
            asm volatile("cp.async.wait_group 0;");
        }
        __syncthreads();

        float Sacc[8][4];
#pragma unroll
        for (int j = 0; j < 8; j++)
#pragma unroll
            for (int c = 0; c < 4; c++) Sacc[j][c] = 0.f;

#pragma unroll
        for (int g = 0; g < 4; g++) {
#pragma unroll
            for (int p = 0; p < 4; p++) {
                uint32_t tmp[4];
                ldm4(tmp, ksB[st] + ((p * 16 + noff) * AR + g * 16 + bkoff) * 2);
                mma16(Sacc[2 * p],     aq[g], tmp);
                mma16(Sacc[2 * p + 1], aq[g], tmp + 2);
            }
        }

#pragma unroll
        for (int j = 0; j < 8; j++)
#pragma unroll
            for (int c = 0; c < 4; c++) Sacc[j][c] *= 0.125f;

        if (kt >= 2 * bx) {
#pragma unroll
            for (int j = 0; j < 8; j++) {
                int col = kt * 64 + 8 * j + 2 * qq;
                if (col     > row_lo) Sacc[j][0] = -1e30f;
                if (col + 1 > row_lo) Sacc[j][1] = -1e30f;
                if (col     > row_hi) Sacc[j][2] = -1e30f;
                if (col + 1 > row_hi) Sacc[j][3] = -1e30f;
            }
        }

        float mt_lo = -1e30f, mt_hi = -1e30f;
#pragma unroll
        for (int j = 0; j < 8; j++) {
            mt_lo = fmaxf(mt_lo, fmaxf(Sacc[j][0], Sacc[j][1]));
            mt_hi = fmaxf(mt_hi, fmaxf(Sacc[j][2], Sacc[j][3]));
        }
        mt_lo = fmaxf(mt_lo, __shfl_xor_sync(0xffffffffu, mt_lo, 1));
        mt_lo = fmaxf(mt_lo, __shfl_xor_sync(0xffffffffu, mt_lo, 2));
        mt_hi = fmaxf(mt_hi, __shfl_xor_sync(0xffffffffu, mt_hi, 1));
        mt_hi = fmaxf(mt_hi, __shfl_xor_sync(0xffffffffu, mt_hi, 2));

        float mn_lo = fmaxf(m_lo, mt_lo);
        float mn_hi = fmaxf(m_hi, mt_hi);
        float al_lo = __expf(m_lo - mn_lo);
        float al_hi = __expf(m_hi - mn_hi);

        float ls_lo = 0.f, ls_hi = 0.f;
#pragma unroll
        for (int j = 0; j < 8; j++) {
            Sacc[j][0] = __expf(Sacc[j][0] - mn_lo);
            Sacc[j][1] = __expf(Sacc[j][1] - mn_lo);
            Sacc[j][2] = __expf(Sacc[j][2] - mn_hi);
            Sacc[j][3] = __expf(Sacc[j][3] - mn_hi);
            ls_lo += Sacc[j][0] + Sacc[j][1];
            ls_hi += Sacc[j][2] + Sacc[j][3];
        }
        ls_lo += __shfl_xor_sync(0xffffffffu, ls_lo, 1);
        ls_lo += __shfl_xor_sync(0xffffffffu, ls_lo, 2);
        ls_hi += __shfl_xor_sync(0xffffffffu, ls_hi, 1);
        ls_hi += __shfl_xor_sync(0xffffffffu, ls_hi, 2);

        l_lo = l_lo * al_lo + ls_lo;
        l_hi = l_hi * al_hi + ls_hi;
        m_lo = mn_lo;
        m_hi = mn_hi;

        uint32_t ap[4][4];
#pragma unroll
        for (int g = 0; g < 4; g++) {
            ap[g][0] = packh2(Sacc[2 * g][0],     Sacc[2 * g][1]);
            ap[g][1] = packh2(Sacc[2 * g][2],     Sacc[2 * g][3]);
            ap[g][2] = packh2(Sacc[2 * g + 1][0], Sacc[2 * g + 1][1]);
            ap[g][3] = packh2(Sacc[2 * g + 1][2], Sacc[2 * g + 1][3]);
        }

#pragma unroll
        for (int j = 0; j < 8; j++) {
            Oacc[j][0] *= al_lo;
            Oacc[j][1] *= al_lo;
            Oacc[j][2] *= al_hi;
            Oacc[j][3] *= al_hi;
        }

#pragma unroll
        for (int g = 0; g < 4; g++) {
#pragma unroll
            for (int p = 0; p < 4; p++) {
                uint32_t tmp[4];
                ldm4t(tmp, vsB[st] + ((g * 16 + rowoff) * AR + p * 16 + vkoff) * 2);
                mma16(Oacc[2 * p],     ap[g], tmp);
                mma16(Oacc[2 * p + 1], ap[g], tmp + 2);
            }
        }

        __syncthreads();
    }

    float il_lo = 1.f / l_lo;
    float il_hi = 1.f / l_hi;
    __half* out_lo = g_ATT + ((size_t)(b * SS + row_lo)) * DD + h * DKK;
    __half* out_hi = g_ATT + ((size_t)(b * SS + row_hi)) * DD + h * DKK;
#pragma unroll
    for (int j = 0; j < 8; j++) {
        int dk = 8 * j + 2 * qq;
        *(__half2*)&out_lo[dk] = __floats2half2_rn(Oacc[j][0] * il_lo, Oacc[j][1] * il_lo);
        *(__half2*)&out_hi[dk] = __floats2half2_rn(Oacc[j][2] * il_hi, Oacc[j][3] * il_hi);
    }
}

// ---------------------------------------------------------------------------
// Entry point. Inputs: q,k,v,mask,w_q,b_q,w_k,b_k,w_v,b_v,w_o,b_o
// ---------------------------------------------------------------------------
extern "C" void kernel_launch(void* const* d_in, const int* in_sizes, int n_in,
                              void* d_out, int out_size)
{
    const float* q  = (const float*)d_in[0];
    const float* k  = (const float*)d_in[1];
    const float* v  = (const float*)d_in[2];
    const float* wq = (const float*)d_in[4];
    const float* bq = (const float*)d_in[5];
    const float* wk = (const float*)d_in[6];
    const float* bk = (const float*)d_in[7];
    const float* wv = (const float*)d_in[8];
    const float* bv = (const float*)d_in[9];
    const float* wo = (const float*)d_in[10];
    const float* bo = (const float*)d_in[11];
    float* out = (float*)d_out;

    f2h_all_kernel<<<(NCONV_TOT + 255) / 256, 256>>>(
        (const float4*)q, (const float4*)k, (const float4*)v,
        (const float4*)wq, (const float4*)wk, (const float4*)wv, (const float4*)wo);

    cudaFuncSetAttribute(qkv_proj_kernel, cudaFuncAttributeMaxDynamicSharedMemorySize, GEMM_SMEM);
    dim3 gproj(MTOT / 128, DD / 128, 3);
    qkv_proj_kernel<<<gproj, 256, GEMM_SMEM>>>(bq, bk, bv);

    cudaFuncSetAttribute(attn_kernel, cudaFuncAttributeMaxDynamicSharedMemorySize, ATTN_SMEM);
    dim3 gattn(SS / 128, HH, BB);
    attn_kernel<<<gattn, 256, ATTN_SMEM>>>();

    cudaFuncSetAttribute(out_proj_kernel, cudaFuncAttributeMaxDynamicSharedMemorySize, GEMM_SMEM);
    dim3 gout(MTOT / 128, DD / 128, 1);
    out_proj_kernel<<<gout, 256, GEMM_SMEM>>>(bo, out);
}

// round 9
// speedup vs baseline: 10.7426x; 1.0099x over previous
#include <cuda_runtime.h>
#include <cuda_fp16.h>
#include <math.h>
#include <stdint.h>

// Problem constants
#define BB 4
#define SS 2048
#define DD 1024
#define HH 16
#define DKK 64
#define MTOT (BB * SS)   // 8192

// Scratch device globals
__device__ __half g_Q[BB * HH * SS * DKK];    // [B,H,S,DK]
__device__ __half g_K[BB * HH * SS * DKK];
__device__ __half g_V[BB * HH * SS * DKK];
__device__ __half g_ATT[(size_t)MTOT * DD];   // [B,S,D]
__device__ __half g_qh[(size_t)MTOT * DD];
__device__ __half g_kh[(size_t)MTOT * DD];
__device__ __half g_vh[(size_t)MTOT * DD];
__device__ __half g_wqh[DD * DD];
__device__ __half g_wkh[DD * DD];
__device__ __half g_wvh[DD * DD];
__device__ __half g_woh[DD * DD];

// ---------------------------------------------------------------------------
// Helpers
// ---------------------------------------------------------------------------
__device__ __forceinline__ uint32_t su(const void* p) {
    return (uint32_t)__cvta_generic_to_shared(p);
}
__device__ __forceinline__ void ldm4(uint32_t* r, uint32_t a) {
    asm volatile("ldmatrix.sync.aligned.m8n8.x4.shared.b16 {%0,%1,%2,%3},[%4];"
        : "=r"(r[0]), "=r"(r[1]), "=r"(r[2]), "=r"(r[3]) : "r"(a));
}
__device__ __forceinline__ void ldm4t(uint32_t* r, uint32_t a) {
    asm volatile("ldmatrix.sync.aligned.m8n8.x4.trans.shared.b16 {%0,%1,%2,%3},[%4];"
        : "=r"(r[0]), "=r"(r[1]), "=r"(r[2]), "=r"(r[3]) : "r"(a));
}
__device__ __forceinline__ void mma16(float* d, const uint32_t* a, const uint32_t* b) {
    asm volatile(
        "mma.sync.aligned.m16n8k16.row.col.f32.f16.f16.f32 "
        "{%0,%1,%2,%3},{%4,%5,%6,%7},{%8,%9},{%0,%1,%2,%3};"
        : "+f"(d[0]), "+f"(d[1]), "+f"(d[2]), "+f"(d[3])
        : "r"(a[0]), "r"(a[1]), "r"(a[2]), "r"(a[3]), "r"(b[0]), "r"(b[1]));
}
__device__ __forceinline__ uint32_t packh2(float x, float y) {
    __half2 h = __floats2half2_rn(x, y);
    return *(uint32_t*)&h;
}
__device__ __forceinline__ void cpa16(uint32_t d, const void* s) {
    asm volatile("cp.async.cg.shared.global [%0],[%1],16;" :: "r"(d), "l"(s));
}
#define CP_COMMIT() asm volatile("cp.async.commit_group;")

// ---------------------------------------------------------------------------
// Merged f32 -> f16 convert for all 7 arrays (one launch)
// ---------------------------------------------------------------------------
#define NACT4 (MTOT * DD / 4)
#define NW4   (DD * DD / 4)
#define NCONV_TOT (3 * NACT4 + 4 * NW4)

__global__ __launch_bounds__(256) void f2h_all_kernel(
    const float4* __restrict__ q, const float4* __restrict__ k,
    const float4* __restrict__ v,
    const float4* __restrict__ wq, const float4* __restrict__ wk,
    const float4* __restrict__ wv, const float4* __restrict__ wo)
{
    int i = blockIdx.x * 256 + threadIdx.x;
    if (i >= NCONV_TOT) return;
    const float4* src;
    uint2* dst;
    int off;
    if (i < 3 * NACT4) {
        int w = i / NACT4;
        off = i - w * NACT4;
        src = (w == 0) ? q : (w == 1) ? k : v;
        dst = (uint2*)((w == 0) ? g_qh : (w == 1) ? g_kh : g_vh);
    } else {
        int j = i - 3 * NACT4;
        int w = j / NW4;
        off = j - w * NW4;
        src = (w == 0) ? wq : (w == 1) ? wk : (w == 2) ? wv : wo;
        dst = (uint2*)((w == 0) ? g_wqh : (w == 1) ? g_wkh : (w == 2) ? g_wvh : g_woh);
    }
    float4 val = src[off];
    dst[off] = make_uint2(packh2(val.x, val.y), packh2(val.z, val.w));
}

// ---------------------------------------------------------------------------
// Pipelined FP16 GEMM core: C = A @ W^T, tile 128x64, K=1024, k-chunk 64.
// 2-stage ring with compute-overlapped prefetch. 8 warps 4(m)x2(n),
// warp tile 32x32 (acc 32 floats -> fits 84-reg cap for 3 CTAs/SM).
// Rows padded to 72 halves (144B): ldmatrix phases conflict-free.
// ---------------------------------------------------------------------------
#define PR 72
#define A_STG (128 * PR * 2)            // 18432 B
#define W_STG (64 * PR * 2)             //  9216 B
#define GEMM_SMEM (2 * (A_STG + W_STG)) // 55296 B

__device__ __forceinline__ void gemm_pipe_core(
    const __half* __restrict__ A, const __half* __restrict__ W,
    __half* smem, float acc[2][4][4])
{
    const int t    = threadIdx.x;
    const int lane = t & 31;
    const int warp = t >> 5;
    const int wm   = warp >> 1;    // 0..3
    const int wn   = warp & 1;     // 0..1

    const int m0 = blockIdx.x * 128;
    const int n0 = blockIdx.y * 64;

    const uint32_t asB = su(smem);
    const uint32_t wsB = asB + 2 * A_STG;

    // cp.async mapping per stage: A 1024 chunks (4/thr), W 512 chunks (2/thr)
    const int r0 = t >> 3;          // 0..31
    const int c  = t & 7;
    const __half* aS = A + (size_t)(m0 + r0) * DD + c * 8;
    const __half* wS = W + (size_t)(n0 + r0) * DD + c * 8;
    const uint32_t cb = (uint32_t)(r0 * (PR * 2) + c * 16);

    // ldmatrix base addresses (stage 0)
    const int rowoff = (lane & 7) + ((lane >> 3) & 1) * 8;
    const int akoff  = ((lane >> 4) & 1) * 8;
    const int noff   = (lane & 7) + ((lane >> 4) & 1) * 8;
    const int bkoff  = ((lane >> 3) & 1) * 8;
    uint32_t aAddr[2], bAddr[2];
#pragma unroll
    for (int mi = 0; mi < 2; mi++)
        aAddr[mi] = asB + ((wm * 32 + mi * 16 + rowoff) * PR + akoff) * 2;
#pragma unroll
    for (int p = 0; p < 2; p++)
        bAddr[p] = wsB + ((wn * 32 + p * 16 + noff) * PR + bkoff) * 2;

    auto issue = [&](int s) {
        const int ko = s * 64;
        const uint32_t st = (uint32_t)(s & 1);
#pragma unroll
        for (int i = 0; i < 4; i++)
            cpa16(asB + st * A_STG + cb + (uint32_t)(32 * i) * (PR * 2),
                  aS + (size_t)(32 * i) * DD + ko);
#pragma unroll
        for (int i = 0; i < 2; i++)
            cpa16(wsB + st * W_STG + cb + (uint32_t)(32 * i) * (PR * 2),
                  wS + (size_t)(32 * i) * DD + ko);
        CP_COMMIT();
    };

    issue(0);

    const int NIT = DD / 64;   // 16
    for (int it = 0; it < NIT; it++) {
        asm volatile("cp.async.wait_group 0;");
        __syncthreads();
        if (it + 1 < NIT) issue(it + 1);

        const uint32_t offA = (uint32_t)(it & 1) * A_STG;
        const uint32_t offB = (uint32_t)(it & 1) * W_STG;
#pragma unroll
        for (int ks = 0; ks < 4; ks++) {
            uint32_t af[2][4];
#pragma unroll
            for (int mi = 0; mi < 2; mi++)
                ldm4(af[mi], aAddr[mi] + offA + ks * 32);
            uint32_t bf[4][2];
#pragma unroll
            for (int p = 0; p < 2; p++) {
                uint32_t tmp[4];
                ldm4(tmp, bAddr[p] + offB + ks * 32);
                bf[2 * p][0] = tmp[0]; bf[2 * p][1] = tmp[1];
                bf[2 * p + 1][0] = tmp[2]; bf[2 * p + 1][1] = tmp[3];
            }
#pragma unroll
            for (int mi = 0; mi < 2; mi++)
#pragma unroll
                for (int ni = 0; ni < 4; ni++)
                    mma16(acc[mi][ni], af[mi], bf[ni]);
        }
    }
}

// ---------------------------------------------------------------------------
// QKV projections (half in/out): Y = X @ W^T + b -> head-split [B,H,S,DK]
// ---------------------------------------------------------------------------
__global__ __launch_bounds__(256, 3) void qkv_proj_kernel(
    const float* __restrict__ bq, const float* __restrict__ bk,
    const float* __restrict__ bv)
{
    extern __shared__ __half smem[];

    const __half* A; const __half* W; const float* bias; __half* out;
    if (blockIdx.z == 0)      { A = g_qh; W = g_wqh; bias = bq; out = g_Q; }
    else if (blockIdx.z == 1) { A = g_kh; W = g_wkh; bias = bk; out = g_K; }
    else                      { A = g_vh; W = g_wvh; bias = bv; out = g_V; }

    float acc[2][4][4];
#pragma unroll
    for (int a = 0; a < 2; a++)
#pragma unroll
        for (int b = 0; b < 4; b++)
#pragma unroll
            for (int c = 0; c < 4; c++) acc[a][b][c] = 0.f;

    gemm_pipe_core(A, W, smem, acc);

    const int lane = threadIdx.x & 31;
    const int warp = threadIdx.x >> 5;
    const int wm = warp >> 1, wn = warp & 1;
    const int qq = lane & 3, l4 = lane >> 2;
    const int m0 = blockIdx.x * 128;
    const int n0 = blockIdx.y * 64;

#pragma unroll
    for (int mi = 0; mi < 2; mi++) {
#pragma unroll
        for (int rr = 0; rr < 2; rr++) {
            int m = m0 + wm * 32 + mi * 16 + l4 + rr * 8;
            int b = m >> 11;
            int s = m & 2047;
#pragma unroll
            for (int ni = 0; ni < 4; ni++) {
                int n  = n0 + wn * 32 + ni * 8 + 2 * qq;
                int h  = n >> 6;
                int dk = n & 63;
                __half2 hv = __floats2half2_rn(acc[mi][ni][rr * 2 + 0] + bias[n],
                                               acc[mi][ni][rr * 2 + 1] + bias[n + 1]);
                *(__half2*)&out[((size_t)(b * HH + h) * SS + s) * DKK + dk] = hv;
            }
        }
    }
}

// ---------------------------------------------------------------------------
// Output projection: out(f32) = g_ATT(half) @ Wo^T + bo
// ---------------------------------------------------------------------------
__global__ __launch_bounds__(256, 3) void out_proj_kernel(
    const float* __restrict__ bo, float* __restrict__ out)
{
    extern __shared__ __half smem[];

    float acc[2][4][4];
#pragma unroll
    for (int a = 0; a < 2; a++)
#pragma unroll
        for (int b = 0; b < 4; b++)
#pragma unroll
            for (int c = 0; c < 4; c++) acc[a][b][c] = 0.f;

    gemm_pipe_core(g_ATT, g_woh, smem, acc);

    const int lane = threadIdx.x & 31;
    const int warp = threadIdx.x >> 5;
    const int wm = warp >> 1, wn = warp & 1;
    const int qq = lane & 3, l4 = lane >> 2;
    const int m0 = blockIdx.x * 128;
    const int n0 = blockIdx.y * 64;

#pragma unroll
    for (int mi = 0; mi < 2; mi++) {
#pragma unroll
        for (int rr = 0; rr < 2; rr++) {
            int m = m0 + wm * 32 + mi * 16 + l4 + rr * 8;
#pragma unroll
            for (int ni = 0; ni < 4; ni++) {
                int n = n0 + wn * 32 + ni * 8 + 2 * qq;
                float2 rv;
                rv.x = acc[mi][ni][rr * 2 + 0] + bo[n];
                rv.y = acc[mi][ni][rr * 2 + 1] + bo[n + 1];
                *(float2*)&out[(size_t)m * DD + n] = rv;
            }
        }
    }
}

// ---------------------------------------------------------------------------
// Flash attention (causal), FP16 mma + ldmatrix + cp.async double-buffered K/V.
// Now bounded to 2 CTAs/SM (reg cap 128) to double warps/SMSP.
// ---------------------------------------------------------------------------
#define AR 72
#define Q_HALVES (128 * AR)
#define KV_HALVES (64 * AR)
#define ATTN_SMEM ((Q_HALVES + 4 * KV_HALVES) * 2)

__global__ __launch_bounds__(256, 2) void attn_kernel()
{
    extern __shared__ __half sm[];
    __half* Qs = sm;
    __half* Ks0 = Qs + Q_HALVES;
    __half* Vs0 = Ks0 + KV_HALVES;
    __half* Ks1 = Vs0 + KV_HALVES;
    __half* Vs1 = Ks1 + KV_HALVES;

    const int t    = threadIdx.x;
    const int lane = t & 31;
    const int w    = t >> 5;
    const int qq   = lane & 3;
    const int l4   = lane >> 2;

    const int bx = blockIdx.x;
    const int h  = blockIdx.y;
    const int b  = blockIdx.z;

    const __half* Qbase = g_Q + ((size_t)(b * HH + h) * SS) * DKK;
    const __half* Kbase = g_K + ((size_t)(b * HH + h) * SS) * DKK;
    const __half* Vbase = g_V + ((size_t)(b * HH + h) * SS) * DKK;

    const uint32_t ksB[2] = { su(Ks0), su(Ks1) };
    const uint32_t vsB[2] = { su(Vs0), su(Vs1) };

    const int qr = t >> 3;
    const int qc = (t & 7) * 16;
    const int kr = t >> 3;
    const int kc = (t & 7) * 16;

    {
        uint32_t qdst = su(Qs);
#pragma unroll
        for (int i = 0; i < 4; i++) {
            int r = qr + 32 * i;
            cpa16(qdst + r * (AR * 2) + qc, (const char*)(Qbase + (size_t)(bx * 128 + r) * DKK) + qc);
        }
    }
    CP_COMMIT();

    {
#pragma unroll
        for (int i = 0; i < 2; i++) {
            int r = kr + 32 * i;
            cpa16(ksB[0] + r * (AR * 2) + kc, (const char*)(Kbase + (size_t)r * DKK) + kc);
            cpa16(vsB[0] + r * (AR * 2) + kc, (const char*)(Vbase + (size_t)r * DKK) + kc);
        }
    }
    CP_COMMIT();

    asm volatile("cp.async.wait_group 1;");
    __syncthreads();

    const int rowoff = (lane & 7) + ((lane >> 3) & 1) * 8;
    const int akoff  = ((lane >> 4) & 1) * 8;
    const int noff   = (lane & 7) + ((lane >> 4) & 1) * 8;
    const int bkoff  = ((lane >> 3) & 1) * 8;
    const int vkoff  = ((lane >> 4) & 1) * 8;

    uint32_t aq[4][4];
#pragma unroll
    for (int g = 0; g < 4; g++)
        ldm4(aq[g], su(&Qs[(16 * w + rowoff) * AR + g * 16 + akoff]));

    const int rl = 16 * w + l4;
    const int row_lo = bx * 128 + rl;
    const int row_hi = row_lo + 8;

    float m_lo = -1e30f, m_hi = -1e30f, l_lo = 0.f, l_hi = 0.f;
    float Oacc[8][4];
#pragma unroll
    for (int j = 0; j < 8; j++)
#pragma unroll
        for (int c = 0; c < 4; c++) Oacc[j][c] = 0.f;

    const int kt_max = 2 * bx + 1;
    for (int kt = 0; kt <= kt_max; kt++) {
        const int st = kt & 1;

        if (kt + 1 <= kt_max) {
            const __half* Kt = Kbase + (size_t)(kt + 1) * 64 * DKK;
            const __half* Vt = Vbase + (size_t)(kt + 1) * 64 * DKK;
            const int ns = st ^ 1;
#pragma unroll
            for (int i = 0; i < 2; i++) {
                int r = kr + 32 * i;
                cpa16(ksB[ns] + r * (AR * 2) + kc, (const char*)(Kt + (size_t)r * DKK) + kc);
                cpa16(vsB[ns] + r * (AR * 2) + kc, (const char*)(Vt + (size_t)r * DKK) + kc);
            }
            CP_COMMIT();
            asm volatile("cp.async.wait_group 1;");
        } else {
            asm volatile("cp.async.wait_group 0;");
        }
        __syncthreads();

        float Sacc[8][4];
#pragma unroll
        for (int j = 0; j < 8; j++)
#pragma unroll
            for (int c = 0; c < 4; c++) Sacc[j][c] = 0.f;

#pragma unroll
        for (int g = 0; g < 4; g++) {
#pragma unroll
            for (int p = 0; p < 4; p++) {
                uint32_t tmp[4];
                ldm4(tmp, ksB[st] + ((p * 16 + noff) * AR + g * 16 + bkoff) * 2);
                mma16(Sacc[2 * p],     aq[g], tmp);
                mma16(Sacc[2 * p + 1], aq[g], tmp + 2);
            }
        }

#pragma unroll
        for (int j = 0; j < 8; j++)
#pragma unroll
            for (int c = 0; c < 4; c++) Sacc[j][c] *= 0.125f;

        if (kt >= 2 * bx) {
#pragma unroll
            for (int j = 0; j < 8; j++) {
                int col = kt * 64 + 8 * j + 2 * qq;
                if (col     > row_lo) Sacc[j][0] = -1e30f;
                if (col + 1 > row_lo) Sacc[j][1] = -1e30f;
                if (col     > row_hi) Sacc[j][2] = -1e30f;
                if (col + 1 > row_hi) Sacc[j][3] = -1e30f;
            }
        }

        float mt_lo = -1e30f, mt_hi = -1e30f;
#pragma unroll
        for (int j = 0; j < 8; j++) {
            mt_lo = fmaxf(mt_lo, fmaxf(Sacc[j][0], Sacc[j][1]));
            mt_hi = fmaxf(mt_hi, fmaxf(Sacc[j][2], Sacc[j][3]));
        }
        mt_lo = fmaxf(mt_lo, __shfl_xor_sync(0xffffffffu, mt_lo, 1));
        mt_lo = fmaxf(mt_lo, __shfl_xor_sync(0xffffffffu, mt_lo, 2));
        mt_hi = fmaxf(mt_hi, __shfl_xor_sync(0xffffffffu, mt_hi, 1));
        mt_hi = fmaxf(mt_hi, __shfl_xor_sync(0xffffffffu, mt_hi, 2));

        float mn_lo = fmaxf(m_lo, mt_lo);
        float mn_hi = fmaxf(m_hi, mt_hi);
        float al_lo = __expf(m_lo - mn_lo);
        float al_hi = __expf(m_hi - mn_hi);

        float ls_lo = 0.f, ls_hi = 0.f;
#pragma unroll
        for (int j = 0; j < 8; j++) {
            Sacc[j][0] = __expf(Sacc[j][0] - mn_lo);
            Sacc[j][1] = __expf(Sacc[j][1] - mn_lo);
            Sacc[j][2] = __expf(Sacc[j][2] - mn_hi);
            Sacc[j][3] = __expf(Sacc[j][3] - mn_hi);
            ls_lo += Sacc[j][0] + Sacc[j][1];
            ls_hi += Sacc[j][2] + Sacc[j][3];
        }
        ls_lo += __shfl_xor_sync(0xffffffffu, ls_lo, 1);
        ls_lo += __shfl_xor_sync(0xffffffffu, ls_lo, 2);
        ls_hi += __shfl_xor_sync(0xffffffffu, ls_hi, 1);
        ls_hi += __shfl_xor_sync(0xffffffffu, ls_hi, 2);

        l_lo = l_lo * al_lo + ls_lo;
        l_hi = l_hi * al_hi + ls_hi;
        m_lo = mn_lo;
        m_hi = mn_hi;

        uint32_t ap[4][4];
#pragma unroll
        for (int g = 0; g < 4; g++) {
            ap[g][0] = packh2(Sacc[2 * g][0],     Sacc[2 * g][1]);
            ap[g][1] = packh2(Sacc[2 * g][2],     Sacc[2 * g][3]);
            ap[g][2] = packh2(Sacc[2 * g + 1][0], Sacc[2 * g + 1][1]);
            ap[g][3] = packh2(Sacc[2 * g + 1][2], Sacc[2 * g + 1][3]);
        }

#pragma unroll
        for (int j = 0; j < 8; j++) {
            Oacc[j][0] *= al_lo;
            Oacc[j][1] *= al_lo;
            Oacc[j][2] *= al_hi;
            Oacc[j][3] *= al_hi;
        }

#pragma unroll
        for (int g = 0; g < 4; g++) {
#pragma unroll
            for (int p = 0; p < 4; p++) {
                uint32_t tmp[4];
                ldm4t(tmp, vsB[st] + ((g * 16 + rowoff) * AR + p * 16 + vkoff) * 2);
                mma16(Oacc[2 * p],     ap[g], tmp);
                mma16(Oacc[2 * p + 1], ap[g], tmp + 2);
            }
        }

        __syncthreads();
    }

    float il_lo = 1.f / l_lo;
    float il_hi = 1.f / l_hi;
    __half* out_lo = g_ATT + ((size_t)(b * SS + row_lo)) * DD + h * DKK;
    __half* out_hi = g_ATT + ((size_t)(b * SS + row_hi)) * DD + h * DKK;
#pragma unroll
    for (int j = 0; j < 8; j++) {
        int dk = 8 * j + 2 * qq;
        *(__half2*)&out_lo[dk] = __floats2half2_rn(Oacc[j][0] * il_lo, Oacc[j][1] * il_lo);
        *(__half2*)&out_hi[dk] = __floats2half2_rn(Oacc[j][2] * il_hi, Oacc[j][3] * il_hi);
    }
}

// ---------------------------------------------------------------------------
// Entry point. Inputs: q,k,v,mask,w_q,b_q,w_k,b_k,w_v,b_v,w_o,b_o
// ---------------------------------------------------------------------------
extern "C" void kernel_launch(void* const* d_in, const int* in_sizes, int n_in,
                              void* d_out, int out_size)
{
    const float* q  = (const float*)d_in[0];
    const float* k  = (const float*)d_in[1];
    const float* v  = (const float*)d_in[2];
    const float* wq = (const float*)d_in[4];
    const float* bq = (const float*)d_in[5];
    const float* wk = (const float*)d_in[6];
    const float* bk = (const float*)d_in[7];
    const float* wv = (const float*)d_in[8];
    const float* bv = (const float*)d_in[9];
    const float* wo = (const float*)d_in[10];
    const float* bo = (const float*)d_in[11];
    float* out = (float*)d_out;

    f2h_all_kernel<<<(NCONV_TOT + 255) / 256, 256>>>(
        (const float4*)q, (const float4*)k, (const float4*)v,
        (const float4*)wq, (const float4*)wk, (const float4*)wv, (const float4*)wo);

    cudaFuncSetAttribute(qkv_proj_kernel, cudaFuncAttributeMaxDynamicSharedMemorySize, GEMM_SMEM);
    dim3 gproj(MTOT / 128, DD / 64, 3);
    qkv_proj_kernel<<<gproj, 256, GEMM_SMEM>>>(bq, bk, bv);

    cudaFuncSetAttribute(attn_kernel, cudaFuncAttributeMaxDynamicSharedMemorySize, ATTN_SMEM);
    dim3 gattn(SS / 128, HH, BB);
    attn_kernel<<<gattn, 256, ATTN_SMEM>>>();

    cudaFuncSetAttribute(out_proj_kernel, cudaFuncAttributeMaxDynamicSharedMemorySize, GEMM_SMEM);
    dim3 gout(MTOT / 128, DD / 64, 1);
    out_proj_kernel<<<gout, 256, GEMM_SMEM>>>(bo, out);
}

// round 10
// speedup vs baseline: 10.7774x; 1.0032x over previous
#include <cuda_runtime.h>
#include <cuda_fp16.h>
#include <math.h>
#include <stdint.h>

// Problem constants
#define BB 4
#define SS 2048
#define DD 1024
#define HH 16
#define DKK 64
#define MTOT (BB * SS)   // 8192

// Scratch device globals
__device__ __half g_Q[BB * HH * SS * DKK];    // [B,H,S,DK]
__device__ __half g_K[BB * HH * SS * DKK];
__device__ __half g_V[BB * HH * SS * DKK];
__device__ __half g_ATT[(size_t)MTOT * DD];   // [B,S,D]
__device__ __half g_qh[(size_t)MTOT * DD];
__device__ __half g_kh[(size_t)MTOT * DD];
__device__ __half g_vh[(size_t)MTOT * DD];
__device__ __half g_wqh[DD * DD];
__device__ __half g_wkh[DD * DD];
__device__ __half g_wvh[DD * DD];
__device__ __half g_woh[DD * DD];

// ---------------------------------------------------------------------------
// Helpers
// ---------------------------------------------------------------------------
__device__ __forceinline__ uint32_t su(const void* p) {
    return (uint32_t)__cvta_generic_to_shared(p);
}
__device__ __forceinline__ void ldm4(uint32_t* r, uint32_t a) {
    asm volatile("ldmatrix.sync.aligned.m8n8.x4.shared.b16 {%0,%1,%2,%3},[%4];"
        : "=r"(r[0]), "=r"(r[1]), "=r"(r[2]), "=r"(r[3]) : "r"(a));
}
__device__ __forceinline__ void ldm4t(uint32_t* r, uint32_t a) {
    asm volatile("ldmatrix.sync.aligned.m8n8.x4.trans.shared.b16 {%0,%1,%2,%3},[%4];"
        : "=r"(r[0]), "=r"(r[1]), "=r"(r[2]), "=r"(r[3]) : "r"(a));
}
__device__ __forceinline__ void mma16(float* d, const uint32_t* a, const uint32_t* b) {
    asm volatile(
        "mma.sync.aligned.m16n8k16.row.col.f32.f16.f16.f32 "
        "{%0,%1,%2,%3},{%4,%5,%6,%7},{%8,%9},{%0,%1,%2,%3};"
        : "+f"(d[0]), "+f"(d[1]), "+f"(d[2]), "+f"(d[3])
        : "r"(a[0]), "r"(a[1]), "r"(a[2]), "r"(a[3]), "r"(b[0]), "r"(b[1]));
}
__device__ __forceinline__ uint32_t packh2(float x, float y) {
    __half2 h = __floats2half2_rn(x, y);
    return *(uint32_t*)&h;
}
__device__ __forceinline__ void cpa16(uint32_t d, const void* s) {
    asm volatile("cp.async.cg.shared.global [%0],[%1],16;" :: "r"(d), "l"(s));
}
#define CP_COMMIT() asm volatile("cp.async.commit_group;")

// ---------------------------------------------------------------------------
// Merged f32 -> f16 convert for all 7 arrays (one launch)
// ---------------------------------------------------------------------------
#define NACT4 (MTOT * DD / 4)
#define NW4   (DD * DD / 4)
#define NCONV_TOT (3 * NACT4 + 4 * NW4)

__global__ __launch_bounds__(256) void f2h_all_kernel(
    const float4* __restrict__ q, const float4* __restrict__ k,
    const float4* __restrict__ v,
    const float4* __restrict__ wq, const float4* __restrict__ wk,
    const float4* __restrict__ wv, const float4* __restrict__ wo)
{
    int i = blockIdx.x * 256 + threadIdx.x;
    if (i >= NCONV_TOT) return;
    const float4* src;
    uint2* dst;
    int off;
    if (i < 3 * NACT4) {
        int w = i / NACT4;
        off = i - w * NACT4;
        src = (w == 0) ? q : (w == 1) ? k : v;
        dst = (uint2*)((w == 0) ? g_qh : (w == 1) ? g_kh : g_vh);
    } else {
        int j = i - 3 * NACT4;
        int w = j / NW4;
        off = j - w * NW4;
        src = (w == 0) ? wq : (w == 1) ? wk : (w == 2) ? wv : wo;
        dst = (uint2*)((w == 0) ? g_wqh : (w == 1) ? g_wkh : (w == 2) ? g_wvh : g_woh);
    }
    float4 val = src[off];
    dst[off] = make_uint2(packh2(val.x, val.y), packh2(val.z, val.w));
}

// ---------------------------------------------------------------------------
// Pipelined FP16 GEMM core: C = A @ W^T, tile 128x64, K=1024, k-chunk 64.
// 2-stage ring with compute-overlapped prefetch. 8 warps 4(m)x2(n),
// warp tile 32x32 (acc 32 floats -> fits 84-reg cap for 3 CTAs/SM).
// Rows padded to 72 halves (144B): ldmatrix phases conflict-free.
// ---------------------------------------------------------------------------
#define PR 72
#define A_STG (128 * PR * 2)            // 18432 B
#define W_STG (64 * PR * 2)             //  9216 B
#define GEMM_SMEM (2 * (A_STG + W_STG)) // 55296 B

__device__ __forceinline__ void gemm_pipe_core(
    const __half* __restrict__ A, const __half* __restrict__ W,
    __half* smem, float acc[2][4][4])
{
    const int t    = threadIdx.x;
    const int lane = t & 31;
    const int warp = t >> 5;
    const int wm   = warp >> 1;    // 0..3
    const int wn   = warp & 1;     // 0..1

    const int m0 = blockIdx.x * 128;
    const int n0 = blockIdx.y * 64;

    const uint32_t asB = su(smem);
    const uint32_t wsB = asB + 2 * A_STG;

    // cp.async mapping per stage: A 1024 chunks (4/thr), W 512 chunks (2/thr)
    const int r0 = t >> 3;          // 0..31
    const int c  = t & 7;
    const __half* aS = A + (size_t)(m0 + r0) * DD + c * 8;
    const __half* wS = W + (size_t)(n0 + r0) * DD + c * 8;
    const uint32_t cb = (uint32_t)(r0 * (PR * 2) + c * 16);

    // ldmatrix base addresses (stage 0)
    const int rowoff = (lane & 7) + ((lane >> 3) & 1) * 8;
    const int akoff  = ((lane >> 4) & 1) * 8;
    const int noff   = (lane & 7) + ((lane >> 4) & 1) * 8;
    const int bkoff  = ((lane >> 3) & 1) * 8;
    uint32_t aAddr[2], bAddr[2];
#pragma unroll
    for (int mi = 0; mi < 2; mi++)
        aAddr[mi] = asB + ((wm * 32 + mi * 16 + rowoff) * PR + akoff) * 2;
#pragma unroll
    for (int p = 0; p < 2; p++)
        bAddr[p] = wsB + ((wn * 32 + p * 16 + noff) * PR + bkoff) * 2;

    auto issue = [&](int s) {
        const int ko = s * 64;
        const uint32_t st = (uint32_t)(s & 1);
#pragma unroll
        for (int i = 0; i < 4; i++)
            cpa16(asB + st * A_STG + cb + (uint32_t)(32 * i) * (PR * 2),
                  aS + (size_t)(32 * i) * DD + ko);
#pragma unroll
        for (int i = 0; i < 2; i++)
            cpa16(wsB + st * W_STG + cb + (uint32_t)(32 * i) * (PR * 2),
                  wS + (size_t)(32 * i) * DD + ko);
        CP_COMMIT();
    };

    issue(0);

    const int NIT = DD / 64;   // 16
    for (int it = 0; it < NIT; it++) {
        asm volatile("cp.async.wait_group 0;");
        __syncthreads();
        if (it + 1 < NIT) issue(it + 1);

        const uint32_t offA = (uint32_t)(it & 1) * A_STG;
        const uint32_t offB = (uint32_t)(it & 1) * W_STG;
#pragma unroll
        for (int ks = 0; ks < 4; ks++) {
            uint32_t af[2][4];
#pragma unroll
            for (int mi = 0; mi < 2; mi++)
                ldm4(af[mi], aAddr[mi] + offA + ks * 32);
            uint32_t bf[4][2];
#pragma unroll
            for (int p = 0; p < 2; p++) {
                uint32_t tmp[4];
                ldm4(tmp, bAddr[p] + offB + ks * 32);
                bf[2 * p][0] = tmp[0]; bf[2 * p][1] = tmp[1];
                bf[2 * p + 1][0] = tmp[2]; bf[2 * p + 1][1] = tmp[3];
            }
#pragma unroll
            for (int mi = 0; mi < 2; mi++)
#pragma unroll
                for (int ni = 0; ni < 4; ni++)
                    mma16(acc[mi][ni], af[mi], bf[ni]);
        }
    }
}

// ---------------------------------------------------------------------------
// QKV projections (half in/out): Y = X @ W^T + b -> head-split [B,H,S,DK]
// ---------------------------------------------------------------------------
__global__ __launch_bounds__(256, 3) void qkv_proj_kernel(
    const float* __restrict__ bq, const float* __restrict__ bk,
    const float* __restrict__ bv)
{
    extern __shared__ __half smem[];

    const __half* A; const __half* W; const float* bias; __half* out;
    if (blockIdx.z == 0)      { A = g_qh; W = g_wqh; bias = bq; out = g_Q; }
    else if (blockIdx.z == 1) { A = g_kh; W = g_wkh; bias = bk; out = g_K; }
    else                      { A = g_vh; W = g_wvh; bias = bv; out = g_V; }

    float acc[2][4][4];
#pragma unroll
    for (int a = 0; a < 2; a++)
#pragma unroll
        for (int b = 0; b < 4; b++)
#pragma unroll
            for (int c = 0; c < 4; c++) acc[a][b][c] = 0.f;

    gemm_pipe_core(A, W, smem, acc);

    const int lane = threadIdx.x & 31;
    const int warp = threadIdx.x >> 5;
    const int wm = warp >> 1, wn = warp & 1;
    const int qq = lane & 3, l4 = lane >> 2;
    const int m0 = blockIdx.x * 128;
    const int n0 = blockIdx.y * 64;

#pragma unroll
    for (int mi = 0; mi < 2; mi++) {
#pragma unroll
        for (int rr = 0; rr < 2; rr++) {
            int m = m0 + wm * 32 + mi * 16 + l4 + rr * 8;
            int b = m >> 11;
            int s = m & 2047;
#pragma unroll
            for (int ni = 0; ni < 4; ni++) {
                int n  = n0 + wn * 32 + ni * 8 + 2 * qq;
                int h  = n >> 6;
                int dk = n & 63;
                __half2 hv = __floats2half2_rn(acc[mi][ni][rr * 2 + 0] + bias[n],
                                               acc[mi][ni][rr * 2 + 1] + bias[n + 1]);
                *(__half2*)&out[((size_t)(b * HH + h) * SS + s) * DKK + dk] = hv;
            }
        }
    }
}

// ---------------------------------------------------------------------------
// Output projection: out(f32) = g_ATT(half) @ Wo^T + bo
// ---------------------------------------------------------------------------
__global__ __launch_bounds__(256, 3) void out_proj_kernel(
    const float* __restrict__ bo, float* __restrict__ out)
{
    extern __shared__ __half smem[];

    float acc[2][4][4];
#pragma unroll
    for (int a = 0; a < 2; a++)
#pragma unroll
        for (int b = 0; b < 4; b++)
#pragma unroll
            for (int c = 0; c < 4; c++) acc[a][b][c] = 0.f;

    gemm_pipe_core(g_ATT, g_woh, smem, acc);

    const int lane = threadIdx.x & 31;
    const int warp = threadIdx.x >> 5;
    const int wm = warp >> 1, wn = warp & 1;
    const int qq = lane & 3, l4 = lane >> 2;
    const int m0 = blockIdx.x * 128;
    const int n0 = blockIdx.y * 64;

#pragma unroll
    for (int mi = 0; mi < 2; mi++) {
#pragma unroll
        for (int rr = 0; rr < 2; rr++) {
            int m = m0 + wm * 32 + mi * 16 + l4 + rr * 8;
#pragma unroll
            for (int ni = 0; ni < 4; ni++) {
                int n = n0 + wn * 32 + ni * 8 + 2 * qq;
                float2 rv;
                rv.x = acc[mi][ni][rr * 2 + 0] + bo[n];
                rv.y = acc[mi][ni][rr * 2 + 1] + bo[n + 1];
                *(float2*)&out[(size_t)m * DD + n] = rv;
            }
        }
    }
}

// ---------------------------------------------------------------------------
// Flash attention (causal), FP16 mma + ldmatrix + cp.async double-buffered K/V.
// Now bounded to 2 CTAs/SM (reg cap 128) to double warps/SMSP.
// ---------------------------------------------------------------------------
#define AR 72
#define Q_HALVES (128 * AR)
#define KV_HALVES (64 * AR)
#define ATTN_SMEM ((Q_HALVES + 4 * KV_HALVES) * 2)

__global__ __launch_bounds__(256, 2) void attn_kernel()
{
    extern __shared__ __half sm[];
    __half* Qs = sm;
    __half* Ks0 = Qs + Q_HALVES;
    __half* Vs0 = Ks0 + KV_HALVES;
    __half* Ks1 = Vs0 + KV_HALVES;
    __half* Vs1 = Ks1 + KV_HALVES;

    const int t    = threadIdx.x;
    const int lane = t & 31;
    const int w    = t >> 5;
    const int qq   = lane & 3;
    const int l4   = lane >> 2;

    const int bx = blockIdx.x;
    const int h  = blockIdx.y;
    const int b  = blockIdx.z;

    const __half* Qbase = g_Q + ((size_t)(b * HH + h) * SS) * DKK;
    const __half* Kbase = g_K + ((size_t)(b * HH + h) * SS) * DKK;
    const __half* Vbase = g_V + ((size_t)(b * HH + h) * SS) * DKK;

    const uint32_t ksB[2] = { su(Ks0), su(Ks1) };
    const uint32_t vsB[2] = { su(Vs0), su(Vs1) };

    const int qr = t >> 3;
    const int qc = (t & 7) * 16;
    const int kr = t >> 3;
    const int kc = (t & 7) * 16;

    {
        uint32_t qdst = su(Qs);
#pragma unroll
        for (int i = 0; i < 4; i++) {
            int r = qr + 32 * i;
            cpa16(qdst + r * (AR * 2) + qc, (const char*)(Qbase + (size_t)(bx * 128 + r) * DKK) + qc);
        }
    }
    CP_COMMIT();

    {
#pragma unroll
        for (int i = 0; i < 2; i++) {
            int r = kr + 32 * i;
            cpa16(ksB[0] + r * (AR * 2) + kc, (const char*)(Kbase + (size_t)r * DKK) + kc);
            cpa16(vsB[0] + r * (AR * 2) + kc, (const char*)(Vbase + (size_t)r * DKK) + kc);
        }
    }
    CP_COMMIT();

    asm volatile("cp.async.wait_group 1;");
    __syncthreads();

    const int rowoff = (lane & 7) + ((lane >> 3) & 1) * 8;
    const int akoff  = ((lane >> 4) & 1) * 8;
    const int noff   = (lane & 7) + ((lane >> 4) & 1) * 8;
    const int bkoff  = ((lane >> 3) & 1) * 8;
    const int vkoff  = ((lane >> 4) & 1) * 8;

    uint32_t aq[4][4];
#pragma unroll
    for (int g = 0; g < 4; g++)
        ldm4(aq[g], su(&Qs[(16 * w + rowoff) * AR + g * 16 + akoff]));

    const int rl = 16 * w + l4;
    const int row_lo = bx * 128 + rl;
    const int row_hi = row_lo + 8;

    float m_lo = -1e30f, m_hi = -1e30f, l_lo = 0.f, l_hi = 0.f;
    float Oacc[8][4];
#pragma unroll
    for (int j = 0; j < 8; j++)
#pragma unroll
        for (int c = 0; c < 4; c++) Oacc[j][c] = 0.f;

    const int kt_max = 2 * bx + 1;
    for (int kt = 0; kt <= kt_max; kt++) {
        const int st = kt & 1;

        if (kt + 1 <= kt_max) {
            const __half* Kt = Kbase + (size_t)(kt + 1) * 64 * DKK;
            const __half* Vt = Vbase + (size_t)(kt + 1) * 64 * DKK;
            const int ns = st ^ 1;
#pragma unroll
            for (int i = 0; i < 2; i++) {
                int r = kr + 32 * i;
                cpa16(ksB[ns] + r * (AR * 2) + kc, (const char*)(Kt + (size_t)r * DKK) + kc);
                cpa16(vsB[ns] + r * (AR * 2) + kc, (const char*)(Vt + (size_t)r * DKK) + kc);
            }
            CP_COMMIT();
            asm volatile("cp.async.wait_group 1;");
        } else {
            asm volatile("cp.async.wait_group 0;");
        }
        __syncthreads();

        float Sacc[8][4];
#pragma unroll
        for (int j = 0; j < 8; j++)
#pragma unroll
            for (int c = 0; c < 4; c++) Sacc[j][c] = 0.f;

#pragma unroll
        for (int g = 0; g < 4; g++) {
#pragma unroll
            for (int p = 0; p < 4; p++) {
                uint32_t tmp[4];
                ldm4(tmp, ksB[st] + ((p * 16 + noff) * AR + g * 16 + bkoff) * 2);
                mma16(Sacc[2 * p],     aq[g], tmp);
                mma16(Sacc[2 * p + 1], aq[g], tmp + 2);
            }
        }

#pragma unroll
        for (int j = 0; j < 8; j++)
#pragma unroll
            for (int c = 0; c < 4; c++) Sacc[j][c] *= 0.125f;

        if (kt >= 2 * bx) {
#pragma unroll
            for (int j = 0; j < 8; j++) {
                int col = kt * 64 + 8 * j + 2 * qq;
                if (col     > row_lo) Sacc[j][0] = -1e30f;
                if (col + 1 > row_lo) Sacc[j][1] = -1e30f;
                if (col     > row_hi) Sacc[j][2] = -1e30f;
                if (col + 1 > row_hi) Sacc[j][3] = -1e30f;
            }
        }

        float mt_lo = -1e30f, mt_hi = -1e30f;
#pragma unroll
        for (int j = 0; j < 8; j++) {
            mt_lo = fmaxf(mt_lo, fmaxf(Sacc[j][0], Sacc[j][1]));
            mt_hi = fmaxf(mt_hi, fmaxf(Sacc[j][2], Sacc[j][3]));
        }
        mt_lo = fmaxf(mt_lo, __shfl_xor_sync(0xffffffffu, mt_lo, 1));
        mt_lo = fmaxf(mt_lo, __shfl_xor_sync(0xffffffffu, mt_lo, 2));
        mt_hi = fmaxf(mt_hi, __shfl_xor_sync(0xffffffffu, mt_hi, 1));
        mt_hi = fmaxf(mt_hi, __shfl_xor_sync(0xffffffffu, mt_hi, 2));

        float mn_lo = fmaxf(m_lo, mt_lo);
        float mn_hi = fmaxf(m_hi, mt_hi);
        float al_lo = __expf(m_lo - mn_lo);
        float al_hi = __expf(m_hi - mn_hi);

        float ls_lo = 0.f, ls_hi = 0.f;
#pragma unroll
        for (int j = 0; j < 8; j++) {
            Sacc[j][0] = __expf(Sacc[j][0] - mn_lo);
            Sacc[j][1] = __expf(Sacc[j][1] - mn_lo);
            Sacc[j][2] = __expf(Sacc[j][2] - mn_hi);
            Sacc[j][3] = __expf(Sacc[j][3] - mn_hi);
            ls_lo += Sacc[j][0] + Sacc[j][1];
            ls_hi += Sacc[j][2] + Sacc[j][3];
        }
        ls_lo += __shfl_xor_sync(0xffffffffu, ls_lo, 1);
        ls_lo += __shfl_xor_sync(0xffffffffu, ls_lo, 2);
        ls_hi += __shfl_xor_sync(0xffffffffu, ls_hi, 1);
        ls_hi += __shfl_xor_sync(0xffffffffu, ls_hi, 2);

        l_lo = l_lo * al_lo + ls_lo;
        l_hi = l_hi * al_hi + ls_hi;
        m_lo = mn_lo;
        m_hi = mn_hi;

        uint32_t ap[4][4];
#pragma unroll
        for (int g = 0; g < 4; g++) {
            ap[g][0] = packh2(Sacc[2 * g][0],     Sacc[2 * g][1]);
            ap[g][1] = packh2(Sacc[2 * g][2],     Sacc[2 * g][3]);
            ap[g][2] = packh2(Sacc[2 * g + 1][0], Sacc[2 * g + 1][1]);
            ap[g][3] = packh2(Sacc[2 * g + 1][2], Sacc[2 * g + 1][3]);
        }

#pragma unroll
        for (int j = 0; j < 8; j++) {
            Oacc[j][0] *= al_lo;
            Oacc[j][1] *= al_lo;
            Oacc[j][2] *= al_hi;
            Oacc[j][3] *= al_hi;
        }

#pragma unroll
        for (int g = 0; g < 4; g++) {
#pragma unroll
            for (int p = 0; p < 4; p++) {
                uint32_t tmp[4];
                ldm4t(tmp, vsB[st] + ((g * 16 + rowoff) * AR + p * 16 + vkoff) * 2);
                mma16(Oacc[2 * p],     ap[g], tmp);
                mma16(Oacc[2 * p + 1], ap[g], tmp + 2);
            }
        }

        __syncthreads();
    }

    float il_lo = 1.f / l_lo;
    float il_hi = 1.f / l_hi;
    __half* out_lo = g_ATT + ((size_t)(b * SS + row_lo)) * DD + h * DKK;
    __half* out_hi = g_ATT + ((size_t)(b * SS + row_hi)) * DD + h * DKK;
#pragma unroll
    for (int j = 0; j < 8; j++) {
        int dk = 8 * j + 2 * qq;
        *(__half2*)&out_lo[dk] = __floats2half2_rn(Oacc[j][0] * il_lo, Oacc[j][1] * il_lo);
        *(__half2*)&out_hi[dk] = __floats2half2_rn(Oacc[j][2] * il_hi, Oacc[j][3] * il_hi);
    }
}

// ---------------------------------------------------------------------------
// Entry point. Inputs: q,k,v,mask,w_q,b_q,w_k,b_k,w_v,b_v,w_o,b_o
// ---------------------------------------------------------------------------
extern "C" void kernel_launch(void* const* d_in, const int* in_sizes, int n_in,
                              void* d_out, int out_size)
{
    const float* q  = (const float*)d_in[0];
    const float* k  = (const float*)d_in[1];
    const float* v  = (const float*)d_in[2];
    const float* wq = (const float*)d_in[4];
    const float* bq = (const float*)d_in[5];
    const float* wk = (const float*)d_in[6];
    const float* bk = (const float*)d_in[7];
    const float* wv = (const float*)d_in[8];
    const float* bv = (const float*)d_in[9];
    const float* wo = (const float*)d_in[10];
    const float* bo = (const float*)d_in[11];
    float* out = (float*)d_out;

    f2h_all_kernel<<<(NCONV_TOT + 255) / 256, 256>>>(
        (const float4*)q, (const float4*)k, (const float4*)v,
        (const float4*)wq, (const float4*)wk, (const float4*)wv, (const float4*)wo);

    cudaFuncSetAttribute(qkv_proj_kernel, cudaFuncAttributeMaxDynamicSharedMemorySize, GEMM_SMEM);
    dim3 gproj(MTOT / 128, DD / 64, 3);
    qkv_proj_kernel<<<gproj, 256, GEMM_SMEM>>>(bq, bk, bv);

    cudaFuncSetAttribute(attn_kernel, cudaFuncAttributeMaxDynamicSharedMemorySize, ATTN_SMEM);
    dim3 gattn(SS / 128, HH, BB);
    attn_kernel<<<gattn, 256, ATTN_SMEM>>>();

    cudaFuncSetAttribute(out_proj_kernel, cudaFuncAttributeMaxDynamicSharedMemorySize, GEMM_SMEM);
    dim3 gout(MTOT / 128, DD / 64, 1);
    out_proj_kernel<<<gout, 256, GEMM_SMEM>>>(bo, out);
}

// round 12
// speedup vs baseline: 10.9949x; 1.0202x over previous
#include <cuda_runtime.h>
#include <cuda_fp16.h>
#include <math.h>
#include <stdint.h>

// Problem constants
#define BB 4
#define SS 2048
#define DD 1024
#define HH 16
#define DKK 64
#define MTOT (BB * SS)   // 8192

// Scratch device globals
__device__ __half g_Q[BB * HH * SS * DKK];    // [B,H,S,DK]
__device__ __half g_K[BB * HH * SS * DKK];
__device__ __half g_V[BB * HH * SS * DKK];
__device__ __half g_ATT[(size_t)MTOT * DD];   // [B,S,D]
__device__ __half g_qh[(size_t)MTOT * DD];
__device__ __half g_kh[(size_t)MTOT * DD];
__device__ __half g_vh[(size_t)MTOT * DD];
__device__ __half g_wqh[DD * DD];
__device__ __half g_wkh[DD * DD];
__device__ __half g_wvh[DD * DD];
__device__ __half g_woh[DD * DD];

// ---------------------------------------------------------------------------
// Helpers
// ---------------------------------------------------------------------------
__device__ __forceinline__ uint32_t su(const void* p) {
    return (uint32_t)__cvta_generic_to_shared(p);
}
__device__ __forceinline__ void ldm4(uint32_t* r, uint32_t a) {
    asm volatile("ldmatrix.sync.aligned.m8n8.x4.shared.b16 {%0,%1,%2,%3},[%4];"
        : "=r"(r[0]), "=r"(r[1]), "=r"(r[2]), "=r"(r[3]) : "r"(a));
}
__device__ __forceinline__ void ldm4t(uint32_t* r, uint32_t a) {
    asm volatile("ldmatrix.sync.aligned.m8n8.x4.trans.shared.b16 {%0,%1,%2,%3},[%4];"
        : "=r"(r[0]), "=r"(r[1]), "=r"(r[2]), "=r"(r[3]) : "r"(a));
}
__device__ __forceinline__ void mma16(float* d, const uint32_t* a, const uint32_t* b) {
    asm volatile(
        "mma.sync.aligned.m16n8k16.row.col.f32.f16.f16.f32 "
        "{%0,%1,%2,%3},{%4,%5,%6,%7},{%8,%9},{%0,%1,%2,%3};"
        : "+f"(d[0]), "+f"(d[1]), "+f"(d[2]), "+f"(d[3])
        : "r"(a[0]), "r"(a[1]), "r"(a[2]), "r"(a[3]), "r"(b[0]), "r"(b[1]));
}
__device__ __forceinline__ uint32_t packh2(float x, float y) {
    __half2 h = __floats2half2_rn(x, y);
    return *(uint32_t*)&h;
}
__device__ __forceinline__ void cpa16(uint32_t d, const void* s) {
    asm volatile("cp.async.cg.shared.global [%0],[%1],16;" :: "r"(d), "l"(s));
}
#define CP_COMMIT() asm volatile("cp.async.commit_group;")

// ---------------------------------------------------------------------------
// Merged f32 -> f16 convert for all 7 arrays (one launch)
// ---------------------------------------------------------------------------
#define NACT4 (MTOT * DD / 4)
#define NW4   (DD * DD / 4)
#define NCONV_TOT (3 * NACT4 + 4 * NW4)

__global__ __launch_bounds__(256) void f2h_all_kernel(
    const float4* __restrict__ q, const float4* __restrict__ k,
    const float4* __restrict__ v,
    const float4* __restrict__ wq, const float4* __restrict__ wk,
    const float4* __restrict__ wv, const float4* __restrict__ wo)
{
    int i = blockIdx.x * 256 + threadIdx.x;
    if (i >= NCONV_TOT) return;
    const float4* src;
    uint2* dst;
    int off;
    if (i < 3 * NACT4) {
        int w = i / NACT4;
        off = i - w * NACT4;
        src = (w == 0) ? q : (w == 1) ? k : v;
        dst = (uint2*)((w == 0) ? g_qh : (w == 1) ? g_kh : g_vh);
    } else {
        int j = i - 3 * NACT4;
        int w = j / NW4;
        off = j - w * NW4;
        src = (w == 0) ? wq : (w == 1) ? wk : (w == 2) ? wv : wo;
        dst = (uint2*)((w == 0) ? g_wqh : (w == 1) ? g_wkh : (w == 2) ? g_wvh : g_woh);
    }
    float4 val = src[off];
    dst[off] = make_uint2(packh2(val.x, val.y), packh2(val.z, val.w));
}

// ---------------------------------------------------------------------------
// Pipelined FP16 GEMM core: C = A @ W^T, tile 128x64, K=1024, k-chunk 64.
// 2-stage ring with compute-overlapped prefetch. 8 warps 4(m)x2(n),
// warp tile 32x32. Rows padded to 72 halves (144B).
// ---------------------------------------------------------------------------
#define PR 72
#define A_STG (128 * PR * 2)            // 18432 B
#define W_STG (64 * PR * 2)             //  9216 B
#define GEMM_SMEM (2 * (A_STG + W_STG)) // 55296 B

__device__ __forceinline__ void gemm_pipe_core(
    const __half* __restrict__ A, const __half* __restrict__ W,
    __half* smem, float acc[2][4][4])
{
    const int t    = threadIdx.x;
    const int lane = t & 31;
    const int warp = t >> 5;
    const int wm   = warp >> 1;    // 0..3
    const int wn   = warp & 1;     // 0..1

    const int m0 = blockIdx.x * 128;
    const int n0 = blockIdx.y * 64;

    const uint32_t asB = su(smem);
    const uint32_t wsB = asB + 2 * A_STG;

    const int r0 = t >> 3;          // 0..31
    const int c  = t & 7;
    const __half* aS = A + (size_t)(m0 + r0) * DD + c * 8;
    const __half* wS = W + (size_t)(n0 + r0) * DD + c * 8;
    const uint32_t cb = (uint32_t)(r0 * (PR * 2) + c * 16);

    const int rowoff = (lane & 7) + ((lane >> 3) & 1) * 8;
    const int akoff  = ((lane >> 4) & 1) * 8;
    const int noff   = (lane & 7) + ((lane >> 4) & 1) * 8;
    const int bkoff  = ((lane >> 3) & 1) * 8;
    uint32_t aAddr[2], bAddr[2];
#pragma unroll
    for (int mi = 0; mi < 2; mi++)
        aAddr[mi] = asB + ((wm * 32 + mi * 16 + rowoff) * PR + akoff) * 2;
#pragma unroll
    for (int p = 0; p < 2; p++)
        bAddr[p] = wsB + ((wn * 32 + p * 16 + noff) * PR + bkoff) * 2;

    auto issue = [&](int s) {
        const int ko = s * 64;
        const uint32_t st = (uint32_t)(s & 1);
#pragma unroll
        for (int i = 0; i < 4; i++)
            cpa16(asB + st * A_STG + cb + (uint32_t)(32 * i) * (PR * 2),
                  aS + (size_t)(32 * i) * DD + ko);
#pragma unroll
        for (int i = 0; i < 2; i++)
            cpa16(wsB + st * W_STG + cb + (uint32_t)(32 * i) * (PR * 2),
                  wS + (size_t)(32 * i) * DD + ko);
        CP_COMMIT();
    };

    issue(0);

    const int NIT = DD / 64;   // 16
    for (int it = 0; it < NIT; it++) {
        asm volatile("cp.async.wait_group 0;");
        __syncthreads();
        if (it + 1 < NIT) issue(it + 1);

        const uint32_t offA = (uint32_t)(it & 1) * A_STG;
        const uint32_t offB = (uint32_t)(it & 1) * W_STG;
#pragma unroll
        for (int ks = 0; ks < 4; ks++) {
            uint32_t af[2][4];
#pragma unroll
            for (int mi = 0; mi < 2; mi++)
                ldm4(af[mi], aAddr[mi] + offA + ks * 32);
            uint32_t bf[4][2];
#pragma unroll
            for (int p = 0; p < 2; p++) {
                uint32_t tmp[4];
                ldm4(tmp, bAddr[p] + offB + ks * 32);
                bf[2 * p][0] = tmp[0]; bf[2 * p][1] = tmp[1];
                bf[2 * p + 1][0] = tmp[2]; bf[2 * p + 1][1] = tmp[3];
            }
#pragma unroll
            for (int mi = 0; mi < 2; mi++)
#pragma unroll
                for (int ni = 0; ni < 4; ni++)
                    mma16(acc[mi][ni], af[mi], bf[ni]);
        }
    }
}

// ---------------------------------------------------------------------------
// QKV projections (half in/out): Y = X @ W^T + b -> head-split [B,H,S,DK]
// ---------------------------------------------------------------------------
__global__ __launch_bounds__(256, 3) void qkv_proj_kernel(
    const float* __restrict__ bq, const float* __restrict__ bk,
    const float* __restrict__ bv)
{
    extern __shared__ __half smem[];

    const __half* A; const __half* W; const float* bias; __half* out;
    if (blockIdx.z == 0)      { A = g_qh; W = g_wqh; bias = bq; out = g_Q; }
    else if (blockIdx.z == 1) { A = g_kh; W = g_wkh; bias = bk; out = g_K; }
    else                      { A = g_vh; W = g_wvh; bias = bv; out = g_V; }

    float acc[2][4][4];
#pragma unroll
    for (int a = 0; a < 2; a++)
#pragma unroll
        for (int b = 0; b < 4; b++)
#pragma unroll
            for (int c = 0; c < 4; c++) acc[a][b][c] = 0.f;

    gemm_pipe_core(A, W, smem, acc);

    const int lane = threadIdx.x & 31;
    const int warp = threadIdx.x >> 5;
    const int wm = warp >> 1, wn = warp & 1;
    const int qq = lane & 3, l4 = lane >> 2;
    const int m0 = blockIdx.x * 128;
    const int n0 = blockIdx.y * 64;

#pragma unroll
    for (int mi = 0; mi < 2; mi++) {
#pragma unroll
        for (int rr = 0; rr < 2; rr++) {
            int m = m0 + wm * 32 + mi * 16 + l4 + rr * 8;
            int b = m >> 11;
            int s = m & 2047;
#pragma unroll
            for (int ni = 0; ni < 4; ni++) {
                int n  = n0 + wn * 32 + ni * 8 + 2 * qq;
                int h  = n >> 6;
                int dk = n & 63;
                __half2 hv = __floats2half2_rn(acc[mi][ni][rr * 2 + 0] + bias[n],
                                               acc[mi][ni][rr * 2 + 1] + bias[n + 1]);
                *(__half2*)&out[((size_t)(b * HH + h) * SS + s) * DKK + dk] = hv;
            }
        }
    }
}

// ---------------------------------------------------------------------------
// Output projection: out(f32) = g_ATT(half) @ Wo^T + bo
// ---------------------------------------------------------------------------
__global__ __launch_bounds__(256, 3) void out_proj_kernel(
    const float* __restrict__ bo, float* __restrict__ out)
{
    extern __shared__ __half smem[];

    float acc[2][4][4];
#pragma unroll
    for (int a = 0; a < 2; a++)
#pragma unroll
        for (int b = 0; b < 4; b++)
#pragma unroll
            for (int c = 0; c < 4; c++) acc[a][b][c] = 0.f;

    gemm_pipe_core(g_ATT, g_woh, smem, acc);

    const int lane = threadIdx.x & 31;
    const int warp = threadIdx.x >> 5;
    const int wm = warp >> 1, wn = warp & 1;
    const int qq = lane & 3, l4 = lane >> 2;
    const int m0 = blockIdx.x * 128;
    const int n0 = blockIdx.y * 64;

#pragma unroll
    for (int mi = 0; mi < 2; mi++) {
#pragma unroll
        for (int rr = 0; rr < 2; rr++) {
            int m = m0 + wm * 32 + mi * 16 + l4 + rr * 8;
#pragma unroll
            for (int ni = 0; ni < 4; ni++) {
                int n = n0 + wn * 32 + ni * 8 + 2 * qq;
                float2 rv;
                rv.x = acc[mi][ni][rr * 2 + 0] + bo[n];
                rv.y = acc[mi][ni][rr * 2 + 1] + bo[n + 1];
                *(float2*)&out[(size_t)m * DD + n] = rv;
            }
        }
    }
}

// ---------------------------------------------------------------------------
// Flash attention (causal), FP16 mma + ldmatrix + cp.async.
// 4-stage KV ring, tiles processed in PAIRS: one wait+sync per 128 keys.
// Heavy q-tiles launch first (bx reversed) for better tail packing.
// ---------------------------------------------------------------------------
#define AR 72
#define Q_HALVES (128 * AR)
#define KV_HALVES (64 * AR)
#define ATTN_SMEM ((Q_HALVES + 8 * KV_HALVES) * 2)   // 92160 B

__global__ __launch_bounds__(256, 2) void attn_kernel()
{
    extern __shared__ __half sm[];
    __half* Qs = sm;

    const int t    = threadIdx.x;
    const int lane = t & 31;
    const int w    = t >> 5;
    const int qq   = lane & 3;
    const int l4   = lane >> 2;

    const int bx = (int)gridDim.x - 1 - (int)blockIdx.x;   // heavy first
    const int h  = blockIdx.y;
    const int b  = blockIdx.z;

    const __half* Qbase = g_Q + ((size_t)(b * HH + h) * SS) * DKK;
    const __half* Kbase = g_K + ((size_t)(b * HH + h) * SS) * DKK;
    const __half* Vbase = g_V + ((size_t)(b * HH + h) * SS) * DKK;

    uint32_t ksB[4], vsB[4];
#pragma unroll
    for (int i = 0; i < 4; i++) {
        ksB[i] = su(Qs + Q_HALVES + (size_t)i * KV_HALVES);
        vsB[i] = su(Qs + Q_HALVES + (size_t)(4 + i) * KV_HALVES);
    }

    const int qr = t >> 3;
    const int qc = (t & 7) * 16;
    const int kr = t >> 3;
    const int kc = (t & 7) * 16;

    // Issue Q (own commit group)
    {
        uint32_t qdst = su(Qs);
#pragma unroll
        for (int i = 0; i < 4; i++) {
            int r = qr + 32 * i;
            cpa16(qdst + r * (AR * 2) + qc, (const char*)(Qbase + (size_t)(bx * 128 + r) * DKK) + qc);
        }
    }
    CP_COMMIT();

    // Issue a PAIR of KV tiles as one commit group
    auto issue_group = [&](int g) {
#pragma unroll
        for (int tt = 0; tt < 2; tt++) {
            const int kt = 2 * g + tt;
            const __half* Kt = Kbase + (size_t)kt * 64 * DKK;
            const __half* Vt = Vbase + (size_t)kt * 64 * DKK;
            const int st = kt & 3;
#pragma unroll
            for (int i = 0; i < 2; i++) {
                int r = kr + 32 * i;
                cpa16(ksB[st] + r * (AR * 2) + kc, (const char*)(Kt + (size_t)r * DKK) + kc);
                cpa16(vsB[st] + r * (AR * 2) + kc, (const char*)(Vt + (size_t)r * DKK) + kc);
            }
        }
        CP_COMMIT();
    };

    issue_group(0);

    // Wait for Q (group 0 may remain in flight), extract Q fragments
    asm volatile("cp.async.wait_group 1;");
    __syncthreads();

    const int rowoff = (lane & 7) + ((lane >> 3) & 1) * 8;
    const int akoff  = ((lane >> 4) & 1) * 8;
    const int noff   = (lane & 7) + ((lane >> 4) & 1) * 8;
    const int bkoff  = ((lane >> 3) & 1) * 8;
    const int vkoff  = ((lane >> 4) & 1) * 8;

    uint32_t aq[4][4];
#pragma unroll
    for (int g = 0; g < 4; g++)
        ldm4(aq[g], su(&Qs[(16 * w + rowoff) * AR + g * 16 + akoff]));

    const int rl = 16 * w + l4;
    const int row_lo = bx * 128 + rl;
    const int row_hi = row_lo + 8;

    float m_lo = -1e30f, m_hi = -1e30f, l_lo = 0.f, l_hi = 0.f;
    float Oacc[8][4];
#pragma unroll
    for (int j = 0; j < 8; j++)
#pragma unroll
        for (int c = 0; c < 4; c++) Oacc[j][c] = 0.f;

    // Process one 64-key tile (stage kt&3)
    auto process_tile = [&](int kt) {
        const int st = kt & 3;

        float Sacc[8][4];
#pragma unroll
        for (int j = 0; j < 8; j++)
#pragma unroll
            for (int c = 0; c < 4; c++) Sacc[j][c] = 0.f;

#pragma unroll
        for (int g = 0; g < 4; g++) {
#pragma unroll
            for (int p = 0; p < 4; p++) {
                uint32_t tmp[4];
                ldm4(tmp, ksB[st] + ((p * 16 + noff) * AR + g * 16 + bkoff) * 2);
                mma16(Sacc[2 * p],     aq[g], tmp);
                mma16(Sacc[2 * p + 1], aq[g], tmp + 2);
            }
        }

#pragma unroll
        for (int j = 0; j < 8; j++)
#pragma unroll
            for (int c = 0; c < 4; c++) Sacc[j][c] *= 0.125f;

        if (kt >= 2 * bx) {
#pragma unroll
            for (int j = 0; j < 8; j++) {
                int col = kt * 64 + 8 * j + 2 * qq;
                if (col     > row_lo) Sacc[j][0] = -1e30f;
                if (col + 1 > row_lo) Sacc[j][1] = -1e30f;
                if (col     > row_hi) Sacc[j][2] = -1e30f;
                if (col + 1 > row_hi) Sacc[j][3] = -1e30f;
            }
        }

        float mt_lo = -1e30f, mt_hi = -1e30f;
#pragma unroll
        for (int j = 0; j < 8; j++) {
            mt_lo = fmaxf(mt_lo, fmaxf(Sacc[j][0], Sacc[j][1]));
            mt_hi = fmaxf(mt_hi, fmaxf(Sacc[j][2], Sacc[j][3]));
        }
        mt_lo = fmaxf(mt_lo, __shfl_xor_sync(0xffffffffu, mt_lo, 1));
        mt_lo = fmaxf(mt_lo, __shfl_xor_sync(0xffffffffu, mt_lo, 2));
        mt_hi = fmaxf(mt_hi, __shfl_xor_sync(0xffffffffu, mt_hi, 1));
        mt_hi = fmaxf(mt_hi, __shfl_xor_sync(0xffffffffu, mt_hi, 2));

        float mn_lo = fmaxf(m_lo, mt_lo);
        float mn_hi = fmaxf(m_hi, mt_hi);
        float al_lo = __expf(m_lo - mn_lo);
        float al_hi = __expf(m_hi - mn_hi);

        float ls_lo = 0.f, ls_hi = 0.f;
#pragma unroll
        for (int j = 0; j < 8; j++) {
            Sacc[j][0] = __expf(Sacc[j][0] - mn_lo);
            Sacc[j][1] = __expf(Sacc[j][1] - mn_lo);
            Sacc[j][2] = __expf(Sacc[j][2] - mn_hi);
            Sacc[j][3] = __expf(Sacc[j][3] - mn_hi);
            ls_lo += Sacc[j][0] + Sacc[j][1];
            ls_hi += Sacc[j][2] + Sacc[j][3];
        }
        ls_lo += __shfl_xor_sync(0xffffffffu, ls_lo, 1);
        ls_lo += __shfl_xor_sync(0xffffffffu, ls_lo, 2);
        ls_hi += __shfl_xor_sync(0xffffffffu, ls_hi, 1);
        ls_hi += __shfl_xor_sync(0xffffffffu, ls_hi, 2);

        l_lo = l_lo * al_lo + ls_lo;
        l_hi = l_hi * al_hi + ls_hi;
        m_lo = mn_lo;
        m_hi = mn_hi;

        uint32_t ap[4][4];
#pragma unroll
        for (int g = 0; g < 4; g++) {
            ap[g][0] = packh2(Sacc[2 * g][0],     Sacc[2 * g][1]);
            ap[g][1] = packh2(Sacc[2 * g][2],     Sacc[2 * g][3]);
            ap[g][2] = packh2(Sacc[2 * g + 1][0], Sacc[2 * g + 1][1]);
            ap[g][3] = packh2(Sacc[2 * g + 1][2], Sacc[2 * g + 1][3]);
        }

#pragma unroll
        for (int j = 0; j < 8; j++) {
            Oacc[j][0] *= al_lo;
            Oacc[j][1] *= al_lo;
            Oacc[j][2] *= al_hi;
            Oacc[j][3] *= al_hi;
        }

#pragma unroll
        for (int g = 0; g < 4; g++) {
#pragma unroll
            for (int p = 0; p < 4; p++) {
                uint32_t tmp[4];
                ldm4t(tmp, vsB[st] + ((g * 16 + rowoff) * AR + p * 16 + vkoff) * 2);
                mma16(Oacc[2 * p],     ap[g], tmp);
                mma16(Oacc[2 * p + 1], ap[g], tmp + 2);
            }
        }
    };

    // Main loop: bx+1 iterations, each consumes a pair of tiles.
    // Iter j: wait group j (all outstanding), sync (all warps done with group
    // j-1, whose stages group j+1 reuses), prefetch group j+1, compute pair.
    for (int j = 0; j <= bx; j++) {
        asm volatile("cp.async.wait_group 0;");
        __syncthreads();
        if (j < bx) issue_group(j + 1);
        process_tile(2 * j);
        process_tile(2 * j + 1);
    }

    float il_lo = 1.f / l_lo;
    float il_hi = 1.f / l_hi;
    __half* out_lo = g_ATT + ((size_t)(b * SS + row_lo)) * DD + h * DKK;
    __half* out_hi = g_ATT + ((size_t)(b * SS + row_hi)) * DD + h * DKK;
#pragma unroll
    for (int j = 0; j < 8; j++) {
        int dk = 8 * j + 2 * qq;
        *(__half2*)&out_lo[dk] = __floats2half2_rn(Oacc[j][0] * il_lo, Oacc[j][1] * il_lo);
        *(__half2*)&out_hi[dk] = __floats2half2_rn(Oacc[j][2] * il_hi, Oacc[j][3] * il_hi);
    }
}

// ---------------------------------------------------------------------------
// Entry point. Inputs: q,k,v,mask,w_q,b_q,w_k,b_k,w_v,b_v,w_o,b_o
// ---------------------------------------------------------------------------
extern "C" void kernel_launch(void* const* d_in, const int* in_sizes, int n_in,
                              void* d_out, int out_size)
{
    const float* q  = (const float*)d_in[0];
    const float* k  = (const float*)d_in[1];
    const float* v  = (const float*)d_in[2];
    const float* wq = (const float*)d_in[4];
    const float* bq = (const float*)d_in[5];
    const float* wk = (const float*)d_in[6];
    const float* bk = (const float*)d_in[7];
    const float* wv = (const float*)d_in[8];
    const float* bv = (const float*)d_in[9];
    const float* wo = (const float*)d_in[10];
    const float* bo = (const float*)d_in[11];
    float* out = (float*)d_out;

    f2h_all_kernel<<<(NCONV_TOT + 255) / 256, 256>>>(
        (const float4*)q, (const float4*)k, (const float4*)v,
        (const float4*)wq, (const float4*)wk, (const float4*)wv, (const float4*)wo);

    cudaFuncSetAttribute(qkv_proj_kernel, cudaFuncAttributeMaxDynamicSharedMemorySize, GEMM_SMEM);
    dim3 gproj(MTOT / 128, DD / 64, 3);
    qkv_proj_kernel<<<gproj, 256, GEMM_SMEM>>>(bq, bk, bv);

    cudaFuncSetAttribute(attn_kernel, cudaFuncAttributeMaxDynamicSharedMemorySize, ATTN_SMEM);
    dim3 gattn(SS / 128, HH, BB);
    attn_kernel<<<gattn, 256, ATTN_SMEM>>>();

    cudaFuncSetAttribute(out_proj_kernel, cudaFuncAttributeMaxDynamicSharedMemorySize, GEMM_SMEM);
    dim3 gout(MTOT / 128, DD / 64, 1);
    out_proj_kernel<<<gout, 256, GEMM_SMEM>>>(bo, out);
}